// round 1
// baseline (speedup 1.0000x reference)
#include <cuda_runtime.h>
#include <math.h>

// ---------------------------------------------------------------------------
// Problem constants (fixed by the dataset: B=2, S=2048, D_MODEL=1024, H=16, Dh=64)
// ---------------------------------------------------------------------------
#define NB      2
#define SEQ     2048
#define DM      1024
#define NHEADS  16
#define HEAD    64

// Scratch: Q/K/V in [B][H][S][HEAD] layout, bias per (h, delta)
__device__ float g_q[NB * NHEADS * SEQ * HEAD];
__device__ float g_k[NB * NHEADS * SEQ * HEAD];
__device__ float g_v[NB * NHEADS * SEQ * HEAD];
__device__ float g_bias[NHEADS * 4096];   // [h][delta + 2047], delta in [-2047, 2047]

// ---------------------------------------------------------------------------
// Kernel 1: relative-position bias table, expanded per delta.
// T5 bucket (bidirectional, num_buckets=32 -> 16 per side, max_exact=8,
// max_distance=128 -> log(16) divisor).
// Power-of-two distances are the exact integer crossings of the log formula;
// handle them exactly to avoid 1-ulp truncation flips vs the jax reference.
// ---------------------------------------------------------------------------
__global__ void bias_precompute_kernel(const float* __restrict__ bias_table) {
    int i = blockIdx.x * blockDim.x + threadIdx.x;   // 0..4095
    if (i >= 4095) return;
    int delta = i - 2047;                            // mem - ctx
    int ret = (delta > 0) ? 16 : 0;
    int rp = abs(delta);
    int bucket;
    if (rp < 8) {
        bucket = ret + rp;
    } else {
        int vl;
        if ((rp & (rp - 1)) == 0) {
            // rp = 2^k: exact value is 2*(k-3)
            int k = __ffs(rp) - 1;
            vl = 8 + 2 * (k - 3);
        } else {
            float t = logf((float)rp * 0.125f) / 2.7725887f;  // log(16) as f32
            vl = 8 + (int)(t * 8.0f);
        }
        bucket = ret + min(vl, 15);
    }
    #pragma unroll
    for (int h = 0; h < NHEADS; h++)
        g_bias[h * 4096 + i] = bias_table[bucket * NHEADS + h];
}

// ---------------------------------------------------------------------------
// Kernel 2: fused QKV projection.
// Y[t,n] = sum_m X[t,m] * W[m,n],  M = B*S = 4096, N = 1024, K = 1024.
// blockIdx.z in {0,1,2} selects (query,Wq)->g_q, (key,Wk)->g_k, (value,Wv)->g_v.
// Classic 128x128x8 SGEMM, 256 threads, 8x8 per-thread microtile.
// Epilogue writes into [B][H][S][HEAD] scratch layout.
// ---------------------------------------------------------------------------
#define PBM 128
#define PBN 128
#define PBK 8

__global__ void __launch_bounds__(256) proj_kernel(
    const float* __restrict__ Xq, const float* __restrict__ Xk,
    const float* __restrict__ Xv,
    const float* __restrict__ Wq, const float* __restrict__ Wk,
    const float* __restrict__ Wv)
{
    __shared__ float As[PBK][PBM];   // transposed A tile: As[k][m]
    __shared__ float Bs[PBK][PBN];

    const float* X; const float* W; float* dst;
    int z = blockIdx.z;
    if (z == 0)      { X = Xq; W = Wq; dst = g_q; }
    else if (z == 1) { X = Xk; W = Wk; dst = g_k; }
    else             { X = Xv; W = Wv; dst = g_v; }

    const int bm0 = blockIdx.y * PBM;
    const int bn0 = blockIdx.x * PBN;
    const int tid = threadIdx.x;
    const int txx = tid & 15;      // 0..15 (N direction)
    const int tyy = tid >> 4;      // 0..15 (M direction)

    // global load indices
    const int a_r = tid >> 1;            // 0..127
    const int a_c = (tid & 1) * 4;       // 0 or 4
    const int b_r = tid >> 5;            // 0..7
    const int b_c = (tid & 31) * 4;      // 0..124

    float acc[8][8];
    #pragma unroll
    for (int i = 0; i < 8; i++)
        #pragma unroll
        for (int j = 0; j < 8; j++) acc[i][j] = 0.0f;

    for (int k0 = 0; k0 < DM; k0 += PBK) {
        float4 av = *(const float4*)(X + (size_t)(bm0 + a_r) * DM + k0 + a_c);
        float4 bv = *(const float4*)(W + (size_t)(k0 + b_r) * (NHEADS * HEAD) + bn0 + b_c);
        __syncthreads();   // previous iteration's reads complete
        As[a_c + 0][a_r] = av.x;
        As[a_c + 1][a_r] = av.y;
        As[a_c + 2][a_r] = av.z;
        As[a_c + 3][a_r] = av.w;
        *(float4*)&Bs[b_r][b_c] = bv;
        __syncthreads();

        #pragma unroll
        for (int kk = 0; kk < PBK; kk++) {
            float a[8], b[8];
            *(float4*)(a)     = *(const float4*)&As[kk][tyy * 8];
            *(float4*)(a + 4) = *(const float4*)&As[kk][tyy * 8 + 4];
            *(float4*)(b)     = *(const float4*)&Bs[kk][txx * 8];
            *(float4*)(b + 4) = *(const float4*)&Bs[kk][txx * 8 + 4];
            #pragma unroll
            for (int i = 0; i < 8; i++)
                #pragma unroll
                for (int j = 0; j < 8; j++)
                    acc[i][j] = fmaf(a[i], b[j], acc[i][j]);
        }
    }

    // epilogue: scatter into [B][H][S][HEAD]
    #pragma unroll
    for (int i = 0; i < 8; i++) {
        int m = bm0 + tyy * 8 + i;      // token
        int bb = m >> 11;               // /SEQ
        int ss = m & (SEQ - 1);
        #pragma unroll
        for (int j = 0; j < 8; j += 4) {
            int n = bn0 + txx * 8 + j;
            int h = n >> 6;
            int d = n & 63;
            float4 v;
            v.x = acc[i][j]; v.y = acc[i][j + 1]; v.z = acc[i][j + 2]; v.w = acc[i][j + 3];
            *(float4*)&dst[(((size_t)(bb * NHEADS + h) * SEQ + ss) << 6) + d] = v;
        }
    }
}

// ---------------------------------------------------------------------------
// Kernel 3: flash attention, fp32.
// grid = (SEQ/64, H, B), 128 threads.
// Thread (ty,tx): ty = tid/8 in [0,16), tx = tid%8 in [0,8).
//   - owns score/O rows r = 4*ty + i (i<4), columns c = tx + 8*j (j<8)
//   - holds Q[r][tx*8 .. tx*8+7] in registers (broadcast via width-8 shuffles)
// Smem: Ks[64][65] (reused for P), Vs[64][64], bias/mask windows. 33.8 KB.
// ---------------------------------------------------------------------------
__global__ void __launch_bounds__(128) attn_kernel(
    const float* __restrict__ key_mask, float* __restrict__ out)
{
    __shared__ float Ks[64][65];    // K tile, later reused as P
    __shared__ float Vs[64][64];
    __shared__ float bwin[128];     // bias window over (c - r + 63)
    __shared__ float mwin[64];      // mask additive term per key col

    const int qt0 = blockIdx.x * 64;
    const int h   = blockIdx.y;
    const int b   = blockIdx.z;
    const int tid = threadIdx.x;
    const int tx  = tid & 7;
    const int ty  = tid >> 3;

    const size_t bh = ((size_t)(b * NHEADS + h)) << 17;   // * SEQ * HEAD
    const float* Qbh = g_q + bh;
    const float* Kbh = g_k + bh;
    const float* Vbh = g_v + bh;
    const float* bias_h = g_bias + h * 4096;

    // Load Q rows into registers: qreg[i][u] = Q[qt0 + 4*ty + i][tx*8 + u]
    float qreg[4][8];
    #pragma unroll
    for (int i = 0; i < 4; i++) {
        const float* qp = Qbh + (size_t)(qt0 + ty * 4 + i) * HEAD + tx * 8;
        float4 v0 = *(const float4*)(qp);
        float4 v1 = *(const float4*)(qp + 4);
        qreg[i][0] = v0.x; qreg[i][1] = v0.y; qreg[i][2] = v0.z; qreg[i][3] = v0.w;
        qreg[i][4] = v1.x; qreg[i][5] = v1.y; qreg[i][6] = v1.z; qreg[i][7] = v1.w;
    }

    float o[4][8];
    #pragma unroll
    for (int i = 0; i < 4; i++)
        #pragma unroll
        for (int j = 0; j < 8; j++) o[i][j] = 0.0f;
    float mrow[4], lrow[4];
    #pragma unroll
    for (int i = 0; i < 4; i++) { mrow[i] = -INFINITY; lrow[i] = 0.0f; }

    for (int kt0 = 0; kt0 < SEQ; kt0 += 64) {
        // ---- load K, V tiles + bias/mask windows ----
        #pragma unroll
        for (int v = 0; v < 8; v++) {
            int e = (v * 128 + tid) * 4;      // 0..4092
            int c = e >> 6, d = e & 63;
            float4 kv4 = *(const float4*)(Kbh + (size_t)(kt0 + c) * HEAD + d);
            Ks[c][d + 0] = kv4.x; Ks[c][d + 1] = kv4.y;
            Ks[c][d + 2] = kv4.z; Ks[c][d + 3] = kv4.w;
            float4 vv4 = *(const float4*)(Vbh + (size_t)(kt0 + c) * HEAD + d);
            *(float4*)&Vs[c][d] = vv4;
        }
        if (tid < 127) {
            int idx = kt0 - qt0 + tid - 63 + 2047;
            idx = max(0, min(4094, idx));
            bwin[tid] = bias_h[idx];
        }
        if (tid < 64) {
            float mk = key_mask[(size_t)b * SEQ + kt0 + tid];
            mwin[tid] = (1.0f - mk) * -10000.0f;
        }
        __syncthreads();

        // ---- scores S = Q K^T (Q from registers via shuffles) ----
        float s[4][8];
        #pragma unroll
        for (int i = 0; i < 4; i++)
            #pragma unroll
            for (int j = 0; j < 8; j++) s[i][j] = 0.0f;

        const float* ksbase = &Ks[tx][0];
        for (int g = 0; g < 8; g++) {
            const float* kd = ksbase + g * 8;
            #pragma unroll
            for (int u = 0; u < 8; u++) {
                float kv[8];
                #pragma unroll
                for (int j = 0; j < 8; j++) kv[j] = kd[j * 8 * 65 + u];
                float qv[4];
                #pragma unroll
                for (int i = 0; i < 4; i++)
                    qv[i] = __shfl_sync(0xffffffffu, qreg[i][u], g, 8);
                #pragma unroll
                for (int i = 0; i < 4; i++)
                    #pragma unroll
                    for (int j = 0; j < 8; j++)
                        s[i][j] = fmaf(qv[i], kv[j], s[i][j]);
            }
        }

        // ---- bias + mask + row max ----
        float mt[4];
        #pragma unroll
        for (int i = 0; i < 4; i++) {
            int r = ty * 4 + i;
            float mx = -INFINITY;
            #pragma unroll
            for (int j = 0; j < 8; j++) {
                int c = tx + 8 * j;
                s[i][j] += bwin[c - r + 63] + mwin[c];
                mx = fmaxf(mx, s[i][j]);
            }
            mx = fmaxf(mx, __shfl_xor_sync(0xffffffffu, mx, 1, 8));
            mx = fmaxf(mx, __shfl_xor_sync(0xffffffffu, mx, 2, 8));
            mx = fmaxf(mx, __shfl_xor_sync(0xffffffffu, mx, 4, 8));
            mt[i] = mx;
        }

        __syncthreads();   // all K reads done; safe to overwrite Ks with P

        // ---- online softmax; write P into Ks buffer ----
        #pragma unroll
        for (int i = 0; i < 4; i++) {
            float mnew = fmaxf(mrow[i], mt[i]);
            float corr = __expf(mrow[i] - mnew);
            mrow[i] = mnew;
            float sum = 0.0f;
            #pragma unroll
            for (int j = 0; j < 8; j++) {
                float p = __expf(s[i][j] - mnew);
                s[i][j] = p;
                sum += p;
            }
            sum += __shfl_xor_sync(0xffffffffu, sum, 1, 8);
            sum += __shfl_xor_sync(0xffffffffu, sum, 2, 8);
            sum += __shfl_xor_sync(0xffffffffu, sum, 4, 8);
            lrow[i] = lrow[i] * corr + sum;
            #pragma unroll
            for (int j = 0; j < 8; j++) o[i][j] *= corr;
            #pragma unroll
            for (int j = 0; j < 8; j++)
                Ks[ty * 4 + i][tx + 8 * j] = s[i][j];
        }
        __syncthreads();   // P visible to everyone

        // ---- O += P * V ----
        #pragma unroll 4
        for (int k = 0; k < 64; k++) {
            float pk[4], vv[8];
            #pragma unroll
            for (int i = 0; i < 4; i++) pk[i] = Ks[ty * 4 + i][k];
            #pragma unroll
            for (int j = 0; j < 8; j++) vv[j] = Vs[k][tx + 8 * j];
            #pragma unroll
            for (int i = 0; i < 4; i++)
                #pragma unroll
                for (int j = 0; j < 8; j++)
                    o[i][j] = fmaf(pk[i], vv[j], o[i][j]);
        }
        __syncthreads();   // PV done before next tile overwrites Ks/Vs
    }

    // ---- epilogue: out[b][s][h*64 + d] = o / l ----
    #pragma unroll
    for (int i = 0; i < 4; i++) {
        int srow = qt0 + ty * 4 + i;
        float inv = 1.0f / lrow[i];
        #pragma unroll
        for (int j = 0; j < 8; j++) {
            int dc = tx + 8 * j;
            out[((size_t)(b * SEQ + srow)) * (NHEADS * HEAD) + h * HEAD + dc] =
                o[i][j] * inv;
        }
    }
}

// ---------------------------------------------------------------------------
// Launch
// Inputs (metadata order): query, key, value, key_mask, Wq, Wk, Wv, bias_table
// Output: float32 [B, S, H*HEAD]
// ---------------------------------------------------------------------------
extern "C" void kernel_launch(void* const* d_in, const int* in_sizes, int n_in,
                              void* d_out, int out_size) {
    const float* query    = (const float*)d_in[0];
    const float* key      = (const float*)d_in[1];
    const float* value    = (const float*)d_in[2];
    const float* key_mask = (const float*)d_in[3];
    const float* Wq       = (const float*)d_in[4];
    const float* Wk       = (const float*)d_in[5];
    const float* Wv       = (const float*)d_in[6];
    const float* bias_tab = (const float*)d_in[7];
    float* out = (float*)d_out;

    bias_precompute_kernel<<<16, 256>>>(bias_tab);
    proj_kernel<<<dim3((NHEADS * HEAD) / PBN, (NB * SEQ) / PBM, 3), 256>>>(
        query, key, value, Wq, Wk, Wv);
    attn_kernel<<<dim3(SEQ / 64, NHEADS, NB), 128>>>(key_mask, out);
}

// round 3
// speedup vs baseline: 1.2026x; 1.2026x over previous
#include <cuda_runtime.h>
#include <cuda_bf16.h>
#include <math.h>
#include <stdint.h>

// ---------------------------------------------------------------------------
// Problem constants (B=2, S=2048, D_MODEL=1024, H=16, Dh=64)
// ---------------------------------------------------------------------------
#define NB      2
#define SEQ     2048
#define DM      1024
#define NHEADS  16
#define HEAD    64

// Scratch
__device__ float g_q[NB * NHEADS * SEQ * HEAD];
__device__ float g_k[NB * NHEADS * SEQ * HEAD];
__device__ float g_v[NB * NHEADS * SEQ * HEAD];
__device__ float g_bias[NHEADS * 4096];

// bf16 split operands for projection GEMMs
// A: activations [z][4096 tokens][1024 k] ; B: W^T [z][1024 n][1024 k]
__device__ __nv_bfloat16 g_Ahi[3][4096 * 1024];
__device__ __nv_bfloat16 g_Alo[3][4096 * 1024];
__device__ __nv_bfloat16 g_Bhi[3][1024 * 1024];
__device__ __nv_bfloat16 g_Blo[3][1024 * 1024];

// ---------------------------------------------------------------------------
// PTX helpers (sm_100 base target: cp.async / ldmatrix / mma.sync only)
// ---------------------------------------------------------------------------
__device__ __forceinline__ uint32_t smem_u32(const void* p) {
    uint32_t a;
    asm("{ .reg .u64 t; cvta.to.shared.u64 t, %1; cvt.u32.u64 %0, t; }"
        : "=r"(a) : "l"(p));
    return a;
}
#define CP_ASYNC16(dst, src) \
    asm volatile("cp.async.cg.shared.global [%0], [%1], 16;" :: "r"(dst), "l"(src))
#define CP_COMMIT() asm volatile("cp.async.commit_group;" ::: "memory")
#define CP_WAIT(n)  asm volatile("cp.async.wait_group %0;" :: "n"(n) : "memory")

#define LDMATRIX_X4(r0, r1, r2, r3, addr) \
    asm volatile("ldmatrix.sync.aligned.m8n8.x4.shared.b16 {%0,%1,%2,%3}, [%4];" \
                 : "=r"(r0), "=r"(r1), "=r"(r2), "=r"(r3) : "r"(addr))

__device__ __forceinline__ void mma_bf16(float* d, const uint32_t* a,
                                         const uint32_t* b) {
    asm volatile(
        "mma.sync.aligned.m16n8k16.row.col.f32.bf16.bf16.f32 "
        "{%0,%1,%2,%3}, {%4,%5,%6,%7}, {%8,%9}, {%0,%1,%2,%3};"
        : "+f"(d[0]), "+f"(d[1]), "+f"(d[2]), "+f"(d[3])
        : "r"(a[0]), "r"(a[1]), "r"(a[2]), "r"(a[3]), "r"(b[0]), "r"(b[1]));
}

// ---------------------------------------------------------------------------
// Kernel 1: relative-position bias table expansion (known-good)
// ---------------------------------------------------------------------------
__global__ void bias_precompute_kernel(const float* __restrict__ bias_table) {
    int i = blockIdx.x * blockDim.x + threadIdx.x;
    if (i >= 4095) return;
    int delta = i - 2047;
    int ret = (delta > 0) ? 16 : 0;
    int rp = abs(delta);
    int bucket;
    if (rp < 8) {
        bucket = ret + rp;
    } else {
        int vl;
        if ((rp & (rp - 1)) == 0) {
            int k = __ffs(rp) - 1;
            vl = 8 + 2 * (k - 3);
        } else {
            float t = logf((float)rp * 0.125f) / 2.7725887f;
            vl = 8 + (int)(t * 8.0f);
        }
        bucket = ret + min(vl, 15);
    }
    #pragma unroll
    for (int h = 0; h < NHEADS; h++)
        g_bias[h * 4096 + i] = bias_table[bucket * NHEADS + h];
}

// ---------------------------------------------------------------------------
// Kernel 2a: split activations X -> bf16 hi/lo (z = 0,1,2 : query,key,value)
// ---------------------------------------------------------------------------
__global__ void __launch_bounds__(256) convert_x_kernel(
    const float* __restrict__ Xq, const float* __restrict__ Xk,
    const float* __restrict__ Xv)
{
    int z = blockIdx.y;
    const float* X = (z == 0) ? Xq : (z == 1) ? Xk : Xv;
    __nv_bfloat16* hi = g_Ahi[z];
    __nv_bfloat16* lo = g_Alo[z];
    size_t i = ((size_t)blockIdx.x * 256 + threadIdx.x) * 4;
    float4 v = *(const float4*)(X + i);
    float f[4] = {v.x, v.y, v.z, v.w};
    #pragma unroll
    for (int j = 0; j < 4; j++) {
        __nv_bfloat16 h = __float2bfloat16(f[j]);
        hi[i + j] = h;
        lo[i + j] = __float2bfloat16(f[j] - __bfloat162float(h));
    }
}

// ---------------------------------------------------------------------------
// Kernel 2b: transpose + split weights  W[k][n] -> Wt[n][k] bf16 hi/lo
// ---------------------------------------------------------------------------
__global__ void __launch_bounds__(1024) convert_w_kernel(
    const float* __restrict__ Wq, const float* __restrict__ Wk,
    const float* __restrict__ Wv)
{
    __shared__ float tile[32][33];
    int z = blockIdx.z;
    const float* W = (z == 0) ? Wq : (z == 1) ? Wk : Wv;
    int k0 = blockIdx.x * 32;
    int n0 = blockIdx.y * 32;
    int tx = threadIdx.x, ty = threadIdx.y;
    tile[ty][tx] = W[(size_t)(k0 + ty) * DM + n0 + tx];
    __syncthreads();
    float v = tile[tx][ty];          // = W[k0+tx][n0+ty]
    __nv_bfloat16 h = __float2bfloat16(v);
    size_t idx = (size_t)(n0 + ty) * DM + k0 + tx;
    g_Bhi[z][idx] = h;
    g_Blo[z][idx] = __float2bfloat16(v - __bfloat162float(h));
}

// ---------------------------------------------------------------------------
// Kernel 3: projection GEMM on tensor cores (mma.sync, bf16 2-term split).
// Y[m,n] = sum_k A[m,k] * Wt[n,k], M=4096, N=1024, K=1024, 3 passes.
// Block 128x128, 256 threads (8 warps, warp tile 64x32), BK=32,
// 2-stage cp.async double buffer, ldmatrix fragment loads.
// Smem rows padded to 40 bf16 (80B) -> conflict-free ldmatrix.
// ---------------------------------------------------------------------------
#define BK 32
#define ROWPAD 40                      // elements per padded row
#define TILE_ELE (128 * ROWPAD)        // 5120 elems = 10240 B
#define NT 96                          // 3 passes * 32 k-tiles

__global__ void __launch_bounds__(256) proj_mma_kernel() {
    __shared__ alignas(16) __nv_bfloat16 sA[2][TILE_ELE];
    __shared__ alignas(16) __nv_bfloat16 sB[2][TILE_ELE];

    const int tid  = threadIdx.x;
    const int lane = tid & 31;
    const int wid  = tid >> 5;        // 0..7
    const int wm   = wid >> 2;        // 0..1  (m block of 64)
    const int wn   = wid & 3;         // 0..3  (n block of 32)
    const int grp  = lane >> 2;       // 0..7
    const int q4   = lane & 3;        // 0..3

    const int z   = blockIdx.z;
    const int bm0 = blockIdx.y * 128;
    const int bn0 = blockIdx.x * 128;

    const __nv_bfloat16* Ahi = g_Ahi[z];
    const __nv_bfloat16* Alo = g_Alo[z];
    const __nv_bfloat16* Bhi = g_Bhi[z];
    const __nv_bfloat16* Blo = g_Blo[z];
    float* dst = (z == 0) ? g_q : (z == 1) ? g_k : g_v;

    const uint32_t sA0 = smem_u32(&sA[0][0]);
    const uint32_t sB0 = smem_u32(&sB[0][0]);

    float acc[4][4][4];
    #pragma unroll
    for (int i = 0; i < 4; i++)
        #pragma unroll
        for (int j = 0; j < 4; j++)
            #pragma unroll
            for (int r = 0; r < 4; r++) acc[i][j][r] = 0.0f;

    // ---- tile loader: 512 16B-chunks each for A and B; 2 per thread ----
    auto load_tile = [&](int t, int s) {
        int pass = t >> 5;
        int k0 = (t & 31) * BK;
        const __nv_bfloat16* Ap = (pass == 2) ? Alo : Ahi;
        const __nv_bfloat16* Bp = (pass == 1) ? Blo : Bhi;
        uint32_t da = sA0 + s * (TILE_ELE * 2);
        uint32_t db = sB0 + s * (TILE_ELE * 2);
        #pragma unroll
        for (int j = 0; j < 2; j++) {
            int id = tid + 256 * j;
            int row = id >> 2, part = id & 3;
            uint32_t off = (uint32_t)(row * 80 + part * 16);
            CP_ASYNC16(da + off, Ap + (size_t)(bm0 + row) * DM + k0 + part * 8);
            CP_ASYNC16(db + off, Bp + (size_t)(bn0 + row) * DM + k0 + part * 8);
        }
        CP_COMMIT();
    };

    // ldmatrix address components (lane-dependent, loop-invariant)
    const int l7  = lane & 7;
    const int l8  = (lane >> 3) & 1;
    const int l16 = (lane >> 4) & 1;

    load_tile(0, 0);

    for (int t = 0; t < NT; t++) {
        if (t + 1 < NT) {
            load_tile(t + 1, (t + 1) & 1);
            CP_WAIT(1);
        } else {
            CP_WAIT(0);
        }
        __syncthreads();

        uint32_t aBase = sA0 + (t & 1) * (TILE_ELE * 2);
        uint32_t bBase = sB0 + (t & 1) * (TILE_ELE * 2);

        #pragma unroll
        for (int ks = 0; ks < 2; ks++) {
            const int kb = ks * 16;
            uint32_t afrag[4][4], bfrag[4][2];
            // A: 4 m16 tiles. matrices: m = (l>>3)&1 selects row+8, k = (l>>4)*8
            #pragma unroll
            for (int mt = 0; mt < 4; mt++) {
                uint32_t addr = aBase +
                    (uint32_t)((wm * 64 + mt * 16 + l8 * 8 + l7) * 80 +
                               (kb + l16 * 8) * 2);
                LDMATRIX_X4(afrag[mt][0], afrag[mt][1], afrag[mt][2], afrag[mt][3], addr);
            }
            // B: 2 x4 loads cover 4 n8 tiles. matrices: n = (l>>4)*8, k = ((l>>3)&1)*8
            #pragma unroll
            for (int bp = 0; bp < 2; bp++) {
                uint32_t r0, r1, r2, r3;
                uint32_t addr = bBase +
                    (uint32_t)((wn * 32 + bp * 16 + l16 * 8 + l7) * 80 +
                               (kb + l8 * 8) * 2);
                LDMATRIX_X4(r0, r1, r2, r3, addr);
                bfrag[bp * 2 + 0][0] = r0; bfrag[bp * 2 + 0][1] = r1;
                bfrag[bp * 2 + 1][0] = r2; bfrag[bp * 2 + 1][1] = r3;
            }
            #pragma unroll
            for (int mt = 0; mt < 4; mt++)
                #pragma unroll
                for (int nt = 0; nt < 4; nt++)
                    mma_bf16(acc[mt][nt], afrag[mt], bfrag[nt]);
        }
        __syncthreads();
    }

    // ---- epilogue: scatter into [B][H][S][HEAD] ----
    #pragma unroll
    for (int mt = 0; mt < 4; mt++) {
        #pragma unroll
        for (int half = 0; half < 2; half++) {
            int m = bm0 + wm * 64 + mt * 16 + grp + half * 8;
            int bb = m >> 11;
            int ss = m & (SEQ - 1);
            size_t rowbase = ((size_t)bb * NHEADS) * (SEQ * HEAD) + (size_t)ss * HEAD;
            #pragma unroll
            for (int nt = 0; nt < 4; nt++) {
                int n = bn0 + wn * 32 + nt * 8 + q4 * 2;
                int h = n >> 6, d = n & 63;
                float2 v;
                v.x = acc[mt][nt][half * 2 + 0];
                v.y = acc[mt][nt][half * 2 + 1];
                *(float2*)&dst[rowbase + (size_t)h * (SEQ * HEAD) + d] = v;
            }
        }
    }
}

// ---------------------------------------------------------------------------
// Kernel 4: flash attention fp32 (unchanged, known-good)
// ---------------------------------------------------------------------------
__global__ void __launch_bounds__(128) attn_kernel(
    const float* __restrict__ key_mask, float* __restrict__ out)
{
    __shared__ float Ks[64][65];
    __shared__ float Vs[64][64];
    __shared__ float bwin[128];
    __shared__ float mwin[64];

    const int qt0 = blockIdx.x * 64;
    const int h   = blockIdx.y;
    const int b   = blockIdx.z;
    const int tid = threadIdx.x;
    const int tx  = tid & 7;
    const int ty  = tid >> 3;

    const size_t bh = ((size_t)(b * NHEADS + h)) << 17;
    const float* Qbh = g_q + bh;
    const float* Kbh = g_k + bh;
    const float* Vbh = g_v + bh;
    const float* bias_h = g_bias + h * 4096;

    float qreg[4][8];
    #pragma unroll
    for (int i = 0; i < 4; i++) {
        const float* qp = Qbh + (size_t)(qt0 + ty * 4 + i) * HEAD + tx * 8;
        float4 v0 = *(const float4*)(qp);
        float4 v1 = *(const float4*)(qp + 4);
        qreg[i][0] = v0.x; qreg[i][1] = v0.y; qreg[i][2] = v0.z; qreg[i][3] = v0.w;
        qreg[i][4] = v1.x; qreg[i][5] = v1.y; qreg[i][6] = v1.z; qreg[i][7] = v1.w;
    }

    float o[4][8];
    #pragma unroll
    for (int i = 0; i < 4; i++)
        #pragma unroll
        for (int j = 0; j < 8; j++) o[i][j] = 0.0f;
    float mrow[4], lrow[4];
    #pragma unroll
    for (int i = 0; i < 4; i++) { mrow[i] = -INFINITY; lrow[i] = 0.0f; }

    for (int kt0 = 0; kt0 < SEQ; kt0 += 64) {
        #pragma unroll
        for (int v = 0; v < 8; v++) {
            int e = (v * 128 + tid) * 4;
            int c = e >> 6, d = e & 63;
            float4 kv4 = *(const float4*)(Kbh + (size_t)(kt0 + c) * HEAD + d);
            Ks[c][d + 0] = kv4.x; Ks[c][d + 1] = kv4.y;
            Ks[c][d + 2] = kv4.z; Ks[c][d + 3] = kv4.w;
            float4 vv4 = *(const float4*)(Vbh + (size_t)(kt0 + c) * HEAD + d);
            *(float4*)&Vs[c][d] = vv4;
        }
        if (tid < 127) {
            int idx = kt0 - qt0 + tid - 63 + 2047;
            idx = max(0, min(4094, idx));
            bwin[tid] = bias_h[idx];
        }
        if (tid < 64) {
            float mk = key_mask[(size_t)b * SEQ + kt0 + tid];
            mwin[tid] = (1.0f - mk) * -10000.0f;
        }
        __syncthreads();

        float s[4][8];
        #pragma unroll
        for (int i = 0; i < 4; i++)
            #pragma unroll
            for (int j = 0; j < 8; j++) s[i][j] = 0.0f;

        const float* ksbase = &Ks[tx][0];
        for (int g = 0; g < 8; g++) {
            const float* kd = ksbase + g * 8;
            #pragma unroll
            for (int u = 0; u < 8; u++) {
                float kv[8];
                #pragma unroll
                for (int j = 0; j < 8; j++) kv[j] = kd[j * 8 * 65 + u];
                float qv[4];
                #pragma unroll
                for (int i = 0; i < 4; i++)
                    qv[i] = __shfl_sync(0xffffffffu, qreg[i][u], g, 8);
                #pragma unroll
                for (int i = 0; i < 4; i++)
                    #pragma unroll
                    for (int j = 0; j < 8; j++)
                        s[i][j] = fmaf(qv[i], kv[j], s[i][j]);
            }
        }

        float mt[4];
        #pragma unroll
        for (int i = 0; i < 4; i++) {
            int r = ty * 4 + i;
            float mx = -INFINITY;
            #pragma unroll
            for (int j = 0; j < 8; j++) {
                int c = tx + 8 * j;
                s[i][j] += bwin[c - r + 63] + mwin[c];
                mx = fmaxf(mx, s[i][j]);
            }
            mx = fmaxf(mx, __shfl_xor_sync(0xffffffffu, mx, 1, 8));
            mx = fmaxf(mx, __shfl_xor_sync(0xffffffffu, mx, 2, 8));
            mx = fmaxf(mx, __shfl_xor_sync(0xffffffffu, mx, 4, 8));
            mt[i] = mx;
        }

        __syncthreads();

        #pragma unroll
        for (int i = 0; i < 4; i++) {
            float mnew = fmaxf(mrow[i], mt[i]);
            float corr = __expf(mrow[i] - mnew);
            mrow[i] = mnew;
            float sum = 0.0f;
            #pragma unroll
            for (int j = 0; j < 8; j++) {
                float p = __expf(s[i][j] - mnew);
                s[i][j] = p;
                sum += p;
            }
            sum += __shfl_xor_sync(0xffffffffu, sum, 1, 8);
            sum += __shfl_xor_sync(0xffffffffu, sum, 2, 8);
            sum += __shfl_xor_sync(0xffffffffu, sum, 4, 8);
            lrow[i] = lrow[i] * corr + sum;
            #pragma unroll
            for (int j = 0; j < 8; j++) o[i][j] *= corr;
            #pragma unroll
            for (int j = 0; j < 8; j++)
                Ks[ty * 4 + i][tx + 8 * j] = s[i][j];
        }
        __syncthreads();

        #pragma unroll 4
        for (int k = 0; k < 64; k++) {
            float pk[4], vv[8];
            #pragma unroll
            for (int i = 0; i < 4; i++) pk[i] = Ks[ty * 4 + i][k];
            #pragma unroll
            for (int j = 0; j < 8; j++) vv[j] = Vs[k][tx + 8 * j];
            #pragma unroll
            for (int i = 0; i < 4; i++)
                #pragma unroll
                for (int j = 0; j < 8; j++)
                    o[i][j] = fmaf(pk[i], vv[j], o[i][j]);
        }
        __syncthreads();
    }

    #pragma unroll
    for (int i = 0; i < 4; i++) {
        int srow = qt0 + ty * 4 + i;
        float inv = 1.0f / lrow[i];
        #pragma unroll
        for (int j = 0; j < 8; j++) {
            int dc = tx + 8 * j;
            out[((size_t)(b * SEQ + srow)) * (NHEADS * HEAD) + h * HEAD + dc] =
                o[i][j] * inv;
        }
    }
}

// ---------------------------------------------------------------------------
// Launch
// ---------------------------------------------------------------------------
extern "C" void kernel_launch(void* const* d_in, const int* in_sizes, int n_in,
                              void* d_out, int out_size) {
    const float* query    = (const float*)d_in[0];
    const float* key      = (const float*)d_in[1];
    const float* value    = (const float*)d_in[2];
    const float* key_mask = (const float*)d_in[3];
    const float* Wq       = (const float*)d_in[4];
    const float* Wk       = (const float*)d_in[5];
    const float* Wv       = (const float*)d_in[6];
    const float* bias_tab = (const float*)d_in[7];
    float* out = (float*)d_out;

    bias_precompute_kernel<<<16, 256>>>(bias_tab);
    convert_x_kernel<<<dim3(4096, 3), 256>>>(query, key, value);
    convert_w_kernel<<<dim3(32, 32, 3), dim3(32, 32)>>>(Wq, Wk, Wv);
    proj_mma_kernel<<<dim3(8, 32, 3), 256>>>();
    attn_kernel<<<dim3(SEQ / 64, NHEADS, NB), 128>>>(key_mask, out);
}

// round 5
// speedup vs baseline: 2.2084x; 1.8364x over previous
#include <cuda_runtime.h>
#include <cuda_bf16.h>
#include <math.h>
#include <stdint.h>

// ---------------------------------------------------------------------------
// Problem constants (B=2, S=2048, D_MODEL=1024, H=16, Dh=64)
// ---------------------------------------------------------------------------
#define NB      2
#define SEQ     2048
#define DM      1024
#define NHEADS  16
#define HEAD    64

__device__ float g_bias[NHEADS * 4096];

// bf16 split operands for projection GEMMs
__device__ __nv_bfloat16 g_Ahi[3][4096 * 1024];
__device__ __nv_bfloat16 g_Alo[3][4096 * 1024];
__device__ __nv_bfloat16 g_Bhi[3][1024 * 1024];
__device__ __nv_bfloat16 g_Blo[3][1024 * 1024];

// Q/K/V split outputs of projections: [B][H][S][64] bf16 hi/lo
#define QKV_ELE (NB * NHEADS * SEQ * HEAD)
__device__ __nv_bfloat16 g_qhi[QKV_ELE], g_qlo[QKV_ELE];
__device__ __nv_bfloat16 g_khi[QKV_ELE], g_klo[QKV_ELE];
__device__ __nv_bfloat16 g_vhi[QKV_ELE], g_vlo[QKV_ELE];

// ---------------------------------------------------------------------------
// PTX helpers
// ---------------------------------------------------------------------------
__device__ __forceinline__ uint32_t smem_u32(const void* p) {
    uint32_t a;
    asm("{ .reg .u64 t; cvta.to.shared.u64 t, %1; cvt.u32.u64 %0, t; }"
        : "=r"(a) : "l"(p));
    return a;
}
#define CP_ASYNC16(dst, src) \
    asm volatile("cp.async.cg.shared.global [%0], [%1], 16;" :: "r"(dst), "l"(src))
#define CP_COMMIT() asm volatile("cp.async.commit_group;" ::: "memory")
#define CP_WAIT(n)  asm volatile("cp.async.wait_group %0;" :: "n"(n) : "memory")

#define LDMATRIX_X4(r0, r1, r2, r3, addr) \
    asm volatile("ldmatrix.sync.aligned.m8n8.x4.shared.b16 {%0,%1,%2,%3}, [%4];" \
                 : "=r"(r0), "=r"(r1), "=r"(r2), "=r"(r3) : "r"(addr))
#define LDMATRIX_X4T(r0, r1, r2, r3, addr) \
    asm volatile("ldmatrix.sync.aligned.m8n8.x4.trans.shared.b16 {%0,%1,%2,%3}, [%4];" \
                 : "=r"(r0), "=r"(r1), "=r"(r2), "=r"(r3) : "r"(addr))

__device__ __forceinline__ void mma_bf16(float* d, const uint32_t* a,
                                         const uint32_t* b) {
    asm volatile(
        "mma.sync.aligned.m16n8k16.row.col.f32.bf16.bf16.f32 "
        "{%0,%1,%2,%3}, {%4,%5,%6,%7}, {%8,%9}, {%0,%1,%2,%3};"
        : "+f"(d[0]), "+f"(d[1]), "+f"(d[2]), "+f"(d[3])
        : "r"(a[0]), "r"(a[1]), "r"(a[2]), "r"(a[3]), "r"(b[0]), "r"(b[1]));
}
__device__ __forceinline__ uint32_t pack_bf2(float a, float b) {
    __nv_bfloat162 t = __floats2bfloat162_rn(a, b);
    return *(uint32_t*)&t;
}

// ---------------------------------------------------------------------------
// Kernel 1: relative-position bias table expansion (known-good)
// ---------------------------------------------------------------------------
__global__ void bias_precompute_kernel(const float* __restrict__ bias_table) {
    int i = blockIdx.x * blockDim.x + threadIdx.x;
    if (i >= 4095) return;
    int delta = i - 2047;
    int ret = (delta > 0) ? 16 : 0;
    int rp = abs(delta);
    int bucket;
    if (rp < 8) {
        bucket = ret + rp;
    } else {
        int vl;
        if ((rp & (rp - 1)) == 0) {
            int k = __ffs(rp) - 1;
            vl = 8 + 2 * (k - 3);
        } else {
            float t = logf((float)rp * 0.125f) / 2.7725887f;
            vl = 8 + (int)(t * 8.0f);
        }
        bucket = ret + min(vl, 15);
    }
    #pragma unroll
    for (int h = 0; h < NHEADS; h++)
        g_bias[h * 4096 + i] = bias_table[bucket * NHEADS + h];
}

// ---------------------------------------------------------------------------
// Kernel 2a: split activations X -> bf16 hi/lo
// ---------------------------------------------------------------------------
__global__ void __launch_bounds__(256) convert_x_kernel(
    const float* __restrict__ Xq, const float* __restrict__ Xk,
    const float* __restrict__ Xv)
{
    int z = blockIdx.y;
    const float* X = (z == 0) ? Xq : (z == 1) ? Xk : Xv;
    __nv_bfloat16* hi = g_Ahi[z];
    __nv_bfloat16* lo = g_Alo[z];
    size_t i = ((size_t)blockIdx.x * 256 + threadIdx.x) * 4;
    float4 v = *(const float4*)(X + i);
    float f[4] = {v.x, v.y, v.z, v.w};
    #pragma unroll
    for (int j = 0; j < 4; j++) {
        __nv_bfloat16 h = __float2bfloat16(f[j]);
        hi[i + j] = h;
        lo[i + j] = __float2bfloat16(f[j] - __bfloat162float(h));
    }
}

// ---------------------------------------------------------------------------
// Kernel 2b: transpose + split weights  W[k][n] -> Wt[n][k] bf16 hi/lo
// ---------------------------------------------------------------------------
__global__ void __launch_bounds__(1024) convert_w_kernel(
    const float* __restrict__ Wq, const float* __restrict__ Wk,
    const float* __restrict__ Wv)
{
    __shared__ float tile[32][33];
    int z = blockIdx.z;
    const float* W = (z == 0) ? Wq : (z == 1) ? Wk : Wv;
    int k0 = blockIdx.x * 32;
    int n0 = blockIdx.y * 32;
    int tx = threadIdx.x, ty = threadIdx.y;
    tile[ty][tx] = W[(size_t)(k0 + ty) * DM + n0 + tx];
    __syncthreads();
    float v = tile[tx][ty];
    __nv_bfloat16 h = __float2bfloat16(v);
    size_t idx = (size_t)(n0 + ty) * DM + k0 + tx;
    g_Bhi[z][idx] = h;
    g_Blo[z][idx] = __float2bfloat16(v - __bfloat162float(h));
}

// ---------------------------------------------------------------------------
// Kernel 3: projection GEMM (mma.sync, bf16 2-term split, 3 passes).
// Epilogue writes bf16 hi/lo Q/K/V in [B][H][S][64].
// ---------------------------------------------------------------------------
#define BK 32
#define TILE_ELE (128 * 40)
#define NT 96

__global__ void __launch_bounds__(256) proj_mma_kernel() {
    __shared__ alignas(16) __nv_bfloat16 sA[2][TILE_ELE];
    __shared__ alignas(16) __nv_bfloat16 sB[2][TILE_ELE];

    const int tid  = threadIdx.x;
    const int lane = tid & 31;
    const int wid  = tid >> 5;
    const int wm   = wid >> 2;
    const int wn   = wid & 3;
    const int grp  = lane >> 2;
    const int q4   = lane & 3;

    const int z   = blockIdx.z;
    const int bm0 = blockIdx.y * 128;
    const int bn0 = blockIdx.x * 128;

    const __nv_bfloat16* Ahi = g_Ahi[z];
    const __nv_bfloat16* Alo = g_Alo[z];
    const __nv_bfloat16* Bhi = g_Bhi[z];
    const __nv_bfloat16* Blo = g_Blo[z];
    __nv_bfloat16* dhi = (z == 0) ? g_qhi : (z == 1) ? g_khi : g_vhi;
    __nv_bfloat16* dlo = (z == 0) ? g_qlo : (z == 1) ? g_klo : g_vlo;

    const uint32_t sA0 = smem_u32(&sA[0][0]);
    const uint32_t sB0 = smem_u32(&sB[0][0]);

    float acc[4][4][4];
    #pragma unroll
    for (int i = 0; i < 4; i++)
        #pragma unroll
        for (int j = 0; j < 4; j++)
            #pragma unroll
            for (int r = 0; r < 4; r++) acc[i][j][r] = 0.0f;

    auto load_tile = [&](int t, int s) {
        int pass = t >> 5;
        int k0 = (t & 31) * BK;
        const __nv_bfloat16* Ap = (pass == 2) ? Alo : Ahi;
        const __nv_bfloat16* Bp = (pass == 1) ? Blo : Bhi;
        uint32_t da = sA0 + s * (TILE_ELE * 2);
        uint32_t db = sB0 + s * (TILE_ELE * 2);
        #pragma unroll
        for (int j = 0; j < 2; j++) {
            int id = tid + 256 * j;
            int row = id >> 2, part = id & 3;
            uint32_t off = (uint32_t)(row * 80 + part * 16);
            CP_ASYNC16(da + off, Ap + (size_t)(bm0 + row) * DM + k0 + part * 8);
            CP_ASYNC16(db + off, Bp + (size_t)(bn0 + row) * DM + k0 + part * 8);
        }
        CP_COMMIT();
    };

    const int l7  = lane & 7;
    const int l8  = (lane >> 3) & 1;
    const int l16 = (lane >> 4) & 1;

    load_tile(0, 0);

    for (int t = 0; t < NT; t++) {
        if (t + 1 < NT) {
            load_tile(t + 1, (t + 1) & 1);
            CP_WAIT(1);
        } else {
            CP_WAIT(0);
        }
        __syncthreads();

        uint32_t aBase = sA0 + (t & 1) * (TILE_ELE * 2);
        uint32_t bBase = sB0 + (t & 1) * (TILE_ELE * 2);

        #pragma unroll
        for (int ks = 0; ks < 2; ks++) {
            const int kb = ks * 16;
            uint32_t afrag[4][4], bfrag[4][2];
            #pragma unroll
            for (int mt = 0; mt < 4; mt++) {
                uint32_t addr = aBase +
                    (uint32_t)((wm * 64 + mt * 16 + l8 * 8 + l7) * 80 +
                               (kb + l16 * 8) * 2);
                LDMATRIX_X4(afrag[mt][0], afrag[mt][1], afrag[mt][2], afrag[mt][3], addr);
            }
            #pragma unroll
            for (int bp = 0; bp < 2; bp++) {
                uint32_t r0, r1, r2, r3;
                uint32_t addr = bBase +
                    (uint32_t)((wn * 32 + bp * 16 + l16 * 8 + l7) * 80 +
                               (kb + l8 * 8) * 2);
                LDMATRIX_X4(r0, r1, r2, r3, addr);
                bfrag[bp * 2 + 0][0] = r0; bfrag[bp * 2 + 0][1] = r1;
                bfrag[bp * 2 + 1][0] = r2; bfrag[bp * 2 + 1][1] = r3;
            }
            #pragma unroll
            for (int mt = 0; mt < 4; mt++)
                #pragma unroll
                for (int nt = 0; nt < 4; nt++)
                    mma_bf16(acc[mt][nt], afrag[mt], bfrag[nt]);
        }
        __syncthreads();
    }

    // epilogue: split into bf16 hi/lo, scatter into [B][H][S][64]
    #pragma unroll
    for (int mt = 0; mt < 4; mt++) {
        #pragma unroll
        for (int half = 0; half < 2; half++) {
            int m = bm0 + wm * 64 + mt * 16 + grp + half * 8;
            int bb = m >> 11;
            int ss = m & (SEQ - 1);
            #pragma unroll
            for (int nt = 0; nt < 4; nt++) {
                int n = bn0 + wn * 32 + nt * 8 + q4 * 2;
                int h = n >> 6, d = n & 63;
                float x = acc[mt][nt][half * 2 + 0];
                float y = acc[mt][nt][half * 2 + 1];
                float xh = __bfloat162float(__float2bfloat16(x));
                float yh = __bfloat162float(__float2bfloat16(y));
                size_t idx = (((size_t)(bb * NHEADS + h) * SEQ + ss) << 6) + d;
                *(uint32_t*)&dhi[idx] = pack_bf2(x, y);
                *(uint32_t*)&dlo[idx] = pack_bf2(x - xh, y - yh);
            }
        }
    }
}

// ---------------------------------------------------------------------------
// Kernel 4: flash attention on tensor cores, bf16 split, fp32 softmax.
// grid (16 qtiles, 16 heads, 2 batch), 256 threads (8 warps x 16 q-rows).
// BN=64 key tiles, cp.async double buffer (Khi/Klo/Vhi/Vlo), 144B rows.
// ---------------------------------------------------------------------------
#define AT_RB   144                     // bytes per padded row (72 bf16)
#define AT_TILE (64 * AT_RB)            // 9216 B per 64x64 tile
#define KV_OFF  0                       // [stage][arr] arr: 0 Khi 1 Klo 2 Vhi 3 Vlo
#define Q_OFF   (8 * AT_TILE)           // 73728: Qhi, Qlo 128x144B each
#define BW_OFF  (Q_OFF + 2 * 128 * AT_RB)   // 110592: bwin[2][192] f32
#define MW_OFF  (BW_OFF + 2 * 192 * 4)      // 112128: mwin[2][64] f32
#define AT_SMEM (MW_OFF + 2 * 64 * 4)       // 112640

__global__ void __launch_bounds__(256, 1) attn_mma_kernel(
    const float* __restrict__ key_mask, float* __restrict__ out)
{
    extern __shared__ char dsm[];
    const uint32_t sb = smem_u32(dsm);

    const int tid  = threadIdx.x;
    const int lane = tid & 31;
    const int wid  = tid >> 5;
    const int g    = lane >> 2;
    const int q4   = lane & 3;
    const int l7   = lane & 7;
    const int l8   = (lane >> 3) & 1;
    const int l16  = (lane >> 4) & 1;

    const int qt0 = blockIdx.x * 128;
    const int h   = blockIdx.y;
    const int b   = blockIdx.z;
    const size_t bh = ((size_t)(b * NHEADS + h)) << 17;   // *SEQ*HEAD

    const __nv_bfloat16* Khi = g_khi + bh;
    const __nv_bfloat16* Klo = g_klo + bh;
    const __nv_bfloat16* Vhi = g_vhi + bh;
    const __nv_bfloat16* Vlo = g_vlo + bh;
    const float* bias_h = g_bias + h * 4096;

    // ---- issue Q loads (group 0) ----
    {
        const __nv_bfloat16* srcs[2] = { g_qhi + bh, g_qlo + bh };
        #pragma unroll
        for (int arr = 0; arr < 2; arr++)
            #pragma unroll
            for (int jj = 0; jj < 4; jj++) {
                int rem = jj * 256 + tid;          // 0..1023
                int row = rem >> 3, part = rem & 7;
                uint32_t dst = sb + Q_OFF + arr * (128 * AT_RB) + row * AT_RB + part * 16;
                CP_ASYNC16(dst, srcs[arr] + (size_t)(qt0 + row) * HEAD + part * 8);
            }
        CP_COMMIT();
    }

    auto issue_kv = [&](int kt, int s) {
        const __nv_bfloat16* srcs[4] = { Khi, Klo, Vhi, Vlo };
        #pragma unroll
        for (int arr = 0; arr < 4; arr++)
            #pragma unroll
            for (int jj = 0; jj < 2; jj++) {
                int rem = jj * 256 + tid;          // 0..511
                int row = rem >> 3, part = rem & 7;
                uint32_t dst = sb + (s * 4 + arr) * AT_TILE + row * AT_RB + part * 16;
                CP_ASYNC16(dst, srcs[arr] + (size_t)(kt * 64 + row) * HEAD + part * 8);
            }
        CP_COMMIT();
        // bias + mask windows (plain ld/st)
        float* bw = (float*)(dsm + BW_OFF + s * 768);
        float* mw = (float*)(dsm + MW_OFF + s * 256);
        if (tid < 192) {
            int idx = kt * 64 + tid - 127 - qt0 + 2047;
            idx = max(0, min(4094, idx));
            bw[tid] = bias_h[idx];
        }
        if (tid < 64) {
            float mk = key_mask[(size_t)b * SEQ + kt * 64 + tid];
            mw[tid] = (1.0f - mk) * -10000.0f;
        }
    };

    issue_kv(0, 0);

    uint32_t qhi[4][4], qlo[4][4];
    float oacc[8][4];
    #pragma unroll
    for (int nt = 0; nt < 8; nt++)
        #pragma unroll
        for (int r = 0; r < 4; r++) oacc[nt][r] = 0.0f;
    float mrow[2] = { -INFINITY, -INFINITY };
    float lrow[2] = { 0.0f, 0.0f };

    for (int t = 0; t < SEQ / 64; t++) {
        __syncthreads();                 // stage (t+1)&1 free for reuse
        if (t + 1 < SEQ / 64) {
            issue_kv(t + 1, (t + 1) & 1);
            CP_WAIT(1);
        } else {
            CP_WAIT(0);
        }
        __syncthreads();                 // tile t (and Q) visible

        if (t == 0) {
            #pragma unroll
            for (int kk = 0; kk < 4; kk++) {
                uint32_t ah = sb + Q_OFF + (wid * 16 + l8 * 8 + l7) * AT_RB +
                              (kk * 16 + l16 * 8) * 2;
                LDMATRIX_X4(qhi[kk][0], qhi[kk][1], qhi[kk][2], qhi[kk][3], ah);
                uint32_t al = ah + 128 * AT_RB;
                LDMATRIX_X4(qlo[kk][0], qlo[kk][1], qlo[kk][2], qlo[kk][3], al);
            }
        }

        const int s = t & 1;
        const uint32_t kb_hi = sb + (s * 4 + 0) * AT_TILE;
        const uint32_t kb_lo = sb + (s * 4 + 1) * AT_TILE;
        const uint32_t vb_hi = sb + (s * 4 + 2) * AT_TILE;
        const uint32_t vb_lo = sb + (s * 4 + 3) * AT_TILE;
        const float* bw = (const float*)(dsm + BW_OFF + s * 768);
        const float* mw = (const float*)(dsm + MW_OFF + s * 256);

        // ---- S = Q K^T (3-pass split) ----
        float sacc[8][4];
        #pragma unroll
        for (int nt = 0; nt < 8; nt++)
            #pragma unroll
            for (int r = 0; r < 4; r++) sacc[nt][r] = 0.0f;

        #pragma unroll
        for (int kk = 0; kk < 4; kk++) {
            uint32_t bhif[8][2], blof[8][2];
            #pragma unroll
            for (int bp = 0; bp < 4; bp++) {
                uint32_t off = (uint32_t)((bp * 16 + l16 * 8 + l7) * AT_RB +
                                          (kk * 16 + l8 * 8) * 2);
                uint32_t r0, r1, r2, r3;
                LDMATRIX_X4(r0, r1, r2, r3, kb_hi + off);
                bhif[bp * 2][0] = r0; bhif[bp * 2][1] = r1;
                bhif[bp * 2 + 1][0] = r2; bhif[bp * 2 + 1][1] = r3;
                LDMATRIX_X4(r0, r1, r2, r3, kb_lo + off);
                blof[bp * 2][0] = r0; blof[bp * 2][1] = r1;
                blof[bp * 2 + 1][0] = r2; blof[bp * 2 + 1][1] = r3;
            }
            #pragma unroll
            for (int nt = 0; nt < 8; nt++) {
                mma_bf16(sacc[nt], qhi[kk], bhif[nt]);
                mma_bf16(sacc[nt], qlo[kk], bhif[nt]);
                mma_bf16(sacc[nt], qhi[kk], blof[nt]);
            }
        }

        // ---- softmax in registers ----
        #pragma unroll
        for (int hl = 0; hl < 2; hl++) {
            int rr = wid * 16 + g + hl * 8;     // CTA-local q row
            float mx = -INFINITY;
            #pragma unroll
            for (int nt = 0; nt < 8; nt++) {
                #pragma unroll
                for (int e = 0; e < 2; e++) {
                    int c = nt * 8 + q4 * 2 + e;
                    float v = sacc[nt][hl * 2 + e] + bw[c - rr + 127] + mw[c];
                    sacc[nt][hl * 2 + e] = v;
                    mx = fmaxf(mx, v);
                }
            }
            mx = fmaxf(mx, __shfl_xor_sync(0xffffffffu, mx, 1));
            mx = fmaxf(mx, __shfl_xor_sync(0xffffffffu, mx, 2));
            float mnew = fmaxf(mrow[hl], mx);
            float corr = __expf(mrow[hl] - mnew);
            mrow[hl] = mnew;
            float sum = 0.0f;
            #pragma unroll
            for (int nt = 0; nt < 8; nt++) {
                #pragma unroll
                for (int e = 0; e < 2; e++) {
                    float p = __expf(sacc[nt][hl * 2 + e] - mnew);
                    sacc[nt][hl * 2 + e] = p;
                    sum += p;
                }
            }
            sum += __shfl_xor_sync(0xffffffffu, sum, 1);
            sum += __shfl_xor_sync(0xffffffffu, sum, 2);
            lrow[hl] = lrow[hl] * corr + sum;
            #pragma unroll
            for (int nt = 0; nt < 8; nt++) {
                oacc[nt][hl * 2 + 0] *= corr;
                oacc[nt][hl * 2 + 1] *= corr;
            }
        }

        // ---- P -> bf16 hi/lo A-fragments ----
        uint32_t phi[4][4], plo[4][4];
        #pragma unroll
        for (int kk = 0; kk < 4; kk++) {
            #pragma unroll
            for (int part = 0; part < 4; part++) {
                int nt = 2 * kk + (part >> 1);
                int o = (part & 1) * 2;
                float p0 = sacc[nt][o], p1 = sacc[nt][o + 1];
                float h0 = __bfloat162float(__float2bfloat16(p0));
                float h1 = __bfloat162float(__float2bfloat16(p1));
                phi[kk][part] = pack_bf2(p0, p1);
                plo[kk][part] = pack_bf2(p0 - h0, p1 - h1);
            }
        }

        // ---- O += P V (3-pass split), V via trans ldmatrix ----
        #pragma unroll
        for (int kk = 0; kk < 4; kk++) {
            uint32_t vhif[8][2], vlof[8][2];
            #pragma unroll
            for (int db = 0; db < 4; db++) {
                uint32_t off = (uint32_t)((kk * 16 + l8 * 8 + l7) * AT_RB +
                                          (db * 16 + l16 * 8) * 2);
                uint32_t r0, r1, r2, r3;
                LDMATRIX_X4T(r0, r1, r2, r3, vb_hi + off);
                vhif[db * 2][0] = r0; vhif[db * 2][1] = r1;
                vhif[db * 2 + 1][0] = r2; vhif[db * 2 + 1][1] = r3;
                LDMATRIX_X4T(r0, r1, r2, r3, vb_lo + off);
                vlof[db * 2][0] = r0; vlof[db * 2][1] = r1;
                vlof[db * 2 + 1][0] = r2; vlof[db * 2 + 1][1] = r3;
            }
            #pragma unroll
            for (int nt = 0; nt < 8; nt++) {
                mma_bf16(oacc[nt], phi[kk], vhif[nt]);
                mma_bf16(oacc[nt], plo[kk], vhif[nt]);
                mma_bf16(oacc[nt], phi[kk], vlof[nt]);
            }
        }
    }

    // ---- epilogue: out[b][qrow][h*64 + d] = O / l ----
    #pragma unroll
    for (int hl = 0; hl < 2; hl++) {
        int rr = wid * 16 + g + hl * 8;
        float inv = 1.0f / lrow[hl];
        size_t base = ((size_t)(b * SEQ + qt0 + rr)) * (NHEADS * HEAD) + h * HEAD;
        #pragma unroll
        for (int nt = 0; nt < 8; nt++) {
            int c = nt * 8 + q4 * 2;
            float2 v;
            v.x = oacc[nt][hl * 2 + 0] * inv;
            v.y = oacc[nt][hl * 2 + 1] * inv;
            *(float2*)&out[base + c] = v;
        }
    }
}

// ---------------------------------------------------------------------------
// Launch
// ---------------------------------------------------------------------------
extern "C" void kernel_launch(void* const* d_in, const int* in_sizes, int n_in,
                              void* d_out, int out_size) {
    const float* query    = (const float*)d_in[0];
    const float* key      = (const float*)d_in[1];
    const float* value    = (const float*)d_in[2];
    const float* key_mask = (const float*)d_in[3];
    const float* Wq       = (const float*)d_in[4];
    const float* Wk       = (const float*)d_in[5];
    const float* Wv       = (const float*)d_in[6];
    const float* bias_tab = (const float*)d_in[7];
    float* out = (float*)d_out;

    cudaFuncSetAttribute(attn_mma_kernel,
                         cudaFuncAttributeMaxDynamicSharedMemorySize, AT_SMEM);

    bias_precompute_kernel<<<16, 256>>>(bias_tab);
    convert_x_kernel<<<dim3(4096, 3), 256>>>(query, key, value);
    convert_w_kernel<<<dim3(32, 32, 3), dim3(32, 32)>>>(Wq, Wk, Wv);
    proj_mma_kernel<<<dim3(8, 32, 3), 256>>>();
    attn_mma_kernel<<<dim3(SEQ / 128, NHEADS, NB), 256, AT_SMEM>>>(key_mask, out);
}

// round 7
// speedup vs baseline: 2.4460x; 1.1076x over previous
#include <cuda_runtime.h>
#include <cuda_bf16.h>
#include <math.h>
#include <stdint.h>

// ---------------------------------------------------------------------------
// Problem constants (B=2, S=2048, D_MODEL=1024, H=16, Dh=64)
// ---------------------------------------------------------------------------
#define NB      2
#define SEQ     2048
#define DM      1024
#define NHEADS  16
#define HEAD    64

__device__ float g_bias[NHEADS * 4096];

// bf16 split operands for projection GEMMs
__device__ __nv_bfloat16 g_Ahi[3][4096 * 1024];
__device__ __nv_bfloat16 g_Alo[3][4096 * 1024];
__device__ __nv_bfloat16 g_Bhi[3][1024 * 1024];
__device__ __nv_bfloat16 g_Blo[3][1024 * 1024];

// Q/K/V split outputs of projections: [B][H][S][64] bf16 hi/lo
#define QKV_ELE (NB * NHEADS * SEQ * HEAD)
__device__ __nv_bfloat16 g_qhi[QKV_ELE], g_qlo[QKV_ELE];
__device__ __nv_bfloat16 g_khi[QKV_ELE], g_klo[QKV_ELE];
__device__ __nv_bfloat16 g_vhi[QKV_ELE], g_vlo[QKV_ELE];

// ---------------------------------------------------------------------------
// PTX helpers
// ---------------------------------------------------------------------------
__device__ __forceinline__ uint32_t smem_u32(const void* p) {
    uint32_t a;
    asm("{ .reg .u64 t; cvta.to.shared.u64 t, %1; cvt.u32.u64 %0, t; }"
        : "=r"(a) : "l"(p));
    return a;
}
#define CP_ASYNC16(dst, src) \
    asm volatile("cp.async.cg.shared.global [%0], [%1], 16;" :: "r"(dst), "l"(src))
#define CP_COMMIT() asm volatile("cp.async.commit_group;" ::: "memory")
#define CP_WAIT(n)  asm volatile("cp.async.wait_group %0;" :: "n"(n) : "memory")

#define LDMATRIX_X4(r0, r1, r2, r3, addr) \
    asm volatile("ldmatrix.sync.aligned.m8n8.x4.shared.b16 {%0,%1,%2,%3}, [%4];" \
                 : "=r"(r0), "=r"(r1), "=r"(r2), "=r"(r3) : "r"(addr))
#define LDMATRIX_X4T(r0, r1, r2, r3, addr) \
    asm volatile("ldmatrix.sync.aligned.m8n8.x4.trans.shared.b16 {%0,%1,%2,%3}, [%4];" \
                 : "=r"(r0), "=r"(r1), "=r"(r2), "=r"(r3) : "r"(addr))

__device__ __forceinline__ void mma_bf16(float* d, const uint32_t* a,
                                         const uint32_t* b) {
    asm volatile(
        "mma.sync.aligned.m16n8k16.row.col.f32.bf16.bf16.f32 "
        "{%0,%1,%2,%3}, {%4,%5,%6,%7}, {%8,%9}, {%0,%1,%2,%3};"
        : "+f"(d[0]), "+f"(d[1]), "+f"(d[2]), "+f"(d[3])
        : "r"(a[0]), "r"(a[1]), "r"(a[2]), "r"(a[3]), "r"(b[0]), "r"(b[1]));
}
__device__ __forceinline__ uint32_t pack_bf2(float a, float b) {
    __nv_bfloat162 t = __floats2bfloat162_rn(a, b);
    return *(uint32_t*)&t;
}

// ---------------------------------------------------------------------------
// Kernel 1: relative-position bias table expansion (known-good)
// ---------------------------------------------------------------------------
__global__ void bias_precompute_kernel(const float* __restrict__ bias_table) {
    int i = blockIdx.x * blockDim.x + threadIdx.x;
    if (i >= 4095) return;
    int delta = i - 2047;
    int ret = (delta > 0) ? 16 : 0;
    int rp = abs(delta);
    int bucket;
    if (rp < 8) {
        bucket = ret + rp;
    } else {
        int vl;
        if ((rp & (rp - 1)) == 0) {
            int k = __ffs(rp) - 1;
            vl = 8 + 2 * (k - 3);
        } else {
            float t = logf((float)rp * 0.125f) / 2.7725887f;
            vl = 8 + (int)(t * 8.0f);
        }
        bucket = ret + min(vl, 15);
    }
    #pragma unroll
    for (int h = 0; h < NHEADS; h++)
        g_bias[h * 4096 + i] = bias_table[bucket * NHEADS + h];
}

// ---------------------------------------------------------------------------
// Kernel 2a: split activations X -> bf16 hi/lo
// ---------------------------------------------------------------------------
__global__ void __launch_bounds__(256) convert_x_kernel(
    const float* __restrict__ Xq, const float* __restrict__ Xk,
    const float* __restrict__ Xv)
{
    int z = blockIdx.y;
    const float* X = (z == 0) ? Xq : (z == 1) ? Xk : Xv;
    __nv_bfloat16* hi = g_Ahi[z];
    __nv_bfloat16* lo = g_Alo[z];
    size_t i = ((size_t)blockIdx.x * 256 + threadIdx.x) * 4;
    float4 v = *(const float4*)(X + i);
    float f[4] = {v.x, v.y, v.z, v.w};
    #pragma unroll
    for (int j = 0; j < 4; j++) {
        __nv_bfloat16 h = __float2bfloat16(f[j]);
        hi[i + j] = h;
        lo[i + j] = __float2bfloat16(f[j] - __bfloat162float(h));
    }
}

// ---------------------------------------------------------------------------
// Kernel 2b: transpose + split weights  W[k][n] -> Wt[n][k] bf16 hi/lo
// ---------------------------------------------------------------------------
__global__ void __launch_bounds__(1024) convert_w_kernel(
    const float* __restrict__ Wq, const float* __restrict__ Wk,
    const float* __restrict__ Wv)
{
    __shared__ float tile[32][33];
    int z = blockIdx.z;
    const float* W = (z == 0) ? Wq : (z == 1) ? Wk : Wv;
    int k0 = blockIdx.x * 32;
    int n0 = blockIdx.y * 32;
    int tx = threadIdx.x, ty = threadIdx.y;
    tile[ty][tx] = W[(size_t)(k0 + ty) * DM + n0 + tx];
    __syncthreads();
    float v = tile[tx][ty];
    __nv_bfloat16 h = __float2bfloat16(v);
    size_t idx = (size_t)(n0 + ty) * DM + k0 + tx;
    g_Bhi[z][idx] = h;
    g_Blo[z][idx] = __float2bfloat16(v - __bfloat162float(h));
}

// ---------------------------------------------------------------------------
// Kernel 3: projection GEMM (mma.sync, bf16 2-term split, 3 passes).
// 3-stage cp.async ring (DYNAMIC smem, 61440 B), ONE __syncthreads per tile.
// Epilogue writes bf16 hi/lo Q/K/V in [B][H][S][64].
// ---------------------------------------------------------------------------
#define BK 32
#define TILE_BYTES (128 * 80)           // 10240 B per operand tile
#define NT 96
#define PNS 3
#define PROJ_SMEM (PNS * 2 * TILE_BYTES)   // 61440 B

__global__ void __launch_bounds__(256) proj_mma_kernel() {
    extern __shared__ char psm[];

    const int tid  = threadIdx.x;
    const int lane = tid & 31;
    const int wid  = tid >> 5;
    const int wm   = wid >> 2;
    const int wn   = wid & 3;
    const int grp  = lane >> 2;
    const int q4   = lane & 3;

    const int z   = blockIdx.z;
    const int bm0 = blockIdx.y * 128;
    const int bn0 = blockIdx.x * 128;

    const __nv_bfloat16* Ahi = g_Ahi[z];
    const __nv_bfloat16* Alo = g_Alo[z];
    const __nv_bfloat16* Bhi = g_Bhi[z];
    const __nv_bfloat16* Blo = g_Blo[z];
    __nv_bfloat16* dhi = (z == 0) ? g_qhi : (z == 1) ? g_khi : g_vhi;
    __nv_bfloat16* dlo = (z == 0) ? g_qlo : (z == 1) ? g_klo : g_vlo;

    const uint32_t sA0 = smem_u32(psm);                       // [PNS][10240]
    const uint32_t sB0 = sA0 + PNS * TILE_BYTES;              // [PNS][10240]

    float acc[4][4][4];
    #pragma unroll
    for (int i = 0; i < 4; i++)
        #pragma unroll
        for (int j = 0; j < 4; j++)
            #pragma unroll
            for (int r = 0; r < 4; r++) acc[i][j][r] = 0.0f;

    auto load_tile = [&](int t, int s) {
        int pass = t >> 5;
        int k0 = (t & 31) * BK;
        const __nv_bfloat16* Ap = (pass == 2) ? Alo : Ahi;
        const __nv_bfloat16* Bp = (pass == 1) ? Blo : Bhi;
        uint32_t da = sA0 + s * TILE_BYTES;
        uint32_t db = sB0 + s * TILE_BYTES;
        #pragma unroll
        for (int j = 0; j < 2; j++) {
            int id = tid + 256 * j;
            int row = id >> 2, part = id & 3;
            uint32_t off = (uint32_t)(row * 80 + part * 16);
            CP_ASYNC16(da + off, Ap + (size_t)(bm0 + row) * DM + k0 + part * 8);
            CP_ASYNC16(db + off, Bp + (size_t)(bn0 + row) * DM + k0 + part * 8);
        }
        CP_COMMIT();
    };

    const int l7  = lane & 7;
    const int l8  = (lane >> 3) & 1;
    const int l16 = (lane >> 4) & 1;

    load_tile(0, 0);
    load_tile(1, 1);

    for (int t = 0; t < NT; t++) {
        if (t + 1 < NT) CP_WAIT(1);
        else            CP_WAIT(0);
        __syncthreads();                  // single barrier per iteration

        int s = t % PNS;
        uint32_t aBase = sA0 + s * TILE_BYTES;
        uint32_t bBase = sB0 + s * TILE_BYTES;

        #pragma unroll
        for (int ks = 0; ks < 2; ks++) {
            const int kb = ks * 16;
            uint32_t afrag[4][4], bfrag[4][2];
            #pragma unroll
            for (int mt = 0; mt < 4; mt++) {
                uint32_t addr = aBase +
                    (uint32_t)((wm * 64 + mt * 16 + l8 * 8 + l7) * 80 +
                               (kb + l16 * 8) * 2);
                LDMATRIX_X4(afrag[mt][0], afrag[mt][1], afrag[mt][2], afrag[mt][3], addr);
            }
            #pragma unroll
            for (int bp = 0; bp < 2; bp++) {
                uint32_t r0, r1, r2, r3;
                uint32_t addr = bBase +
                    (uint32_t)((wn * 32 + bp * 16 + l16 * 8 + l7) * 80 +
                               (kb + l8 * 8) * 2);
                LDMATRIX_X4(r0, r1, r2, r3, addr);
                bfrag[bp * 2 + 0][0] = r0; bfrag[bp * 2 + 0][1] = r1;
                bfrag[bp * 2 + 1][0] = r2; bfrag[bp * 2 + 1][1] = r3;
            }
            #pragma unroll
            for (int mt = 0; mt < 4; mt++)
                #pragma unroll
                for (int nt = 0; nt < 4; nt++)
                    mma_bf16(acc[mt][nt], afrag[mt], bfrag[nt]);
        }

        // issue next-next tile into stage (t+2)%3 == (t-1)%3 (already consumed)
        if (t + 2 < NT) load_tile(t + 2, (t + 2) % PNS);
    }

    // epilogue: split into bf16 hi/lo, scatter into [B][H][S][64]
    #pragma unroll
    for (int mt = 0; mt < 4; mt++) {
        #pragma unroll
        for (int half = 0; half < 2; half++) {
            int m = bm0 + wm * 64 + mt * 16 + grp + half * 8;
            int bb = m >> 11;
            int ss = m & (SEQ - 1);
            #pragma unroll
            for (int nt = 0; nt < 4; nt++) {
                int n = bn0 + wn * 32 + nt * 8 + q4 * 2;
                int h = n >> 6, d = n & 63;
                float x = acc[mt][nt][half * 2 + 0];
                float y = acc[mt][nt][half * 2 + 1];
                float xh = __bfloat162float(__float2bfloat16(x));
                float yh = __bfloat162float(__float2bfloat16(y));
                size_t idx = (((size_t)(bb * NHEADS + h) * SEQ + ss) << 6) + d;
                *(uint32_t*)&dhi[idx] = pack_bf2(x, y);
                *(uint32_t*)&dlo[idx] = pack_bf2(x - xh, y - yh);
            }
        }
    }
}

// ---------------------------------------------------------------------------
// Kernel 4: flash attention on tensor cores, bf16 split, fp32 softmax.
// 3-stage KV ring, ONE __syncthreads per key tile.
// grid (16 qtiles, 16 heads, 2 batch), 256 threads (8 warps x 16 q-rows).
// ---------------------------------------------------------------------------
#define AT_RB   144                     // bytes per padded row (72 bf16)
#define AT_TILE (64 * AT_RB)            // 9216 B per 64x64 tile
#define ANS     3                       // KV pipeline stages
#define Q_OFF   (ANS * 4 * AT_TILE)               // 110592
#define BW_OFF  (Q_OFF + 2 * 128 * AT_RB)         // 147456
#define MW_OFF  (BW_OFF + ANS * 192 * 4)          // 149760
#define AT_SMEM (MW_OFF + ANS * 64 * 4)           // 150528
#define NKT     (SEQ / 64)

__global__ void __launch_bounds__(256, 1) attn_mma_kernel(
    const float* __restrict__ key_mask, float* __restrict__ out)
{
    extern __shared__ char dsm[];
    const uint32_t sb = smem_u32(dsm);

    const int tid  = threadIdx.x;
    const int lane = tid & 31;
    const int wid  = tid >> 5;
    const int g    = lane >> 2;
    const int q4   = lane & 3;
    const int l7   = lane & 7;
    const int l8   = (lane >> 3) & 1;
    const int l16  = (lane >> 4) & 1;

    const int qt0 = blockIdx.x * 128;
    const int h   = blockIdx.y;
    const int b   = blockIdx.z;
    const size_t bh = ((size_t)(b * NHEADS + h)) << 17;   // *SEQ*HEAD

    const __nv_bfloat16* Khi = g_khi + bh;
    const __nv_bfloat16* Klo = g_klo + bh;
    const __nv_bfloat16* Vhi = g_vhi + bh;
    const __nv_bfloat16* Vlo = g_vlo + bh;
    const float* bias_h = g_bias + h * 4096;

    // ---- issue Q loads (first commit group) ----
    {
        const __nv_bfloat16* srcs[2] = { g_qhi + bh, g_qlo + bh };
        #pragma unroll
        for (int arr = 0; arr < 2; arr++)
            #pragma unroll
            for (int jj = 0; jj < 4; jj++) {
                int rem = jj * 256 + tid;          // 0..1023
                int row = rem >> 3, part = rem & 7;
                uint32_t dst = sb + Q_OFF + arr * (128 * AT_RB) + row * AT_RB + part * 16;
                CP_ASYNC16(dst, srcs[arr] + (size_t)(qt0 + row) * HEAD + part * 8);
            }
        CP_COMMIT();
    }

    auto issue_kv = [&](int kt, int s) {
        const __nv_bfloat16* srcs[4] = { Khi, Klo, Vhi, Vlo };
        #pragma unroll
        for (int arr = 0; arr < 4; arr++)
            #pragma unroll
            for (int jj = 0; jj < 2; jj++) {
                int rem = jj * 256 + tid;          // 0..511
                int row = rem >> 3, part = rem & 7;
                uint32_t dst = sb + (s * 4 + arr) * AT_TILE + row * AT_RB + part * 16;
                CP_ASYNC16(dst, srcs[arr] + (size_t)(kt * 64 + row) * HEAD + part * 8);
            }
        CP_COMMIT();
        float* bw = (float*)(dsm + BW_OFF + s * 768);
        float* mw = (float*)(dsm + MW_OFF + s * 256);
        if (tid < 192) {
            int idx = kt * 64 + tid - 127 - qt0 + 2047;
            idx = max(0, min(4094, idx));
            bw[tid] = bias_h[idx];
        }
        if (tid < 64) {
            float mk = key_mask[(size_t)b * SEQ + kt * 64 + tid];
            mw[tid] = (1.0f - mk) * -10000.0f;
        }
    };

    issue_kv(0, 0);
    issue_kv(1, 1);

    uint32_t qhi[4][4], qlo[4][4];
    float oacc[8][4];
    #pragma unroll
    for (int nt = 0; nt < 8; nt++)
        #pragma unroll
        for (int r = 0; r < 4; r++) oacc[nt][r] = 0.0f;
    float mrow[2] = { -INFINITY, -INFINITY };
    float lrow[2] = { 0.0f, 0.0f };

    for (int t = 0; t < NKT; t++) {
        if (t + 1 < NKT) CP_WAIT(1);
        else             CP_WAIT(0);
        __syncthreads();                 // single barrier per iteration

        if (t == 0) {
            #pragma unroll
            for (int kk = 0; kk < 4; kk++) {
                uint32_t ah = sb + Q_OFF + (wid * 16 + l8 * 8 + l7) * AT_RB +
                              (kk * 16 + l16 * 8) * 2;
                LDMATRIX_X4(qhi[kk][0], qhi[kk][1], qhi[kk][2], qhi[kk][3], ah);
                uint32_t al = ah + 128 * AT_RB;
                LDMATRIX_X4(qlo[kk][0], qlo[kk][1], qlo[kk][2], qlo[kk][3], al);
            }
        }

        const int s = t % ANS;
        const uint32_t kb_hi = sb + (s * 4 + 0) * AT_TILE;
        const uint32_t kb_lo = sb + (s * 4 + 1) * AT_TILE;
        const uint32_t vb_hi = sb + (s * 4 + 2) * AT_TILE;
        const uint32_t vb_lo = sb + (s * 4 + 3) * AT_TILE;
        const float* bw = (const float*)(dsm + BW_OFF + s * 768);
        const float* mw = (const float*)(dsm + MW_OFF + s * 256);

        // ---- S = Q K^T (3-pass split) ----
        float sacc[8][4];
        #pragma unroll
        for (int nt = 0; nt < 8; nt++)
            #pragma unroll
            for (int r = 0; r < 4; r++) sacc[nt][r] = 0.0f;

        #pragma unroll
        for (int kk = 0; kk < 4; kk++) {
            uint32_t bhif[8][2], blof[8][2];
            #pragma unroll
            for (int bp = 0; bp < 4; bp++) {
                uint32_t off = (uint32_t)((bp * 16 + l16 * 8 + l7) * AT_RB +
                                          (kk * 16 + l8 * 8) * 2);
                uint32_t r0, r1, r2, r3;
                LDMATRIX_X4(r0, r1, r2, r3, kb_hi + off);
                bhif[bp * 2][0] = r0; bhif[bp * 2][1] = r1;
                bhif[bp * 2 + 1][0] = r2; bhif[bp * 2 + 1][1] = r3;
                LDMATRIX_X4(r0, r1, r2, r3, kb_lo + off);
                blof[bp * 2][0] = r0; blof[bp * 2][1] = r1;
                blof[bp * 2 + 1][0] = r2; blof[bp * 2 + 1][1] = r3;
            }
            #pragma unroll
            for (int nt = 0; nt < 8; nt++) {
                mma_bf16(sacc[nt], qhi[kk], bhif[nt]);
                mma_bf16(sacc[nt], qlo[kk], bhif[nt]);
                mma_bf16(sacc[nt], qhi[kk], blof[nt]);
            }
        }

        // ---- softmax in registers ----
        #pragma unroll
        for (int hl = 0; hl < 2; hl++) {
            int rr = wid * 16 + g + hl * 8;
            float mx = -INFINITY;
            #pragma unroll
            for (int nt = 0; nt < 8; nt++) {
                #pragma unroll
                for (int e = 0; e < 2; e++) {
                    int c = nt * 8 + q4 * 2 + e;
                    float v = sacc[nt][hl * 2 + e] + bw[c - rr + 127] + mw[c];
                    sacc[nt][hl * 2 + e] = v;
                    mx = fmaxf(mx, v);
                }
            }
            mx = fmaxf(mx, __shfl_xor_sync(0xffffffffu, mx, 1));
            mx = fmaxf(mx, __shfl_xor_sync(0xffffffffu, mx, 2));
            float mnew = fmaxf(mrow[hl], mx);
            float corr = __expf(mrow[hl] - mnew);
            mrow[hl] = mnew;
            float sum = 0.0f;
            #pragma unroll
            for (int nt = 0; nt < 8; nt++) {
                #pragma unroll
                for (int e = 0; e < 2; e++) {
                    float p = __expf(sacc[nt][hl * 2 + e] - mnew);
                    sacc[nt][hl * 2 + e] = p;
                    sum += p;
                }
            }
            sum += __shfl_xor_sync(0xffffffffu, sum, 1);
            sum += __shfl_xor_sync(0xffffffffu, sum, 2);
            lrow[hl] = lrow[hl] * corr + sum;
            #pragma unroll
            for (int nt = 0; nt < 8; nt++) {
                oacc[nt][hl * 2 + 0] *= corr;
                oacc[nt][hl * 2 + 1] *= corr;
            }
        }

        // ---- P -> bf16 hi/lo A-fragments ----
        uint32_t phi[4][4], plo[4][4];
        #pragma unroll
        for (int kk = 0; kk < 4; kk++) {
            #pragma unroll
            for (int part = 0; part < 4; part++) {
                int nt = 2 * kk + (part >> 1);
                int o = (part & 1) * 2;
                float p0 = sacc[nt][o], p1 = sacc[nt][o + 1];
                float h0 = __bfloat162float(__float2bfloat16(p0));
                float h1 = __bfloat162float(__float2bfloat16(p1));
                phi[kk][part] = pack_bf2(p0, p1);
                plo[kk][part] = pack_bf2(p0 - h0, p1 - h1);
            }
        }

        // ---- O += P V (3-pass split), V via trans ldmatrix ----
        #pragma unroll
        for (int kk = 0; kk < 4; kk++) {
            uint32_t vhif[8][2], vlof[8][2];
            #pragma unroll
            for (int db = 0; db < 4; db++) {
                uint32_t off = (uint32_t)((kk * 16 + l8 * 8 + l7) * AT_RB +
                                          (db * 16 + l16 * 8) * 2);
                uint32_t r0, r1, r2, r3;
                LDMATRIX_X4T(r0, r1, r2, r3, vb_hi + off);
                vhif[db * 2][0] = r0; vhif[db * 2][1] = r1;
                vhif[db * 2 + 1][0] = r2; vhif[db * 2 + 1][1] = r3;
                LDMATRIX_X4T(r0, r1, r2, r3, vb_lo + off);
                vlof[db * 2][0] = r0; vlof[db * 2][1] = r1;
                vlof[db * 2 + 1][0] = r2; vlof[db * 2 + 1][1] = r3;
            }
            #pragma unroll
            for (int nt = 0; nt < 8; nt++) {
                mma_bf16(oacc[nt], phi[kk], vhif[nt]);
                mma_bf16(oacc[nt], plo[kk], vhif[nt]);
                mma_bf16(oacc[nt], phi[kk], vlof[nt]);
            }
        }

        // issue next-next KV tile into stage (t+2)%3 == (t-1)%3 (consumed)
        if (t + 2 < NKT) issue_kv(t + 2, (t + 2) % ANS);
    }

    // ---- epilogue: out[b][qrow][h*64 + d] = O / l ----
    #pragma unroll
    for (int hl = 0; hl < 2; hl++) {
        int rr = wid * 16 + g + hl * 8;
        float inv = 1.0f / lrow[hl];
        size_t base = ((size_t)(b * SEQ + qt0 + rr)) * (NHEADS * HEAD) + h * HEAD;
        #pragma unroll
        for (int nt = 0; nt < 8; nt++) {
            int c = nt * 8 + q4 * 2;
            float2 v;
            v.x = oacc[nt][hl * 2 + 0] * inv;
            v.y = oacc[nt][hl * 2 + 1] * inv;
            *(float2*)&out[base + c] = v;
        }
    }
}

// ---------------------------------------------------------------------------
// Launch
// ---------------------------------------------------------------------------
extern "C" void kernel_launch(void* const* d_in, const int* in_sizes, int n_in,
                              void* d_out, int out_size) {
    const float* query    = (const float*)d_in[0];
    const float* key      = (const float*)d_in[1];
    const float* value    = (const float*)d_in[2];
    const float* key_mask = (const float*)d_in[3];
    const float* Wq       = (const float*)d_in[4];
    const float* Wk       = (const float*)d_in[5];
    const float* Wv       = (const float*)d_in[6];
    const float* bias_tab = (const float*)d_in[7];
    float* out = (float*)d_out;

    cudaFuncSetAttribute(proj_mma_kernel,
                         cudaFuncAttributeMaxDynamicSharedMemorySize, PROJ_SMEM);
    cudaFuncSetAttribute(attn_mma_kernel,
                         cudaFuncAttributeMaxDynamicSharedMemorySize, AT_SMEM);

    bias_precompute_kernel<<<16, 256>>>(bias_tab);
    convert_x_kernel<<<dim3(4096, 3), 256>>>(query, key, value);
    convert_w_kernel<<<dim3(32, 32, 3), dim3(32, 32)>>>(Wq, Wk, Wv);
    proj_mma_kernel<<<dim3(8, 32, 3), 256, PROJ_SMEM>>>();
    attn_mma_kernel<<<dim3(SEQ / 128, NHEADS, NB), 256, AT_SMEM>>>(key_mask, out);
}

// round 9
// speedup vs baseline: 2.5331x; 1.0356x over previous
#include <cuda_runtime.h>
#include <cuda_bf16.h>
#include <math.h>
#include <stdint.h>

// ---------------------------------------------------------------------------
// Problem constants (B=2, S=2048, D_MODEL=1024, H=16, Dh=64)
// ---------------------------------------------------------------------------
#define NB      2
#define SEQ     2048
#define DM      1024
#define NHEADS  16
#define HEAD    64

__device__ float g_bias[NHEADS * 4096];

// bf16 split operands for projection GEMMs
__device__ __nv_bfloat16 g_Ahi[3][4096 * 1024];
__device__ __nv_bfloat16 g_Alo[3][4096 * 1024];
__device__ __nv_bfloat16 g_Bhi[3][1024 * 1024];
__device__ __nv_bfloat16 g_Blo[3][1024 * 1024];

// Q/K/V split outputs of projections: [B][H][S][64] bf16 hi/lo
#define QKV_ELE (NB * NHEADS * SEQ * HEAD)
__device__ __nv_bfloat16 g_qhi[QKV_ELE], g_qlo[QKV_ELE];
__device__ __nv_bfloat16 g_khi[QKV_ELE], g_klo[QKV_ELE];
__device__ __nv_bfloat16 g_vhi[QKV_ELE], g_vlo[QKV_ELE];

// ---------------------------------------------------------------------------
// PTX helpers
// ---------------------------------------------------------------------------
__device__ __forceinline__ uint32_t smem_u32(const void* p) {
    uint32_t a;
    asm("{ .reg .u64 t; cvta.to.shared.u64 t, %1; cvt.u32.u64 %0, t; }"
        : "=r"(a) : "l"(p));
    return a;
}
#define CP_ASYNC16(dst, src) \
    asm volatile("cp.async.cg.shared.global [%0], [%1], 16;" :: "r"(dst), "l"(src))
#define CP_COMMIT() asm volatile("cp.async.commit_group;" ::: "memory")
#define CP_WAIT(n)  asm volatile("cp.async.wait_group %0;" :: "n"(n) : "memory")

#define LDMATRIX_X4(r0, r1, r2, r3, addr) \
    asm volatile("ldmatrix.sync.aligned.m8n8.x4.shared.b16 {%0,%1,%2,%3}, [%4];" \
                 : "=r"(r0), "=r"(r1), "=r"(r2), "=r"(r3) : "r"(addr))
#define LDMATRIX_X4T(r0, r1, r2, r3, addr) \
    asm volatile("ldmatrix.sync.aligned.m8n8.x4.trans.shared.b16 {%0,%1,%2,%3}, [%4];" \
                 : "=r"(r0), "=r"(r1), "=r"(r2), "=r"(r3) : "r"(addr))

__device__ __forceinline__ void mma_bf16(float* d, const uint32_t* a,
                                         const uint32_t* b) {
    asm volatile(
        "mma.sync.aligned.m16n8k16.row.col.f32.bf16.bf16.f32 "
        "{%0,%1,%2,%3}, {%4,%5,%6,%7}, {%8,%9}, {%0,%1,%2,%3};"
        : "+f"(d[0]), "+f"(d[1]), "+f"(d[2]), "+f"(d[3])
        : "r"(a[0]), "r"(a[1]), "r"(a[2]), "r"(a[3]), "r"(b[0]), "r"(b[1]));
}
__device__ __forceinline__ uint32_t pack_bf2(float a, float b) {
    __nv_bfloat162 t = __floats2bfloat162_rn(a, b);
    return *(uint32_t*)&t;
}

// ---------------------------------------------------------------------------
// Kernel 1: relative-position bias table expansion (known-good)
// ---------------------------------------------------------------------------
__global__ void bias_precompute_kernel(const float* __restrict__ bias_table) {
    int i = blockIdx.x * blockDim.x + threadIdx.x;
    if (i >= 4095) return;
    int delta = i - 2047;
    int ret = (delta > 0) ? 16 : 0;
    int rp = abs(delta);
    int bucket;
    if (rp < 8) {
        bucket = ret + rp;
    } else {
        int vl;
        if ((rp & (rp - 1)) == 0) {
            int k = __ffs(rp) - 1;
            vl = 8 + 2 * (k - 3);
        } else {
            float t = logf((float)rp * 0.125f) / 2.7725887f;
            vl = 8 + (int)(t * 8.0f);
        }
        bucket = ret + min(vl, 15);
    }
    #pragma unroll
    for (int h = 0; h < NHEADS; h++)
        g_bias[h * 4096 + i] = bias_table[bucket * NHEADS + h];
}

// ---------------------------------------------------------------------------
// Kernel 2a: split activations X -> bf16 hi/lo
// ---------------------------------------------------------------------------
__global__ void __launch_bounds__(256) convert_x_kernel(
    const float* __restrict__ Xq, const float* __restrict__ Xk,
    const float* __restrict__ Xv)
{
    int z = blockIdx.y;
    const float* X = (z == 0) ? Xq : (z == 1) ? Xk : Xv;
    __nv_bfloat16* hi = g_Ahi[z];
    __nv_bfloat16* lo = g_Alo[z];
    size_t i = ((size_t)blockIdx.x * 256 + threadIdx.x) * 4;
    float4 v = *(const float4*)(X + i);
    float f[4] = {v.x, v.y, v.z, v.w};
    #pragma unroll
    for (int j = 0; j < 4; j++) {
        __nv_bfloat16 h = __float2bfloat16(f[j]);
        hi[i + j] = h;
        lo[i + j] = __float2bfloat16(f[j] - __bfloat162float(h));
    }
}

// ---------------------------------------------------------------------------
// Kernel 2b: transpose + split weights  W[k][n] -> Wt[n][k] bf16 hi/lo
// ---------------------------------------------------------------------------
__global__ void __launch_bounds__(1024) convert_w_kernel(
    const float* __restrict__ Wq, const float* __restrict__ Wk,
    const float* __restrict__ Wv)
{
    __shared__ float tile[32][33];
    int z = blockIdx.z;
    const float* W = (z == 0) ? Wq : (z == 1) ? Wk : Wv;
    int k0 = blockIdx.x * 32;
    int n0 = blockIdx.y * 32;
    int tx = threadIdx.x, ty = threadIdx.y;
    tile[ty][tx] = W[(size_t)(k0 + ty) * DM + n0 + tx];
    __syncthreads();
    float v = tile[tx][ty];
    __nv_bfloat16 h = __float2bfloat16(v);
    size_t idx = (size_t)(n0 + ty) * DM + k0 + tx;
    g_Bhi[z][idx] = h;
    g_Blo[z][idx] = __float2bfloat16(v - __bfloat162float(h));
}

// ---------------------------------------------------------------------------
// Kernel 3: projection GEMM, FUSED 3-pass split.
// Per 32-k chunk: load Ahi/Alo/Bhi/Blo tiles ONCE, run hi*hi + hi*lo + lo*hi.
// 2-stage cp.async double buffer (40 KB/stage, dynamic smem 80 KB),
// 32 iterations. __launch_bounds__(256,2) keeps 2 CTAs/SM.
// Epilogue writes bf16 hi/lo Q/K/V in [B][H][S][64].
// ---------------------------------------------------------------------------
#define BK 32
#define TB 10240                         // bytes per 128x32 bf16 tile (80 B rows)
#define STAGE_B (4 * TB)                 // Ahi,Alo,Bhi,Blo
#define PROJ_SMEM (2 * STAGE_B)          // 81920 B
#define NCHUNK 32

__global__ void __launch_bounds__(256, 2) proj_mma_kernel() {
    extern __shared__ char psm[];

    const int tid  = threadIdx.x;
    const int lane = tid & 31;
    const int wid  = tid >> 5;
    const int wm   = wid >> 2;
    const int wn   = wid & 3;
    const int grp  = lane >> 2;
    const int q4   = lane & 3;

    const int z   = blockIdx.z;
    const int bm0 = blockIdx.y * 128;
    const int bn0 = blockIdx.x * 128;

    const __nv_bfloat16* __restrict__ srcs[4] = {
        g_Ahi[z], g_Alo[z], g_Bhi[z], g_Blo[z] };
    __nv_bfloat16* dhi = (z == 0) ? g_qhi : (z == 1) ? g_khi : g_vhi;
    __nv_bfloat16* dlo = (z == 0) ? g_qlo : (z == 1) ? g_klo : g_vlo;

    const uint32_t s0 = smem_u32(psm);

    float acc[4][4][4];
    #pragma unroll
    for (int i = 0; i < 4; i++)
        #pragma unroll
        for (int j = 0; j < 4; j++)
            #pragma unroll
            for (int r = 0; r < 4; r++) acc[i][j][r] = 0.0f;

    // loader: 4 arrays x 2 chunks of 16B per thread per k-chunk
    auto load_chunk = [&](int t, int s) {
        int k0 = t * BK;
        uint32_t base = s0 + s * STAGE_B;
        #pragma unroll
        for (int arr = 0; arr < 4; arr++) {
            int r0 = (arr < 2) ? bm0 : bn0;
            #pragma unroll
            for (int j = 0; j < 2; j++) {
                int id = tid + 256 * j;
                int row = id >> 2, part = id & 3;
                uint32_t off = (uint32_t)(row * 80 + part * 16);
                CP_ASYNC16(base + arr * TB + off,
                           srcs[arr] + (size_t)(r0 + row) * DM + k0 + part * 8);
            }
        }
        CP_COMMIT();
    };

    const int l7  = lane & 7;
    const int l8  = (lane >> 3) & 1;
    const int l16 = (lane >> 4) & 1;

    load_chunk(0, 0);
    load_chunk(1, 1);

    for (int t = 0; t < NCHUNK; t++) {
        if (t + 1 < NCHUNK) CP_WAIT(1);
        else                CP_WAIT(0);
        __syncthreads();                 // stage t&1 data visible

        const int s = t & 1;
        const uint32_t aHi = s0 + s * STAGE_B;
        const uint32_t aLo = aHi + TB;
        const uint32_t bHi = aHi + 2 * TB;
        const uint32_t bLo = aHi + 3 * TB;

        #pragma unroll
        for (int ks = 0; ks < 2; ks++) {
            const int kb = ks * 16;
            uint32_t afrag[4][4], bhif[4][2], blof[4][2];
            // B hi + lo fragments
            #pragma unroll
            for (int bp = 0; bp < 2; bp++) {
                uint32_t off = (uint32_t)((wn * 32 + bp * 16 + l16 * 8 + l7) * 80 +
                                          (kb + l8 * 8) * 2);
                uint32_t r0, r1, r2, r3;
                LDMATRIX_X4(r0, r1, r2, r3, bHi + off);
                bhif[bp * 2 + 0][0] = r0; bhif[bp * 2 + 0][1] = r1;
                bhif[bp * 2 + 1][0] = r2; bhif[bp * 2 + 1][1] = r3;
                LDMATRIX_X4(r0, r1, r2, r3, bLo + off);
                blof[bp * 2 + 0][0] = r0; blof[bp * 2 + 0][1] = r1;
                blof[bp * 2 + 1][0] = r2; blof[bp * 2 + 1][1] = r3;
            }
            // A hi fragments; Ahi x Bhi and Ahi x Blo
            #pragma unroll
            for (int mt = 0; mt < 4; mt++) {
                uint32_t addr = aHi +
                    (uint32_t)((wm * 64 + mt * 16 + l8 * 8 + l7) * 80 +
                               (kb + l16 * 8) * 2);
                LDMATRIX_X4(afrag[mt][0], afrag[mt][1], afrag[mt][2], afrag[mt][3], addr);
            }
            #pragma unroll
            for (int mt = 0; mt < 4; mt++)
                #pragma unroll
                for (int nt = 0; nt < 4; nt++) {
                    mma_bf16(acc[mt][nt], afrag[mt], bhif[nt]);
                    mma_bf16(acc[mt][nt], afrag[mt], blof[nt]);
                }
            // A lo fragments (reuse regs); Alo x Bhi
            #pragma unroll
            for (int mt = 0; mt < 4; mt++) {
                uint32_t addr = aLo +
                    (uint32_t)((wm * 64 + mt * 16 + l8 * 8 + l7) * 80 +
                               (kb + l16 * 8) * 2);
                LDMATRIX_X4(afrag[mt][0], afrag[mt][1], afrag[mt][2], afrag[mt][3], addr);
            }
            #pragma unroll
            for (int mt = 0; mt < 4; mt++)
                #pragma unroll
                for (int nt = 0; nt < 4; nt++)
                    mma_bf16(acc[mt][nt], afrag[mt], bhif[nt]);
        }

        __syncthreads();                 // all reads of stage s done
        if (t + 2 < NCHUNK) load_chunk(t + 2, s);
    }

    // epilogue: split into bf16 hi/lo, scatter into [B][H][S][64]
    #pragma unroll
    for (int mt = 0; mt < 4; mt++) {
        #pragma unroll
        for (int half = 0; half < 2; half++) {
            int m = bm0 + wm * 64 + mt * 16 + grp + half * 8;
            int bb = m >> 11;
            int ss = m & (SEQ - 1);
            #pragma unroll
            for (int nt = 0; nt < 4; nt++) {
                int n = bn0 + wn * 32 + nt * 8 + q4 * 2;
                int h = n >> 6, d = n & 63;
                float x = acc[mt][nt][half * 2 + 0];
                float y = acc[mt][nt][half * 2 + 1];
                float xh = __bfloat162float(__float2bfloat16(x));
                float yh = __bfloat162float(__float2bfloat16(y));
                size_t idx = (((size_t)(bb * NHEADS + h) * SEQ + ss) << 6) + d;
                *(uint32_t*)&dhi[idx] = pack_bf2(x, y);
                *(uint32_t*)&dlo[idx] = pack_bf2(x - xh, y - yh);
            }
        }
    }
}

// ---------------------------------------------------------------------------
// Kernel 4: flash attention on tensor cores, bf16 split, fp32 softmax.
// 3-stage KV ring, ONE __syncthreads per key tile. (unchanged from R7)
// ---------------------------------------------------------------------------
#define AT_RB   144
#define AT_TILE (64 * AT_RB)
#define ANS     3
#define Q_OFF   (ANS * 4 * AT_TILE)
#define BW_OFF  (Q_OFF + 2 * 128 * AT_RB)
#define MW_OFF  (BW_OFF + ANS * 192 * 4)
#define AT_SMEM (MW_OFF + ANS * 64 * 4)
#define NKT     (SEQ / 64)

__global__ void __launch_bounds__(256, 1) attn_mma_kernel(
    const float* __restrict__ key_mask, float* __restrict__ out)
{
    extern __shared__ char dsm[];
    const uint32_t sb = smem_u32(dsm);

    const int tid  = threadIdx.x;
    const int lane = tid & 31;
    const int wid  = tid >> 5;
    const int g    = lane >> 2;
    const int q4   = lane & 3;
    const int l7   = lane & 7;
    const int l8   = (lane >> 3) & 1;
    const int l16  = (lane >> 4) & 1;

    const int qt0 = blockIdx.x * 128;
    const int h   = blockIdx.y;
    const int b   = blockIdx.z;
    const size_t bh = ((size_t)(b * NHEADS + h)) << 17;

    const __nv_bfloat16* Khi = g_khi + bh;
    const __nv_bfloat16* Klo = g_klo + bh;
    const __nv_bfloat16* Vhi = g_vhi + bh;
    const __nv_bfloat16* Vlo = g_vlo + bh;
    const float* bias_h = g_bias + h * 4096;

    {
        const __nv_bfloat16* srcs[2] = { g_qhi + bh, g_qlo + bh };
        #pragma unroll
        for (int arr = 0; arr < 2; arr++)
            #pragma unroll
            for (int jj = 0; jj < 4; jj++) {
                int rem = jj * 256 + tid;
                int row = rem >> 3, part = rem & 7;
                uint32_t dst = sb + Q_OFF + arr * (128 * AT_RB) + row * AT_RB + part * 16;
                CP_ASYNC16(dst, srcs[arr] + (size_t)(qt0 + row) * HEAD + part * 8);
            }
        CP_COMMIT();
    }

    auto issue_kv = [&](int kt, int s) {
        const __nv_bfloat16* srcs[4] = { Khi, Klo, Vhi, Vlo };
        #pragma unroll
        for (int arr = 0; arr < 4; arr++)
            #pragma unroll
            for (int jj = 0; jj < 2; jj++) {
                int rem = jj * 256 + tid;
                int row = rem >> 3, part = rem & 7;
                uint32_t dst = sb + (s * 4 + arr) * AT_TILE + row * AT_RB + part * 16;
                CP_ASYNC16(dst, srcs[arr] + (size_t)(kt * 64 + row) * HEAD + part * 8);
            }
        CP_COMMIT();
        float* bw = (float*)(dsm + BW_OFF + s * 768);
        float* mw = (float*)(dsm + MW_OFF + s * 256);
        if (tid < 192) {
            int idx = kt * 64 + tid - 127 - qt0 + 2047;
            idx = max(0, min(4094, idx));
            bw[tid] = bias_h[idx];
        }
        if (tid < 64) {
            float mk = key_mask[(size_t)b * SEQ + kt * 64 + tid];
            mw[tid] = (1.0f - mk) * -10000.0f;
        }
    };

    issue_kv(0, 0);
    issue_kv(1, 1);

    uint32_t qhi[4][4], qlo[4][4];
    float oacc[8][4];
    #pragma unroll
    for (int nt = 0; nt < 8; nt++)
        #pragma unroll
        for (int r = 0; r < 4; r++) oacc[nt][r] = 0.0f;
    float mrow[2] = { -INFINITY, -INFINITY };
    float lrow[2] = { 0.0f, 0.0f };

    for (int t = 0; t < NKT; t++) {
        if (t + 1 < NKT) CP_WAIT(1);
        else             CP_WAIT(0);
        __syncthreads();

        if (t == 0) {
            #pragma unroll
            for (int kk = 0; kk < 4; kk++) {
                uint32_t ah = sb + Q_OFF + (wid * 16 + l8 * 8 + l7) * AT_RB +
                              (kk * 16 + l16 * 8) * 2;
                LDMATRIX_X4(qhi[kk][0], qhi[kk][1], qhi[kk][2], qhi[kk][3], ah);
                uint32_t al = ah + 128 * AT_RB;
                LDMATRIX_X4(qlo[kk][0], qlo[kk][1], qlo[kk][2], qlo[kk][3], al);
            }
        }

        const int s = t % ANS;
        const uint32_t kb_hi = sb + (s * 4 + 0) * AT_TILE;
        const uint32_t kb_lo = sb + (s * 4 + 1) * AT_TILE;
        const uint32_t vb_hi = sb + (s * 4 + 2) * AT_TILE;
        const uint32_t vb_lo = sb + (s * 4 + 3) * AT_TILE;
        const float* bw = (const float*)(dsm + BW_OFF + s * 768);
        const float* mw = (const float*)(dsm + MW_OFF + s * 256);

        float sacc[8][4];
        #pragma unroll
        for (int nt = 0; nt < 8; nt++)
            #pragma unroll
            for (int r = 0; r < 4; r++) sacc[nt][r] = 0.0f;

        #pragma unroll
        for (int kk = 0; kk < 4; kk++) {
            uint32_t bhif[8][2], blof[8][2];
            #pragma unroll
            for (int bp = 0; bp < 4; bp++) {
                uint32_t off = (uint32_t)((bp * 16 + l16 * 8 + l7) * AT_RB +
                                          (kk * 16 + l8 * 8) * 2);
                uint32_t r0, r1, r2, r3;
                LDMATRIX_X4(r0, r1, r2, r3, kb_hi + off);
                bhif[bp * 2][0] = r0; bhif[bp * 2][1] = r1;
                bhif[bp * 2 + 1][0] = r2; bhif[bp * 2 + 1][1] = r3;
                LDMATRIX_X4(r0, r1, r2, r3, kb_lo + off);
                blof[bp * 2][0] = r0; blof[bp * 2][1] = r1;
                blof[bp * 2 + 1][0] = r2; blof[bp * 2 + 1][1] = r3;
            }
            #pragma unroll
            for (int nt = 0; nt < 8; nt++) {
                mma_bf16(sacc[nt], qhi[kk], bhif[nt]);
                mma_bf16(sacc[nt], qlo[kk], bhif[nt]);
                mma_bf16(sacc[nt], qhi[kk], blof[nt]);
            }
        }

        #pragma unroll
        for (int hl = 0; hl < 2; hl++) {
            int rr = wid * 16 + g + hl * 8;
            float mx = -INFINITY;
            #pragma unroll
            for (int nt = 0; nt < 8; nt++) {
                #pragma unroll
                for (int e = 0; e < 2; e++) {
                    int c = nt * 8 + q4 * 2 + e;
                    float v = sacc[nt][hl * 2 + e] + bw[c - rr + 127] + mw[c];
                    sacc[nt][hl * 2 + e] = v;
                    mx = fmaxf(mx, v);
                }
            }
            mx = fmaxf(mx, __shfl_xor_sync(0xffffffffu, mx, 1));
            mx = fmaxf(mx, __shfl_xor_sync(0xffffffffu, mx, 2));
            float mnew = fmaxf(mrow[hl], mx);
            float corr = __expf(mrow[hl] - mnew);
            mrow[hl] = mnew;
            float sum = 0.0f;
            #pragma unroll
            for (int nt = 0; nt < 8; nt++) {
                #pragma unroll
                for (int e = 0; e < 2; e++) {
                    float p = __expf(sacc[nt][hl * 2 + e] - mnew);
                    sacc[nt][hl * 2 + e] = p;
                    sum += p;
                }
            }
            sum += __shfl_xor_sync(0xffffffffu, sum, 1);
            sum += __shfl_xor_sync(0xffffffffu, sum, 2);
            lrow[hl] = lrow[hl] * corr + sum;
            #pragma unroll
            for (int nt = 0; nt < 8; nt++) {
                oacc[nt][hl * 2 + 0] *= corr;
                oacc[nt][hl * 2 + 1] *= corr;
            }
        }

        uint32_t phi[4][4], plo[4][4];
        #pragma unroll
        for (int kk = 0; kk < 4; kk++) {
            #pragma unroll
            for (int part = 0; part < 4; part++) {
                int nt = 2 * kk + (part >> 1);
                int o = (part & 1) * 2;
                float p0 = sacc[nt][o], p1 = sacc[nt][o + 1];
                float h0 = __bfloat162float(__float2bfloat16(p0));
                float h1 = __bfloat162float(__float2bfloat16(p1));
                phi[kk][part] = pack_bf2(p0, p1);
                plo[kk][part] = pack_bf2(p0 - h0, p1 - h1);
            }
        }

        #pragma unroll
        for (int kk = 0; kk < 4; kk++) {
            uint32_t vhif[8][2], vlof[8][2];
            #pragma unroll
            for (int db = 0; db < 4; db++) {
                uint32_t off = (uint32_t)((kk * 16 + l8 * 8 + l7) * AT_RB +
                                          (db * 16 + l16 * 8) * 2);
                uint32_t r0, r1, r2, r3;
                LDMATRIX_X4T(r0, r1, r2, r3, vb_hi + off);
                vhif[db * 2][0] = r0; vhif[db * 2][1] = r1;
                vhif[db * 2 + 1][0] = r2; vhif[db * 2 + 1][1] = r3;
                LDMATRIX_X4T(r0, r1, r2, r3, vb_lo + off);
                vlof[db * 2][0] = r0; vlof[db * 2][1] = r1;
                vlof[db * 2 + 1][0] = r2; vlof[db * 2 + 1][1] = r3;
            }
            #pragma unroll
            for (int nt = 0; nt < 8; nt++) {
                mma_bf16(oacc[nt], phi[kk], vhif[nt]);
                mma_bf16(oacc[nt], plo[kk], vhif[nt]);
                mma_bf16(oacc[nt], phi[kk], vlof[nt]);
            }
        }

        if (t + 2 < NKT) issue_kv(t + 2, (t + 2) % ANS);
    }

    #pragma unroll
    for (int hl = 0; hl < 2; hl++) {
        int rr = wid * 16 + g + hl * 8;
        float inv = 1.0f / lrow[hl];
        size_t base = ((size_t)(b * SEQ + qt0 + rr)) * (NHEADS * HEAD) + h * HEAD;
        #pragma unroll
        for (int nt = 0; nt < 8; nt++) {
            int c = nt * 8 + q4 * 2;
            float2 v;
            v.x = oacc[nt][hl * 2 + 0] * inv;
            v.y = oacc[nt][hl * 2 + 1] * inv;
            *(float2*)&out[base + c] = v;
        }
    }
}

// ---------------------------------------------------------------------------
// Launch
// ---------------------------------------------------------------------------
extern "C" void kernel_launch(void* const* d_in, const int* in_sizes, int n_in,
                              void* d_out, int out_size) {
    const float* query    = (const float*)d_in[0];
    const float* key      = (const float*)d_in[1];
    const float* value    = (const float*)d_in[2];
    const float* key_mask = (const float*)d_in[3];
    const float* Wq       = (const float*)d_in[4];
    const float* Wk       = (const float*)d_in[5];
    const float* Wv       = (const float*)d_in[6];
    const float* bias_tab = (const float*)d_in[7];
    float* out = (float*)d_out;

    cudaFuncSetAttribute(proj_mma_kernel,
                         cudaFuncAttributeMaxDynamicSharedMemorySize, PROJ_SMEM);
    cudaFuncSetAttribute(attn_mma_kernel,
                         cudaFuncAttributeMaxDynamicSharedMemorySize, AT_SMEM);

    bias_precompute_kernel<<<16, 256>>>(bias_tab);
    convert_x_kernel<<<dim3(4096, 3), 256>>>(query, key, value);
    convert_w_kernel<<<dim3(32, 32, 3), dim3(32, 32)>>>(Wq, Wk, Wv);
    proj_mma_kernel<<<dim3(8, 32, 3), 256, PROJ_SMEM>>>();
    attn_mma_kernel<<<dim3(SEQ / 128, NHEADS, NB), 256, AT_SMEM>>>(key_mask, out);
}

// round 10
// speedup vs baseline: 2.6883x; 1.0613x over previous
#include <cuda_runtime.h>
#include <cuda_bf16.h>
#include <math.h>
#include <stdint.h>

// ---------------------------------------------------------------------------
// Problem constants (B=2, S=2048, D_MODEL=1024, H=16, Dh=64)
// ---------------------------------------------------------------------------
#define NB      2
#define SEQ     2048
#define DM      1024
#define NHEADS  16
#define HEAD    64

__device__ float g_bias[NHEADS * 4096];

// bf16 split operands for projection GEMMs
__device__ __nv_bfloat16 g_Ahi[3][4096 * 1024];
__device__ __nv_bfloat16 g_Alo[3][4096 * 1024];
__device__ __nv_bfloat16 g_Bhi[3][1024 * 1024];
__device__ __nv_bfloat16 g_Blo[3][1024 * 1024];

// Q/K/V split outputs of projections: [B][H][S][64] bf16 hi/lo
#define QKV_ELE (NB * NHEADS * SEQ * HEAD)
__device__ __nv_bfloat16 g_qhi[QKV_ELE], g_qlo[QKV_ELE];
__device__ __nv_bfloat16 g_khi[QKV_ELE], g_klo[QKV_ELE];
__device__ __nv_bfloat16 g_vhi[QKV_ELE], g_vlo[QKV_ELE];

// ---------------------------------------------------------------------------
// PTX helpers
// ---------------------------------------------------------------------------
__device__ __forceinline__ uint32_t smem_u32(const void* p) {
    uint32_t a;
    asm("{ .reg .u64 t; cvta.to.shared.u64 t, %1; cvt.u32.u64 %0, t; }"
        : "=r"(a) : "l"(p));
    return a;
}
#define CP_ASYNC16(dst, src) \
    asm volatile("cp.async.cg.shared.global [%0], [%1], 16;" :: "r"(dst), "l"(src))
#define CP_COMMIT() asm volatile("cp.async.commit_group;" ::: "memory")
#define CP_WAIT(n)  asm volatile("cp.async.wait_group %0;" :: "n"(n) : "memory")

#define LDMATRIX_X4(r0, r1, r2, r3, addr) \
    asm volatile("ldmatrix.sync.aligned.m8n8.x4.shared.b16 {%0,%1,%2,%3}, [%4];" \
                 : "=r"(r0), "=r"(r1), "=r"(r2), "=r"(r3) : "r"(addr))
#define LDMATRIX_X4T(r0, r1, r2, r3, addr) \
    asm volatile("ldmatrix.sync.aligned.m8n8.x4.trans.shared.b16 {%0,%1,%2,%3}, [%4];" \
                 : "=r"(r0), "=r"(r1), "=r"(r2), "=r"(r3) : "r"(addr))

__device__ __forceinline__ void mma_bf16(float* d, const uint32_t* a,
                                         const uint32_t* b) {
    asm volatile(
        "mma.sync.aligned.m16n8k16.row.col.f32.bf16.bf16.f32 "
        "{%0,%1,%2,%3}, {%4,%5,%6,%7}, {%8,%9}, {%0,%1,%2,%3};"
        : "+f"(d[0]), "+f"(d[1]), "+f"(d[2]), "+f"(d[3])
        : "r"(a[0]), "r"(a[1]), "r"(a[2]), "r"(a[3]), "r"(b[0]), "r"(b[1]));
}
__device__ __forceinline__ uint32_t pack_bf2(float a, float b) {
    __nv_bfloat162 t = __floats2bfloat162_rn(a, b);
    return *(uint32_t*)&t;
}

// ---------------------------------------------------------------------------
// Kernel 1: relative-position bias table expansion (known-good)
// ---------------------------------------------------------------------------
__global__ void bias_precompute_kernel(const float* __restrict__ bias_table) {
    int i = blockIdx.x * blockDim.x + threadIdx.x;
    if (i >= 4095) return;
    int delta = i - 2047;
    int ret = (delta > 0) ? 16 : 0;
    int rp = abs(delta);
    int bucket;
    if (rp < 8) {
        bucket = ret + rp;
    } else {
        int vl;
        if ((rp & (rp - 1)) == 0) {
            int k = __ffs(rp) - 1;
            vl = 8 + 2 * (k - 3);
        } else {
            float t = logf((float)rp * 0.125f) / 2.7725887f;
            vl = 8 + (int)(t * 8.0f);
        }
        bucket = ret + min(vl, 15);
    }
    #pragma unroll
    for (int h = 0; h < NHEADS; h++)
        g_bias[h * 4096 + i] = bias_table[bucket * NHEADS + h];
}

// ---------------------------------------------------------------------------
// Kernel 2a: split activations X -> bf16 hi/lo
// ---------------------------------------------------------------------------
__global__ void __launch_bounds__(256) convert_x_kernel(
    const float* __restrict__ Xq, const float* __restrict__ Xk,
    const float* __restrict__ Xv)
{
    int z = blockIdx.y;
    const float* X = (z == 0) ? Xq : (z == 1) ? Xk : Xv;
    __nv_bfloat16* hi = g_Ahi[z];
    __nv_bfloat16* lo = g_Alo[z];
    size_t i = ((size_t)blockIdx.x * 256 + threadIdx.x) * 4;
    float4 v = *(const float4*)(X + i);
    float f[4] = {v.x, v.y, v.z, v.w};
    #pragma unroll
    for (int j = 0; j < 4; j++) {
        __nv_bfloat16 h = __float2bfloat16(f[j]);
        hi[i + j] = h;
        lo[i + j] = __float2bfloat16(f[j] - __bfloat162float(h));
    }
}

// ---------------------------------------------------------------------------
// Kernel 2b: transpose + split weights  W[k][n] -> Wt[n][k] bf16 hi/lo
// ---------------------------------------------------------------------------
__global__ void __launch_bounds__(1024) convert_w_kernel(
    const float* __restrict__ Wq, const float* __restrict__ Wk,
    const float* __restrict__ Wv)
{
    __shared__ float tile[32][33];
    int z = blockIdx.z;
    const float* W = (z == 0) ? Wq : (z == 1) ? Wk : Wv;
    int k0 = blockIdx.x * 32;
    int n0 = blockIdx.y * 32;
    int tx = threadIdx.x, ty = threadIdx.y;
    tile[ty][tx] = W[(size_t)(k0 + ty) * DM + n0 + tx];
    __syncthreads();
    float v = tile[tx][ty];
    __nv_bfloat16 h = __float2bfloat16(v);
    size_t idx = (size_t)(n0 + ty) * DM + k0 + tx;
    g_Bhi[z][idx] = h;
    g_Blo[z][idx] = __float2bfloat16(v - __bfloat162float(h));
}

// ---------------------------------------------------------------------------
// Kernel 3: projection GEMM, FUSED 3-pass split. (unchanged from R9)
// ---------------------------------------------------------------------------
#define BK 32
#define TB 10240
#define STAGE_B (4 * TB)
#define PROJ_SMEM (2 * STAGE_B)          // 81920 B
#define NCHUNK 32

__global__ void __launch_bounds__(256, 2) proj_mma_kernel() {
    extern __shared__ char psm[];

    const int tid  = threadIdx.x;
    const int lane = tid & 31;
    const int wid  = tid >> 5;
    const int wm   = wid >> 2;
    const int wn   = wid & 3;
    const int grp  = lane >> 2;
    const int q4   = lane & 3;

    const int z   = blockIdx.z;
    const int bm0 = blockIdx.y * 128;
    const int bn0 = blockIdx.x * 128;

    const __nv_bfloat16* __restrict__ srcs[4] = {
        g_Ahi[z], g_Alo[z], g_Bhi[z], g_Blo[z] };
    __nv_bfloat16* dhi = (z == 0) ? g_qhi : (z == 1) ? g_khi : g_vhi;
    __nv_bfloat16* dlo = (z == 0) ? g_qlo : (z == 1) ? g_klo : g_vlo;

    const uint32_t s0 = smem_u32(psm);

    float acc[4][4][4];
    #pragma unroll
    for (int i = 0; i < 4; i++)
        #pragma unroll
        for (int j = 0; j < 4; j++)
            #pragma unroll
            for (int r = 0; r < 4; r++) acc[i][j][r] = 0.0f;

    auto load_chunk = [&](int t, int s) {
        int k0 = t * BK;
        uint32_t base = s0 + s * STAGE_B;
        #pragma unroll
        for (int arr = 0; arr < 4; arr++) {
            int r0 = (arr < 2) ? bm0 : bn0;
            #pragma unroll
            for (int j = 0; j < 2; j++) {
                int id = tid + 256 * j;
                int row = id >> 2, part = id & 3;
                uint32_t off = (uint32_t)(row * 80 + part * 16);
                CP_ASYNC16(base + arr * TB + off,
                           srcs[arr] + (size_t)(r0 + row) * DM + k0 + part * 8);
            }
        }
        CP_COMMIT();
    };

    const int l7  = lane & 7;
    const int l8  = (lane >> 3) & 1;
    const int l16 = (lane >> 4) & 1;

    load_chunk(0, 0);
    load_chunk(1, 1);

    for (int t = 0; t < NCHUNK; t++) {
        if (t + 1 < NCHUNK) CP_WAIT(1);
        else                CP_WAIT(0);
        __syncthreads();

        const int s = t & 1;
        const uint32_t aHi = s0 + s * STAGE_B;
        const uint32_t aLo = aHi + TB;
        const uint32_t bHi = aHi + 2 * TB;
        const uint32_t bLo = aHi + 3 * TB;

        #pragma unroll
        for (int ks = 0; ks < 2; ks++) {
            const int kb = ks * 16;
            uint32_t afrag[4][4], bhif[4][2], blof[4][2];
            #pragma unroll
            for (int bp = 0; bp < 2; bp++) {
                uint32_t off = (uint32_t)((wn * 32 + bp * 16 + l16 * 8 + l7) * 80 +
                                          (kb + l8 * 8) * 2);
                uint32_t r0, r1, r2, r3;
                LDMATRIX_X4(r0, r1, r2, r3, bHi + off);
                bhif[bp * 2 + 0][0] = r0; bhif[bp * 2 + 0][1] = r1;
                bhif[bp * 2 + 1][0] = r2; bhif[bp * 2 + 1][1] = r3;
                LDMATRIX_X4(r0, r1, r2, r3, bLo + off);
                blof[bp * 2 + 0][0] = r0; blof[bp * 2 + 0][1] = r1;
                blof[bp * 2 + 1][0] = r2; blof[bp * 2 + 1][1] = r3;
            }
            #pragma unroll
            for (int mt = 0; mt < 4; mt++) {
                uint32_t addr = aHi +
                    (uint32_t)((wm * 64 + mt * 16 + l8 * 8 + l7) * 80 +
                               (kb + l16 * 8) * 2);
                LDMATRIX_X4(afrag[mt][0], afrag[mt][1], afrag[mt][2], afrag[mt][3], addr);
            }
            #pragma unroll
            for (int mt = 0; mt < 4; mt++)
                #pragma unroll
                for (int nt = 0; nt < 4; nt++) {
                    mma_bf16(acc[mt][nt], afrag[mt], bhif[nt]);
                    mma_bf16(acc[mt][nt], afrag[mt], blof[nt]);
                }
            #pragma unroll
            for (int mt = 0; mt < 4; mt++) {
                uint32_t addr = aLo +
                    (uint32_t)((wm * 64 + mt * 16 + l8 * 8 + l7) * 80 +
                               (kb + l16 * 8) * 2);
                LDMATRIX_X4(afrag[mt][0], afrag[mt][1], afrag[mt][2], afrag[mt][3], addr);
            }
            #pragma unroll
            for (int mt = 0; mt < 4; mt++)
                #pragma unroll
                for (int nt = 0; nt < 4; nt++)
                    mma_bf16(acc[mt][nt], afrag[mt], bhif[nt]);
        }

        __syncthreads();
        if (t + 2 < NCHUNK) load_chunk(t + 2, s);
    }

    #pragma unroll
    for (int mt = 0; mt < 4; mt++) {
        #pragma unroll
        for (int half = 0; half < 2; half++) {
            int m = bm0 + wm * 64 + mt * 16 + grp + half * 8;
            int bb = m >> 11;
            int ss = m & (SEQ - 1);
            #pragma unroll
            for (int nt = 0; nt < 4; nt++) {
                int n = bn0 + wn * 32 + nt * 8 + q4 * 2;
                int h = n >> 6, d = n & 63;
                float x = acc[mt][nt][half * 2 + 0];
                float y = acc[mt][nt][half * 2 + 1];
                float xh = __bfloat162float(__float2bfloat16(x));
                float yh = __bfloat162float(__float2bfloat16(y));
                size_t idx = (((size_t)(bb * NHEADS + h) * SEQ + ss) << 6) + d;
                *(uint32_t*)&dhi[idx] = pack_bf2(x, y);
                *(uint32_t*)&dlo[idx] = pack_bf2(x - xh, y - yh);
            }
        }
    }
}

// ---------------------------------------------------------------------------
// Kernel 4: flash attention, 128 threads (4 warps), BM=64, 2-stage KV ring.
// 2 CTAs/SM (smem 93.7 KB/CTA): independent CTAs overlap softmax with MMA.
// grid (32 qtiles, 16 heads, 2 batch).
// ---------------------------------------------------------------------------
#define AT_RB   144
#define AT_TILE (64 * AT_RB)                      // 9216 B per 64x64 tile
#define A2NS    2                                 // KV stages
#define A2_QOFF (A2NS * 4 * AT_TILE)              // 73728
#define A2_BW   (A2_QOFF + 2 * 64 * AT_RB)        // 92160: bw[2][128] f32
#define A2_MW   (A2_BW + A2NS * 128 * 4)          // 93184: mw[2][64] f32
#define A2_SMEM (A2_MW + A2NS * 64 * 4)           // 93696
#define NKT     (SEQ / 64)

__global__ void __launch_bounds__(128) attn_mma_kernel(
    const float* __restrict__ key_mask, float* __restrict__ out)
{
    extern __shared__ char dsm[];
    const uint32_t sb = smem_u32(dsm);

    const int tid  = threadIdx.x;
    const int lane = tid & 31;
    const int wid  = tid >> 5;          // 0..3
    const int g    = lane >> 2;
    const int q4   = lane & 3;
    const int l7   = lane & 7;
    const int l8   = (lane >> 3) & 1;
    const int l16  = (lane >> 4) & 1;

    const int qt0 = blockIdx.x * 64;
    const int h   = blockIdx.y;
    const int b   = blockIdx.z;
    const size_t bh = ((size_t)(b * NHEADS + h)) << 17;

    const __nv_bfloat16* Khi = g_khi + bh;
    const __nv_bfloat16* Klo = g_klo + bh;
    const __nv_bfloat16* Vhi = g_vhi + bh;
    const __nv_bfloat16* Vlo = g_vlo + bh;
    const float* bias_h = g_bias + h * 4096;

    // ---- issue Q loads (first commit group): 64 rows hi + lo ----
    {
        const __nv_bfloat16* srcs[2] = { g_qhi + bh, g_qlo + bh };
        #pragma unroll
        for (int arr = 0; arr < 2; arr++)
            #pragma unroll
            for (int jj = 0; jj < 4; jj++) {
                int rem = jj * 128 + tid;          // 0..511
                int row = rem >> 3, part = rem & 7;
                uint32_t dst = sb + A2_QOFF + arr * (64 * AT_RB) + row * AT_RB + part * 16;
                CP_ASYNC16(dst, srcs[arr] + (size_t)(qt0 + row) * HEAD + part * 8);
            }
        CP_COMMIT();
    }

    auto issue_kv = [&](int kt, int s) {
        const __nv_bfloat16* srcs[4] = { Khi, Klo, Vhi, Vlo };
        #pragma unroll
        for (int arr = 0; arr < 4; arr++)
            #pragma unroll
            for (int jj = 0; jj < 4; jj++) {
                int rem = jj * 128 + tid;          // 0..511
                int row = rem >> 3, part = rem & 7;
                uint32_t dst = sb + (s * 4 + arr) * AT_TILE + row * AT_RB + part * 16;
                CP_ASYNC16(dst, srcs[arr] + (size_t)(kt * 64 + row) * HEAD + part * 8);
            }
        CP_COMMIT();
        float* bw = (float*)(dsm + A2_BW + s * 512);
        float* mw = (float*)(dsm + A2_MW + s * 256);
        if (tid < 127) {
            int idx = kt * 64 + tid - 63 - qt0 + 2047;
            idx = max(0, min(4094, idx));
            bw[tid] = bias_h[idx];
        }
        if (tid < 64) {
            float mk = key_mask[(size_t)b * SEQ + kt * 64 + tid];
            mw[tid] = (1.0f - mk) * -10000.0f;
        }
    };

    issue_kv(0, 0);

    uint32_t qhi[4][4], qlo[4][4];
    float oacc[8][4];
    #pragma unroll
    for (int nt = 0; nt < 8; nt++)
        #pragma unroll
        for (int r = 0; r < 4; r++) oacc[nt][r] = 0.0f;
    float mrow[2] = { -INFINITY, -INFINITY };
    float lrow[2] = { 0.0f, 0.0f };

    for (int t = 0; t < NKT; t++) {
        if (t + 1 < NKT) { issue_kv(t + 1, (t + 1) & 1); CP_WAIT(1); }
        else             { CP_WAIT(0); }
        __syncthreads();                 // stage t&1 (and Q at t=0) visible

        if (t == 0) {
            #pragma unroll
            for (int kk = 0; kk < 4; kk++) {
                uint32_t ah = sb + A2_QOFF + (wid * 16 + l8 * 8 + l7) * AT_RB +
                              (kk * 16 + l16 * 8) * 2;
                LDMATRIX_X4(qhi[kk][0], qhi[kk][1], qhi[kk][2], qhi[kk][3], ah);
                uint32_t al = ah + 64 * AT_RB;
                LDMATRIX_X4(qlo[kk][0], qlo[kk][1], qlo[kk][2], qlo[kk][3], al);
            }
        }

        const int s = t & 1;
        const uint32_t kb_hi = sb + (s * 4 + 0) * AT_TILE;
        const uint32_t kb_lo = sb + (s * 4 + 1) * AT_TILE;
        const uint32_t vb_hi = sb + (s * 4 + 2) * AT_TILE;
        const uint32_t vb_lo = sb + (s * 4 + 3) * AT_TILE;
        const float* bw = (const float*)(dsm + A2_BW + s * 512);
        const float* mw = (const float*)(dsm + A2_MW + s * 256);

        // ---- S = Q K^T (3-pass split) ----
        float sacc[8][4];
        #pragma unroll
        for (int nt = 0; nt < 8; nt++)
            #pragma unroll
            for (int r = 0; r < 4; r++) sacc[nt][r] = 0.0f;

        #pragma unroll
        for (int kk = 0; kk < 4; kk++) {
            uint32_t bhif[8][2], blof[8][2];
            #pragma unroll
            for (int bp = 0; bp < 4; bp++) {
                uint32_t off = (uint32_t)((bp * 16 + l16 * 8 + l7) * AT_RB +
                                          (kk * 16 + l8 * 8) * 2);
                uint32_t r0, r1, r2, r3;
                LDMATRIX_X4(r0, r1, r2, r3, kb_hi + off);
                bhif[bp * 2][0] = r0; bhif[bp * 2][1] = r1;
                bhif[bp * 2 + 1][0] = r2; bhif[bp * 2 + 1][1] = r3;
                LDMATRIX_X4(r0, r1, r2, r3, kb_lo + off);
                blof[bp * 2][0] = r0; blof[bp * 2][1] = r1;
                blof[bp * 2 + 1][0] = r2; blof[bp * 2 + 1][1] = r3;
            }
            #pragma unroll
            for (int nt = 0; nt < 8; nt++) {
                mma_bf16(sacc[nt], qhi[kk], bhif[nt]);
                mma_bf16(sacc[nt], qlo[kk], bhif[nt]);
                mma_bf16(sacc[nt], qhi[kk], blof[nt]);
            }
        }

        // ---- softmax in registers ----
        #pragma unroll
        for (int hl = 0; hl < 2; hl++) {
            int rr = wid * 16 + g + hl * 8;
            float mx = -INFINITY;
            #pragma unroll
            for (int nt = 0; nt < 8; nt++) {
                #pragma unroll
                for (int e = 0; e < 2; e++) {
                    int c = nt * 8 + q4 * 2 + e;
                    float v = sacc[nt][hl * 2 + e] + bw[c - rr + 63] + mw[c];
                    sacc[nt][hl * 2 + e] = v;
                    mx = fmaxf(mx, v);
                }
            }
            mx = fmaxf(mx, __shfl_xor_sync(0xffffffffu, mx, 1));
            mx = fmaxf(mx, __shfl_xor_sync(0xffffffffu, mx, 2));
            float mnew = fmaxf(mrow[hl], mx);
            float corr = __expf(mrow[hl] - mnew);
            mrow[hl] = mnew;
            float sum = 0.0f;
            #pragma unroll
            for (int nt = 0; nt < 8; nt++) {
                #pragma unroll
                for (int e = 0; e < 2; e++) {
                    float p = __expf(sacc[nt][hl * 2 + e] - mnew);
                    sacc[nt][hl * 2 + e] = p;
                    sum += p;
                }
            }
            sum += __shfl_xor_sync(0xffffffffu, sum, 1);
            sum += __shfl_xor_sync(0xffffffffu, sum, 2);
            lrow[hl] = lrow[hl] * corr + sum;
            #pragma unroll
            for (int nt = 0; nt < 8; nt++) {
                oacc[nt][hl * 2 + 0] *= corr;
                oacc[nt][hl * 2 + 1] *= corr;
            }
        }

        // ---- P -> bf16 hi/lo A-fragments ----
        uint32_t phi[4][4], plo[4][4];
        #pragma unroll
        for (int kk = 0; kk < 4; kk++) {
            #pragma unroll
            for (int part = 0; part < 4; part++) {
                int nt = 2 * kk + (part >> 1);
                int o = (part & 1) * 2;
                float p0 = sacc[nt][o], p1 = sacc[nt][o + 1];
                float h0 = __bfloat162float(__float2bfloat16(p0));
                float h1 = __bfloat162float(__float2bfloat16(p1));
                phi[kk][part] = pack_bf2(p0, p1);
                plo[kk][part] = pack_bf2(p0 - h0, p1 - h1);
            }
        }

        // ---- O += P V (3-pass split), V via trans ldmatrix ----
        #pragma unroll
        for (int kk = 0; kk < 4; kk++) {
            uint32_t vhif[8][2], vlof[8][2];
            #pragma unroll
            for (int db = 0; db < 4; db++) {
                uint32_t off = (uint32_t)((kk * 16 + l8 * 8 + l7) * AT_RB +
                                          (db * 16 + l16 * 8) * 2);
                uint32_t r0, r1, r2, r3;
                LDMATRIX_X4T(r0, r1, r2, r3, vb_hi + off);
                vhif[db * 2][0] = r0; vhif[db * 2][1] = r1;
                vhif[db * 2 + 1][0] = r2; vhif[db * 2 + 1][1] = r3;
                LDMATRIX_X4T(r0, r1, r2, r3, vb_lo + off);
                vlof[db * 2][0] = r0; vlof[db * 2][1] = r1;
                vlof[db * 2 + 1][0] = r2; vlof[db * 2 + 1][1] = r3;
            }
            #pragma unroll
            for (int nt = 0; nt < 8; nt++) {
                mma_bf16(oacc[nt], phi[kk], vhif[nt]);
                mma_bf16(oacc[nt], plo[kk], vhif[nt]);
                mma_bf16(oacc[nt], phi[kk], vlof[nt]);
            }
        }

        __syncthreads();                 // reads of stage s done before reuse
    }

    // ---- epilogue: out[b][qrow][h*64 + d] = O / l ----
    #pragma unroll
    for (int hl = 0; hl < 2; hl++) {
        int rr = wid * 16 + g + hl * 8;
        float inv = 1.0f / lrow[hl];
        size_t base = ((size_t)(b * SEQ + qt0 + rr)) * (NHEADS * HEAD) + h * HEAD;
        #pragma unroll
        for (int nt = 0; nt < 8; nt++) {
            int c = nt * 8 + q4 * 2;
            float2 v;
            v.x = oacc[nt][hl * 2 + 0] * inv;
            v.y = oacc[nt][hl * 2 + 1] * inv;
            *(float2*)&out[base + c] = v;
        }
    }
}

// ---------------------------------------------------------------------------
// Launch
// ---------------------------------------------------------------------------
extern "C" void kernel_launch(void* const* d_in, const int* in_sizes, int n_in,
                              void* d_out, int out_size) {
    const float* query    = (const float*)d_in[0];
    const float* key      = (const float*)d_in[1];
    const float* value    = (const float*)d_in[2];
    const float* key_mask = (const float*)d_in[3];
    const float* Wq       = (const float*)d_in[4];
    const float* Wk       = (const float*)d_in[5];
    const float* Wv       = (const float*)d_in[6];
    const float* bias_tab = (const float*)d_in[7];
    float* out = (float*)d_out;

    cudaFuncSetAttribute(proj_mma_kernel,
                         cudaFuncAttributeMaxDynamicSharedMemorySize, PROJ_SMEM);
    cudaFuncSetAttribute(attn_mma_kernel,
                         cudaFuncAttributeMaxDynamicSharedMemorySize, A2_SMEM);

    bias_precompute_kernel<<<16, 256>>>(bias_tab);
    convert_x_kernel<<<dim3(4096, 3), 256>>>(query, key, value);
    convert_w_kernel<<<dim3(32, 32, 3), dim3(32, 32)>>>(Wq, Wk, Wv);
    proj_mma_kernel<<<dim3(8, 32, 3), 256, PROJ_SMEM>>>();
    attn_mma_kernel<<<dim3(SEQ / 64, NHEADS, NB), 128, A2_SMEM>>>(key_mask, out);
}

// round 12
// speedup vs baseline: 2.6999x; 1.0043x over previous
#include <cuda_runtime.h>
#include <cuda_bf16.h>
#include <math.h>
#include <stdint.h>

// ---------------------------------------------------------------------------
// Problem constants (B=2, S=2048, D_MODEL=1024, H=16, Dh=64)
// ---------------------------------------------------------------------------
#define NB      2
#define SEQ     2048
#define DM      1024
#define NHEADS  16
#define HEAD    64

__device__ float g_bias[NHEADS * 4096];

// bf16 split operands for projection GEMMs
__device__ __nv_bfloat16 g_Ahi[3][4096 * 1024];
__device__ __nv_bfloat16 g_Alo[3][4096 * 1024];
__device__ __nv_bfloat16 g_Bhi[3][1024 * 1024];
__device__ __nv_bfloat16 g_Blo[3][1024 * 1024];

// Q/K/V split outputs of projections: [B][H][S][64] bf16 hi/lo
#define QKV_ELE (NB * NHEADS * SEQ * HEAD)
__device__ __nv_bfloat16 g_qhi[QKV_ELE], g_qlo[QKV_ELE];
__device__ __nv_bfloat16 g_khi[QKV_ELE], g_klo[QKV_ELE];
__device__ __nv_bfloat16 g_vhi[QKV_ELE], g_vlo[QKV_ELE];

// ---------------------------------------------------------------------------
// PTX helpers
// ---------------------------------------------------------------------------
__device__ __forceinline__ uint32_t smem_u32(const void* p) {
    uint32_t a;
    asm("{ .reg .u64 t; cvta.to.shared.u64 t, %1; cvt.u32.u64 %0, t; }"
        : "=r"(a) : "l"(p));
    return a;
}
#define CP_ASYNC16(dst, src) \
    asm volatile("cp.async.cg.shared.global [%0], [%1], 16;" :: "r"(dst), "l"(src))
#define CP_COMMIT() asm volatile("cp.async.commit_group;" ::: "memory")
#define CP_WAIT(n)  asm volatile("cp.async.wait_group %0;" :: "n"(n) : "memory")

#define LDMATRIX_X4(r0, r1, r2, r3, addr) \
    asm volatile("ldmatrix.sync.aligned.m8n8.x4.shared.b16 {%0,%1,%2,%3}, [%4];" \
                 : "=r"(r0), "=r"(r1), "=r"(r2), "=r"(r3) : "r"(addr))
#define LDMATRIX_X4T(r0, r1, r2, r3, addr) \
    asm volatile("ldmatrix.sync.aligned.m8n8.x4.trans.shared.b16 {%0,%1,%2,%3}, [%4];" \
                 : "=r"(r0), "=r"(r1), "=r"(r2), "=r"(r3) : "r"(addr))

__device__ __forceinline__ void mma_bf16(float* d, const uint32_t* a,
                                         const uint32_t* b) {
    asm volatile(
        "mma.sync.aligned.m16n8k16.row.col.f32.bf16.bf16.f32 "
        "{%0,%1,%2,%3}, {%4,%5,%6,%7}, {%8,%9}, {%0,%1,%2,%3};"
        : "+f"(d[0]), "+f"(d[1]), "+f"(d[2]), "+f"(d[3])
        : "r"(a[0]), "r"(a[1]), "r"(a[2]), "r"(a[3]), "r"(b[0]), "r"(b[1]));
}
__device__ __forceinline__ uint32_t pack_bf2(float a, float b) {
    __nv_bfloat162 t = __floats2bfloat162_rn(a, b);
    return *(uint32_t*)&t;
}

// ---------------------------------------------------------------------------
// Kernel 1: relative-position bias table expansion (known-good)
// ---------------------------------------------------------------------------
__global__ void bias_precompute_kernel(const float* __restrict__ bias_table) {
    int i = blockIdx.x * blockDim.x + threadIdx.x;
    if (i >= 4095) return;
    int delta = i - 2047;
    int ret = (delta > 0) ? 16 : 0;
    int rp = abs(delta);
    int bucket;
    if (rp < 8) {
        bucket = ret + rp;
    } else {
        int vl;
        if ((rp & (rp - 1)) == 0) {
            int k = __ffs(rp) - 1;
            vl = 8 + 2 * (k - 3);
        } else {
            float t = logf((float)rp * 0.125f) / 2.7725887f;
            vl = 8 + (int)(t * 8.0f);
        }
        bucket = ret + min(vl, 15);
    }
    #pragma unroll
    for (int h = 0; h < NHEADS; h++)
        g_bias[h * 4096 + i] = bias_table[bucket * NHEADS + h];
}

// ---------------------------------------------------------------------------
// Kernel 2a: split activations X -> bf16 hi/lo
// ---------------------------------------------------------------------------
__global__ void __launch_bounds__(256) convert_x_kernel(
    const float* __restrict__ Xq, const float* __restrict__ Xk,
    const float* __restrict__ Xv)
{
    int z = blockIdx.y;
    const float* X = (z == 0) ? Xq : (z == 1) ? Xk : Xv;
    __nv_bfloat16* hi = g_Ahi[z];
    __nv_bfloat16* lo = g_Alo[z];
    size_t i = ((size_t)blockIdx.x * 256 + threadIdx.x) * 4;
    float4 v = *(const float4*)(X + i);
    float f[4] = {v.x, v.y, v.z, v.w};
    #pragma unroll
    for (int j = 0; j < 4; j++) {
        __nv_bfloat16 h = __float2bfloat16(f[j]);
        hi[i + j] = h;
        lo[i + j] = __float2bfloat16(f[j] - __bfloat162float(h));
    }
}

// ---------------------------------------------------------------------------
// Kernel 2b: transpose + split weights  W[k][n] -> Wt[n][k] bf16 hi/lo
// ---------------------------------------------------------------------------
__global__ void __launch_bounds__(1024) convert_w_kernel(
    const float* __restrict__ Wq, const float* __restrict__ Wk,
    const float* __restrict__ Wv)
{
    __shared__ float tile[32][33];
    int z = blockIdx.z;
    const float* W = (z == 0) ? Wq : (z == 1) ? Wk : Wv;
    int k0 = blockIdx.x * 32;
    int n0 = blockIdx.y * 32;
    int tx = threadIdx.x, ty = threadIdx.y;
    tile[ty][tx] = W[(size_t)(k0 + ty) * DM + n0 + tx];
    __syncthreads();
    float v = tile[tx][ty];
    __nv_bfloat16 h = __float2bfloat16(v);
    size_t idx = (size_t)(n0 + ty) * DM + k0 + tx;
    g_Bhi[z][idx] = h;
    g_Blo[z][idx] = __float2bfloat16(v - __bfloat162float(h));
}

// ---------------------------------------------------------------------------
// Kernel 3: projection GEMM, FUSED 3-pass split, reduced register pressure:
// A processed in two mt-halves per ks phase (peak live A-frags 8 regs not 16).
// 2-stage cp.async double buffer, 32 iterations, 2 CTAs/SM.
// ---------------------------------------------------------------------------
#define BK 32
#define TB 10240
#define STAGE_B (4 * TB)
#define PROJ_SMEM (2 * STAGE_B)          // 81920 B
#define NCHUNK 32

__global__ void __launch_bounds__(256, 2) proj_mma_kernel() {
    extern __shared__ char psm[];

    const int tid  = threadIdx.x;
    const int lane = tid & 31;
    const int wid  = tid >> 5;
    const int wm   = wid >> 2;
    const int wn   = wid & 3;
    const int grp  = lane >> 2;
    const int q4   = lane & 3;

    const int z   = blockIdx.z;
    const int bm0 = blockIdx.y * 128;
    const int bn0 = blockIdx.x * 128;

    const __nv_bfloat16* __restrict__ srcs[4] = {
        g_Ahi[z], g_Alo[z], g_Bhi[z], g_Blo[z] };
    __nv_bfloat16* dhi = (z == 0) ? g_qhi : (z == 1) ? g_khi : g_vhi;
    __nv_bfloat16* dlo = (z == 0) ? g_qlo : (z == 1) ? g_klo : g_vlo;

    const uint32_t s0 = smem_u32(psm);

    float acc[4][4][4];
    #pragma unroll
    for (int i = 0; i < 4; i++)
        #pragma unroll
        for (int j = 0; j < 4; j++)
            #pragma unroll
            for (int r = 0; r < 4; r++) acc[i][j][r] = 0.0f;

    auto load_chunk = [&](int t, int s) {
        int k0 = t * BK;
        uint32_t base = s0 + s * STAGE_B;
        #pragma unroll
        for (int arr = 0; arr < 4; arr++) {
            int r0 = (arr < 2) ? bm0 : bn0;
            #pragma unroll
            for (int j = 0; j < 2; j++) {
                int id = tid + 256 * j;
                int row = id >> 2, part = id & 3;
                uint32_t off = (uint32_t)(row * 80 + part * 16);
                CP_ASYNC16(base + arr * TB + off,
                           srcs[arr] + (size_t)(r0 + row) * DM + k0 + part * 8);
            }
        }
        CP_COMMIT();
    };

    const int l7  = lane & 7;
    const int l8  = (lane >> 3) & 1;
    const int l16 = (lane >> 4) & 1;

    load_chunk(0, 0);
    load_chunk(1, 1);

    for (int t = 0; t < NCHUNK; t++) {
        if (t + 1 < NCHUNK) CP_WAIT(1);
        else                CP_WAIT(0);
        __syncthreads();

        const int s = t & 1;
        const uint32_t aHi = s0 + s * STAGE_B;
        const uint32_t aLo = aHi + TB;
        const uint32_t bHi = aHi + 2 * TB;
        const uint32_t bLo = aHi + 3 * TB;

        #pragma unroll
        for (int ks = 0; ks < 2; ks++) {
            const int kb = ks * 16;
            uint32_t bhif[4][2], blof[4][2];
            // B hi + lo fragments (16 regs live)
            #pragma unroll
            for (int bp = 0; bp < 2; bp++) {
                uint32_t off = (uint32_t)((wn * 32 + bp * 16 + l16 * 8 + l7) * 80 +
                                          (kb + l8 * 8) * 2);
                uint32_t r0, r1, r2, r3;
                LDMATRIX_X4(r0, r1, r2, r3, bHi + off);
                bhif[bp * 2 + 0][0] = r0; bhif[bp * 2 + 0][1] = r1;
                bhif[bp * 2 + 1][0] = r2; bhif[bp * 2 + 1][1] = r3;
                LDMATRIX_X4(r0, r1, r2, r3, bLo + off);
                blof[bp * 2 + 0][0] = r0; blof[bp * 2 + 0][1] = r1;
                blof[bp * 2 + 1][0] = r2; blof[bp * 2 + 1][1] = r3;
            }
            // A processed in two mt-halves: only 2 A-frags (8 regs) live
            #pragma unroll
            for (int mh = 0; mh < 2; mh++) {
                uint32_t afrag[2][4];
                #pragma unroll
                for (int mi = 0; mi < 2; mi++) {
                    int mt = mh * 2 + mi;
                    uint32_t addr = aHi +
                        (uint32_t)((wm * 64 + mt * 16 + l8 * 8 + l7) * 80 +
                                   (kb + l16 * 8) * 2);
                    LDMATRIX_X4(afrag[mi][0], afrag[mi][1], afrag[mi][2], afrag[mi][3], addr);
                }
                #pragma unroll
                for (int mi = 0; mi < 2; mi++)
                    #pragma unroll
                    for (int nt = 0; nt < 4; nt++) {
                        mma_bf16(acc[mh * 2 + mi][nt], afrag[mi], bhif[nt]);
                        mma_bf16(acc[mh * 2 + mi][nt], afrag[mi], blof[nt]);
                    }
                #pragma unroll
                for (int mi = 0; mi < 2; mi++) {
                    int mt = mh * 2 + mi;
                    uint32_t addr = aLo +
                        (uint32_t)((wm * 64 + mt * 16 + l8 * 8 + l7) * 80 +
                                   (kb + l16 * 8) * 2);
                    LDMATRIX_X4(afrag[mi][0], afrag[mi][1], afrag[mi][2], afrag[mi][3], addr);
                }
                #pragma unroll
                for (int mi = 0; mi < 2; mi++)
                    #pragma unroll
                    for (int nt = 0; nt < 4; nt++)
                        mma_bf16(acc[mh * 2 + mi][nt], afrag[mi], bhif[nt]);
            }
        }

        __syncthreads();
        if (t + 2 < NCHUNK) load_chunk(t + 2, s);
    }

    #pragma unroll
    for (int mt = 0; mt < 4; mt++) {
        #pragma unroll
        for (int half = 0; half < 2; half++) {
            int m = bm0 + wm * 64 + mt * 16 + grp + half * 8;
            int bb = m >> 11;
            int ss = m & (SEQ - 1);
            #pragma unroll
            for (int nt = 0; nt < 4; nt++) {
                int n = bn0 + wn * 32 + nt * 8 + q4 * 2;
                int h = n >> 6, d = n & 63;
                float x = acc[mt][nt][half * 2 + 0];
                float y = acc[mt][nt][half * 2 + 1];
                float xh = __bfloat162float(__float2bfloat16(x));
                float yh = __bfloat162float(__float2bfloat16(y));
                size_t idx = (((size_t)(bb * NHEADS + h) * SEQ + ss) << 6) + d;
                *(uint32_t*)&dhi[idx] = pack_bf2(x, y);
                *(uint32_t*)&dlo[idx] = pack_bf2(x - xh, y - yh);
            }
        }
    }
}

// ---------------------------------------------------------------------------
// Kernel 4: flash attention, 128 threads (4 warps), BM=64, 2-stage KV ring,
// ONE __syncthreads per key tile (load issued AFTER the top sync — stage
// (t+1)&1 was last read in iter t-1, before this sync).
// 2 CTAs/SM. grid (32 qtiles, 16 heads, 2 batch).
// ---------------------------------------------------------------------------
#define AT_RB   144
#define AT_TILE (64 * AT_RB)                      // 9216 B per 64x64 tile
#define A2NS    2
#define A2_QOFF (A2NS * 4 * AT_TILE)              // 73728
#define A2_BW   (A2_QOFF + 2 * 64 * AT_RB)        // 92160
#define A2_MW   (A2_BW + A2NS * 128 * 4)          // 93184
#define A2_SMEM (A2_MW + A2NS * 64 * 4)           // 93696
#define NKT     (SEQ / 64)

__global__ void __launch_bounds__(128) attn_mma_kernel(
    const float* __restrict__ key_mask, float* __restrict__ out)
{
    extern __shared__ char dsm[];
    const uint32_t sb = smem_u32(dsm);

    const int tid  = threadIdx.x;
    const int lane = tid & 31;
    const int wid  = tid >> 5;
    const int g    = lane >> 2;
    const int q4   = lane & 3;
    const int l7   = lane & 7;
    const int l8   = (lane >> 3) & 1;
    const int l16  = (lane >> 4) & 1;

    const int qt0 = blockIdx.x * 64;
    const int h   = blockIdx.y;
    const int b   = blockIdx.z;
    const size_t bh = ((size_t)(b * NHEADS + h)) << 17;

    const __nv_bfloat16* Khi = g_khi + bh;
    const __nv_bfloat16* Klo = g_klo + bh;
    const __nv_bfloat16* Vhi = g_vhi + bh;
    const __nv_bfloat16* Vlo = g_vlo + bh;
    const float* bias_h = g_bias + h * 4096;

    // ---- issue Q loads ----
    {
        const __nv_bfloat16* srcs[2] = { g_qhi + bh, g_qlo + bh };
        #pragma unroll
        for (int arr = 0; arr < 2; arr++)
            #pragma unroll
            for (int jj = 0; jj < 4; jj++) {
                int rem = jj * 128 + tid;
                int row = rem >> 3, part = rem & 7;
                uint32_t dst = sb + A2_QOFF + arr * (64 * AT_RB) + row * AT_RB + part * 16;
                CP_ASYNC16(dst, srcs[arr] + (size_t)(qt0 + row) * HEAD + part * 8);
            }
        CP_COMMIT();
    }

    auto issue_kv = [&](int kt, int s) {
        const __nv_bfloat16* srcs[4] = { Khi, Klo, Vhi, Vlo };
        #pragma unroll
        for (int arr = 0; arr < 4; arr++)
            #pragma unroll
            for (int jj = 0; jj < 4; jj++) {
                int rem = jj * 128 + tid;
                int row = rem >> 3, part = rem & 7;
                uint32_t dst = sb + (s * 4 + arr) * AT_TILE + row * AT_RB + part * 16;
                CP_ASYNC16(dst, srcs[arr] + (size_t)(kt * 64 + row) * HEAD + part * 8);
            }
        CP_COMMIT();
        float* bw = (float*)(dsm + A2_BW + s * 512);
        float* mw = (float*)(dsm + A2_MW + s * 256);
        if (tid < 127) {
            int idx = kt * 64 + tid - 63 - qt0 + 2047;
            idx = max(0, min(4094, idx));
            bw[tid] = bias_h[idx];
        }
        if (tid < 64) {
            float mk = key_mask[(size_t)b * SEQ + kt * 64 + tid];
            mw[tid] = (1.0f - mk) * -10000.0f;
        }
    };

    issue_kv(0, 0);

    uint32_t qhi[4][4], qlo[4][4];
    float oacc[8][4];
    #pragma unroll
    for (int nt = 0; nt < 8; nt++)
        #pragma unroll
        for (int r = 0; r < 4; r++) oacc[nt][r] = 0.0f;
    float mrow[2] = { -INFINITY, -INFINITY };
    float lrow[2] = { 0.0f, 0.0f };

    for (int t = 0; t < NKT; t++) {
        CP_WAIT(0);                      // load t (and Q at t=0) complete
        __syncthreads();                 // SINGLE barrier: publishes load t,
                                         // and orders iter t-1's reads of
                                         // stage (t+1)&1 before its reuse
        if (t + 1 < NKT) issue_kv(t + 1, (t + 1) & 1);

        if (t == 0) {
            #pragma unroll
            for (int kk = 0; kk < 4; kk++) {
                uint32_t ah = sb + A2_QOFF + (wid * 16 + l8 * 8 + l7) * AT_RB +
                              (kk * 16 + l16 * 8) * 2;
                LDMATRIX_X4(qhi[kk][0], qhi[kk][1], qhi[kk][2], qhi[kk][3], ah);
                uint32_t al = ah + 64 * AT_RB;
                LDMATRIX_X4(qlo[kk][0], qlo[kk][1], qlo[kk][2], qlo[kk][3], al);
            }
        }

        const int s = t & 1;
        const uint32_t kb_hi = sb + (s * 4 + 0) * AT_TILE;
        const uint32_t kb_lo = sb + (s * 4 + 1) * AT_TILE;
        const uint32_t vb_hi = sb + (s * 4 + 2) * AT_TILE;
        const uint32_t vb_lo = sb + (s * 4 + 3) * AT_TILE;
        const float* bw = (const float*)(dsm + A2_BW + s * 512);
        const float* mw = (const float*)(dsm + A2_MW + s * 256);

        // ---- S = Q K^T (3-pass split) ----
        float sacc[8][4];
        #pragma unroll
        for (int nt = 0; nt < 8; nt++)
            #pragma unroll
            for (int r = 0; r < 4; r++) sacc[nt][r] = 0.0f;

        #pragma unroll
        for (int kk = 0; kk < 4; kk++) {
            uint32_t bhif[8][2], blof[8][2];
            #pragma unroll
            for (int bp = 0; bp < 4; bp++) {
                uint32_t off = (uint32_t)((bp * 16 + l16 * 8 + l7) * AT_RB +
                                          (kk * 16 + l8 * 8) * 2);
                uint32_t r0, r1, r2, r3;
                LDMATRIX_X4(r0, r1, r2, r3, kb_hi + off);
                bhif[bp * 2][0] = r0; bhif[bp * 2][1] = r1;
                bhif[bp * 2 + 1][0] = r2; bhif[bp * 2 + 1][1] = r3;
                LDMATRIX_X4(r0, r1, r2, r3, kb_lo + off);
                blof[bp * 2][0] = r0; blof[bp * 2][1] = r1;
                blof[bp * 2 + 1][0] = r2; blof[bp * 2 + 1][1] = r3;
            }
            #pragma unroll
            for (int nt = 0; nt < 8; nt++) {
                mma_bf16(sacc[nt], qhi[kk], bhif[nt]);
                mma_bf16(sacc[nt], qlo[kk], bhif[nt]);
                mma_bf16(sacc[nt], qhi[kk], blof[nt]);
            }
        }

        // ---- softmax in registers ----
        #pragma unroll
        for (int hl = 0; hl < 2; hl++) {
            int rr = wid * 16 + g + hl * 8;
            float mx = -INFINITY;
            #pragma unroll
            for (int nt = 0; nt < 8; nt++) {
                #pragma unroll
                for (int e = 0; e < 2; e++) {
                    int c = nt * 8 + q4 * 2 + e;
                    float v = sacc[nt][hl * 2 + e] + bw[c - rr + 63] + mw[c];
                    sacc[nt][hl * 2 + e] = v;
                    mx = fmaxf(mx, v);
                }
            }
            mx = fmaxf(mx, __shfl_xor_sync(0xffffffffu, mx, 1));
            mx = fmaxf(mx, __shfl_xor_sync(0xffffffffu, mx, 2));
            float mnew = fmaxf(mrow[hl], mx);
            float corr = __expf(mrow[hl] - mnew);
            mrow[hl] = mnew;
            float sum = 0.0f;
            #pragma unroll
            for (int nt = 0; nt < 8; nt++) {
                #pragma unroll
                for (int e = 0; e < 2; e++) {
                    float p = __expf(sacc[nt][hl * 2 + e] - mnew);
                    sacc[nt][hl * 2 + e] = p;
                    sum += p;
                }
            }
            sum += __shfl_xor_sync(0xffffffffu, sum, 1);
            sum += __shfl_xor_sync(0xffffffffu, sum, 2);
            lrow[hl] = lrow[hl] * corr + sum;
            #pragma unroll
            for (int nt = 0; nt < 8; nt++) {
                oacc[nt][hl * 2 + 0] *= corr;
                oacc[nt][hl * 2 + 1] *= corr;
            }
        }

        // ---- P -> bf16 hi/lo A-fragments ----
        uint32_t phi[4][4], plo[4][4];
        #pragma unroll
        for (int kk = 0; kk < 4; kk++) {
            #pragma unroll
            for (int part = 0; part < 4; part++) {
                int nt = 2 * kk + (part >> 1);
                int o = (part & 1) * 2;
                float p0 = sacc[nt][o], p1 = sacc[nt][o + 1];
                float h0 = __bfloat162float(__float2bfloat16(p0));
                float h1 = __bfloat162float(__float2bfloat16(p1));
                phi[kk][part] = pack_bf2(p0, p1);
                plo[kk][part] = pack_bf2(p0 - h0, p1 - h1);
            }
        }

        // ---- O += P V (3-pass split), V via trans ldmatrix ----
        #pragma unroll
        for (int kk = 0; kk < 4; kk++) {
            uint32_t vhif[8][2], vlof[8][2];
            #pragma unroll
            for (int db = 0; db < 4; db++) {
                uint32_t off = (uint32_t)((kk * 16 + l8 * 8 + l7) * AT_RB +
                                          (db * 16 + l16 * 8) * 2);
                uint32_t r0, r1, r2, r3;
                LDMATRIX_X4T(r0, r1, r2, r3, vb_hi + off);
                vhif[db * 2][0] = r0; vhif[db * 2][1] = r1;
                vhif[db * 2 + 1][0] = r2; vhif[db * 2 + 1][1] = r3;
                LDMATRIX_X4T(r0, r1, r2, r3, vb_lo + off);
                vlof[db * 2][0] = r0; vlof[db * 2][1] = r1;
                vlof[db * 2 + 1][0] = r2; vlof[db * 2 + 1][1] = r3;
            }
            #pragma unroll
            for (int nt = 0; nt < 8; nt++) {
                mma_bf16(oacc[nt], phi[kk], vhif[nt]);
                mma_bf16(oacc[nt], plo[kk], vhif[nt]);
                mma_bf16(oacc[nt], phi[kk], vlof[nt]);
            }
        }
    }

    // ---- epilogue: out[b][qrow][h*64 + d] = O / l ----
    #pragma unroll
    for (int hl = 0; hl < 2; hl++) {
        int rr = wid * 16 + g + hl * 8;
        float inv = 1.0f / lrow[hl];
        size_t base = ((size_t)(b * SEQ + qt0 + rr)) * (NHEADS * HEAD) + h * HEAD;
        #pragma unroll
        for (int nt = 0; nt < 8; nt++) {
            int c = nt * 8 + q4 * 2;
            float2 v;
            v.x = oacc[nt][hl * 2 + 0] * inv;
            v.y = oacc[nt][hl * 2 + 1] * inv;
            *(float2*)&out[base + c] = v;
        }
    }
}

// ---------------------------------------------------------------------------
// Launch
// ---------------------------------------------------------------------------
extern "C" void kernel_launch(void* const* d_in, const int* in_sizes, int n_in,
                              void* d_out, int out_size) {
    const float* query    = (const float*)d_in[0];
    const float* key      = (const float*)d_in[1];
    const float* value    = (const float*)d_in[2];
    const float* key_mask = (const float*)d_in[3];
    const float* Wq       = (const float*)d_in[4];
    const float* Wk       = (const float*)d_in[5];
    const float* Wv       = (const float*)d_in[6];
    const float* bias_tab = (const float*)d_in[7];
    float* out = (float*)d_out;

    cudaFuncSetAttribute(proj_mma_kernel,
                         cudaFuncAttributeMaxDynamicSharedMemorySize, PROJ_SMEM);
    cudaFuncSetAttribute(attn_mma_kernel,
                         cudaFuncAttributeMaxDynamicSharedMemorySize, A2_SMEM);

    bias_precompute_kernel<<<16, 256>>>(bias_tab);
    convert_x_kernel<<<dim3(4096, 3), 256>>>(query, key, value);
    convert_w_kernel<<<dim3(32, 32, 3), dim3(32, 32)>>>(Wq, Wk, Wv);
    proj_mma_kernel<<<dim3(8, 32, 3), 256, PROJ_SMEM>>>();
    attn_mma_kernel<<<dim3(SEQ / 64, NHEADS, NB), 128, A2_SMEM>>>(key_mask, out);
}

// round 13
// speedup vs baseline: 2.7983x; 1.0365x over previous
#include <cuda_runtime.h>
#include <cuda_bf16.h>
#include <math.h>
#include <stdint.h>

// ---------------------------------------------------------------------------
// Problem constants (B=2, S=2048, D_MODEL=1024, H=16, Dh=64)
// ---------------------------------------------------------------------------
#define NB      2
#define SEQ     2048
#define DM      1024
#define NHEADS  16
#define HEAD    64

__device__ float g_bias[NHEADS * 4096];

// bf16 split operands for projection GEMMs
__device__ __nv_bfloat16 g_Ahi[3][4096 * 1024];
__device__ __nv_bfloat16 g_Alo[3][4096 * 1024];
__device__ __nv_bfloat16 g_Bhi[3][1024 * 1024];
__device__ __nv_bfloat16 g_Blo[3][1024 * 1024];

// Q/K/V split outputs of projections: [B][H][S][64] bf16 hi/lo
#define QKV_ELE (NB * NHEADS * SEQ * HEAD)
__device__ __nv_bfloat16 g_qhi[QKV_ELE], g_qlo[QKV_ELE];
__device__ __nv_bfloat16 g_khi[QKV_ELE], g_klo[QKV_ELE];
__device__ __nv_bfloat16 g_vhi[QKV_ELE], g_vlo[QKV_ELE];

// ---------------------------------------------------------------------------
// PTX helpers
// ---------------------------------------------------------------------------
__device__ __forceinline__ uint32_t smem_u32(const void* p) {
    uint32_t a;
    asm("{ .reg .u64 t; cvta.to.shared.u64 t, %1; cvt.u32.u64 %0, t; }"
        : "=r"(a) : "l"(p));
    return a;
}
#define CP_ASYNC16(dst, src) \
    asm volatile("cp.async.cg.shared.global [%0], [%1], 16;" :: "r"(dst), "l"(src))
#define CP_COMMIT() asm volatile("cp.async.commit_group;" ::: "memory")
#define CP_WAIT(n)  asm volatile("cp.async.wait_group %0;" :: "n"(n) : "memory")

#define LDMATRIX_X4(r0, r1, r2, r3, addr) \
    asm volatile("ldmatrix.sync.aligned.m8n8.x4.shared.b16 {%0,%1,%2,%3}, [%4];" \
                 : "=r"(r0), "=r"(r1), "=r"(r2), "=r"(r3) : "r"(addr))
#define LDMATRIX_X4T(r0, r1, r2, r3, addr) \
    asm volatile("ldmatrix.sync.aligned.m8n8.x4.trans.shared.b16 {%0,%1,%2,%3}, [%4];" \
                 : "=r"(r0), "=r"(r1), "=r"(r2), "=r"(r3) : "r"(addr))

__device__ __forceinline__ void mma_bf16(float* d, const uint32_t* a,
                                         const uint32_t* b) {
    asm volatile(
        "mma.sync.aligned.m16n8k16.row.col.f32.bf16.bf16.f32 "
        "{%0,%1,%2,%3}, {%4,%5,%6,%7}, {%8,%9}, {%0,%1,%2,%3};"
        : "+f"(d[0]), "+f"(d[1]), "+f"(d[2]), "+f"(d[3])
        : "r"(a[0]), "r"(a[1]), "r"(a[2]), "r"(a[3]), "r"(b[0]), "r"(b[1]));
}
__device__ __forceinline__ uint32_t pack_bf2(float a, float b) {
    __nv_bfloat162 t = __floats2bfloat162_rn(a, b);
    return *(uint32_t*)&t;
}

// ---------------------------------------------------------------------------
// Kernel 1: relative-position bias table expansion (known-good)
// ---------------------------------------------------------------------------
__global__ void bias_precompute_kernel(const float* __restrict__ bias_table) {
    int i = blockIdx.x * blockDim.x + threadIdx.x;
    if (i >= 4095) return;
    int delta = i - 2047;
    int ret = (delta > 0) ? 16 : 0;
    int rp = abs(delta);
    int bucket;
    if (rp < 8) {
        bucket = ret + rp;
    } else {
        int vl;
        if ((rp & (rp - 1)) == 0) {
            int k = __ffs(rp) - 1;
            vl = 8 + 2 * (k - 3);
        } else {
            float t = logf((float)rp * 0.125f) / 2.7725887f;
            vl = 8 + (int)(t * 8.0f);
        }
        bucket = ret + min(vl, 15);
    }
    #pragma unroll
    for (int h = 0; h < NHEADS; h++)
        g_bias[h * 4096 + i] = bias_table[bucket * NHEADS + h];
}

// ---------------------------------------------------------------------------
// Kernel 2a: split activations X -> bf16 hi/lo
// ---------------------------------------------------------------------------
__global__ void __launch_bounds__(256) convert_x_kernel(
    const float* __restrict__ Xq, const float* __restrict__ Xk,
    const float* __restrict__ Xv)
{
    int z = blockIdx.y;
    const float* X = (z == 0) ? Xq : (z == 1) ? Xk : Xv;
    __nv_bfloat16* hi = g_Ahi[z];
    __nv_bfloat16* lo = g_Alo[z];
    size_t i = ((size_t)blockIdx.x * 256 + threadIdx.x) * 4;
    float4 v = *(const float4*)(X + i);
    float f[4] = {v.x, v.y, v.z, v.w};
    #pragma unroll
    for (int j = 0; j < 4; j++) {
        __nv_bfloat16 h = __float2bfloat16(f[j]);
        hi[i + j] = h;
        lo[i + j] = __float2bfloat16(f[j] - __bfloat162float(h));
    }
}

// ---------------------------------------------------------------------------
// Kernel 2b: transpose + split weights  W[k][n] -> Wt[n][k] bf16 hi/lo
// ---------------------------------------------------------------------------
__global__ void __launch_bounds__(1024) convert_w_kernel(
    const float* __restrict__ Wq, const float* __restrict__ Wk,
    const float* __restrict__ Wv)
{
    __shared__ float tile[32][33];
    int z = blockIdx.z;
    const float* W = (z == 0) ? Wq : (z == 1) ? Wk : Wv;
    int k0 = blockIdx.x * 32;
    int n0 = blockIdx.y * 32;
    int tx = threadIdx.x, ty = threadIdx.y;
    tile[ty][tx] = W[(size_t)(k0 + ty) * DM + n0 + tx];
    __syncthreads();
    float v = tile[tx][ty];
    __nv_bfloat16 h = __float2bfloat16(v);
    size_t idx = (size_t)(n0 + ty) * DM + k0 + tx;
    g_Bhi[z][idx] = h;
    g_Blo[z][idx] = __float2bfloat16(v - __bfloat162float(h));
}

// ---------------------------------------------------------------------------
// Kernel 3: projection GEMM, FUSED 3-pass split, SINGLE barrier per k-iter
// (CP_WAIT(0); sync; issue next; compute — 2-stage ring, race-free:
//  stage (t+1)&1's last reads were in iter t-1, ordered before this sync).
// ---------------------------------------------------------------------------
#define BK 32
#define TB 10240
#define STAGE_B (4 * TB)
#define PROJ_SMEM (2 * STAGE_B)          // 81920 B
#define NCHUNK 32

__global__ void __launch_bounds__(256, 2) proj_mma_kernel() {
    extern __shared__ char psm[];

    const int tid  = threadIdx.x;
    const int lane = tid & 31;
    const int wid  = tid >> 5;
    const int wm   = wid >> 2;
    const int wn   = wid & 3;
    const int grp  = lane >> 2;
    const int q4   = lane & 3;

    const int z   = blockIdx.z;
    const int bm0 = blockIdx.y * 128;
    const int bn0 = blockIdx.x * 128;

    const __nv_bfloat16* __restrict__ srcs[4] = {
        g_Ahi[z], g_Alo[z], g_Bhi[z], g_Blo[z] };
    __nv_bfloat16* dhi = (z == 0) ? g_qhi : (z == 1) ? g_khi : g_vhi;
    __nv_bfloat16* dlo = (z == 0) ? g_qlo : (z == 1) ? g_klo : g_vlo;

    const uint32_t s0 = smem_u32(psm);

    float acc[4][4][4];
    #pragma unroll
    for (int i = 0; i < 4; i++)
        #pragma unroll
        for (int j = 0; j < 4; j++)
            #pragma unroll
            for (int r = 0; r < 4; r++) acc[i][j][r] = 0.0f;

    auto load_chunk = [&](int t, int s) {
        int k0 = t * BK;
        uint32_t base = s0 + s * STAGE_B;
        #pragma unroll
        for (int arr = 0; arr < 4; arr++) {
            int r0 = (arr < 2) ? bm0 : bn0;
            #pragma unroll
            for (int j = 0; j < 2; j++) {
                int id = tid + 256 * j;
                int row = id >> 2, part = id & 3;
                uint32_t off = (uint32_t)(row * 80 + part * 16);
                CP_ASYNC16(base + arr * TB + off,
                           srcs[arr] + (size_t)(r0 + row) * DM + k0 + part * 8);
            }
        }
        CP_COMMIT();
    };

    const int l7  = lane & 7;
    const int l8  = (lane >> 3) & 1;
    const int l16 = (lane >> 4) & 1;

    load_chunk(0, 0);

    for (int t = 0; t < NCHUNK; t++) {
        CP_WAIT(0);                      // load t complete
        __syncthreads();                 // publish load t; order prior reads
        if (t + 1 < NCHUNK) load_chunk(t + 1, (t + 1) & 1);

        const int s = t & 1;
        const uint32_t aHi = s0 + s * STAGE_B;
        const uint32_t aLo = aHi + TB;
        const uint32_t bHi = aHi + 2 * TB;
        const uint32_t bLo = aHi + 3 * TB;

        #pragma unroll
        for (int ks = 0; ks < 2; ks++) {
            const int kb = ks * 16;
            uint32_t bhif[4][2], blof[4][2];
            #pragma unroll
            for (int bp = 0; bp < 2; bp++) {
                uint32_t off = (uint32_t)((wn * 32 + bp * 16 + l16 * 8 + l7) * 80 +
                                          (kb + l8 * 8) * 2);
                uint32_t r0, r1, r2, r3;
                LDMATRIX_X4(r0, r1, r2, r3, bHi + off);
                bhif[bp * 2 + 0][0] = r0; bhif[bp * 2 + 0][1] = r1;
                bhif[bp * 2 + 1][0] = r2; bhif[bp * 2 + 1][1] = r3;
                LDMATRIX_X4(r0, r1, r2, r3, bLo + off);
                blof[bp * 2 + 0][0] = r0; blof[bp * 2 + 0][1] = r1;
                blof[bp * 2 + 1][0] = r2; blof[bp * 2 + 1][1] = r3;
            }
            #pragma unroll
            for (int mh = 0; mh < 2; mh++) {
                uint32_t afrag[2][4];
                #pragma unroll
                for (int mi = 0; mi < 2; mi++) {
                    int mt = mh * 2 + mi;
                    uint32_t addr = aHi +
                        (uint32_t)((wm * 64 + mt * 16 + l8 * 8 + l7) * 80 +
                                   (kb + l16 * 8) * 2);
                    LDMATRIX_X4(afrag[mi][0], afrag[mi][1], afrag[mi][2], afrag[mi][3], addr);
                }
                #pragma unroll
                for (int mi = 0; mi < 2; mi++)
                    #pragma unroll
                    for (int nt = 0; nt < 4; nt++) {
                        mma_bf16(acc[mh * 2 + mi][nt], afrag[mi], bhif[nt]);
                        mma_bf16(acc[mh * 2 + mi][nt], afrag[mi], blof[nt]);
                    }
                #pragma unroll
                for (int mi = 0; mi < 2; mi++) {
                    int mt = mh * 2 + mi;
                    uint32_t addr = aLo +
                        (uint32_t)((wm * 64 + mt * 16 + l8 * 8 + l7) * 80 +
                                   (kb + l16 * 8) * 2);
                    LDMATRIX_X4(afrag[mi][0], afrag[mi][1], afrag[mi][2], afrag[mi][3], addr);
                }
                #pragma unroll
                for (int mi = 0; mi < 2; mi++)
                    #pragma unroll
                    for (int nt = 0; nt < 4; nt++)
                        mma_bf16(acc[mh * 2 + mi][nt], afrag[mi], bhif[nt]);
            }
        }
    }

    #pragma unroll
    for (int mt = 0; mt < 4; mt++) {
        #pragma unroll
        for (int half = 0; half < 2; half++) {
            int m = bm0 + wm * 64 + mt * 16 + grp + half * 8;
            int bb = m >> 11;
            int ss = m & (SEQ - 1);
            #pragma unroll
            for (int nt = 0; nt < 4; nt++) {
                int n = bn0 + wn * 32 + nt * 8 + q4 * 2;
                int h = n >> 6, d = n & 63;
                float x = acc[mt][nt][half * 2 + 0];
                float y = acc[mt][nt][half * 2 + 1];
                float xh = __bfloat162float(__float2bfloat16(x));
                float yh = __bfloat162float(__float2bfloat16(y));
                size_t idx = (((size_t)(bb * NHEADS + h) * SEQ + ss) << 6) + d;
                *(uint32_t*)&dhi[idx] = pack_bf2(x, y);
                *(uint32_t*)&dlo[idx] = pack_bf2(x - xh, y - yh);
            }
        }
    }
}

// ---------------------------------------------------------------------------
// Kernel 4: flash attention, 128 threads, BM=64, 2-stage KV ring,
// ONE __syncthreads per tile. Q loaded gmem->registers directly (bit-identical
// to the old ldmatrix path) so smem drops to 75.3 KB => 3 CTAs/SM.
// ---------------------------------------------------------------------------
#define AT_RB   144
#define AT_TILE (64 * AT_RB)                      // 9216 B per 64x64 tile
#define A2NS    2
#define A2_BW   (A2NS * 4 * AT_TILE)              // 73728: bw[2][128] f32
#define A2_MW   (A2_BW + A2NS * 128 * 4)          // 74752: mw[2][64] f32
#define A2_SMEM (A2_MW + A2NS * 64 * 4)           // 75264
#define NKT     (SEQ / 64)

__global__ void __launch_bounds__(128, 3) attn_mma_kernel(
    const float* __restrict__ key_mask, float* __restrict__ out)
{
    extern __shared__ char dsm[];
    const uint32_t sb = smem_u32(dsm);

    const int tid  = threadIdx.x;
    const int lane = tid & 31;
    const int wid  = tid >> 5;
    const int g    = lane >> 2;
    const int q4   = lane & 3;
    const int l7   = lane & 7;
    const int l8   = (lane >> 3) & 1;
    const int l16  = (lane >> 4) & 1;

    const int qt0 = blockIdx.x * 64;
    const int h   = blockIdx.y;
    const int b   = blockIdx.z;
    const size_t bh = ((size_t)(b * NHEADS + h)) << 17;

    const __nv_bfloat16* Khi = g_khi + bh;
    const __nv_bfloat16* Klo = g_klo + bh;
    const __nv_bfloat16* Vhi = g_vhi + bh;
    const __nv_bfloat16* Vlo = g_vlo + bh;
    const float* bias_h = g_bias + h * 4096;

    auto issue_kv = [&](int kt, int s) {
        const __nv_bfloat16* srcs[4] = { Khi, Klo, Vhi, Vlo };
        #pragma unroll
        for (int arr = 0; arr < 4; arr++)
            #pragma unroll
            for (int jj = 0; jj < 4; jj++) {
                int rem = jj * 128 + tid;
                int row = rem >> 3, part = rem & 7;
                uint32_t dst = sb + (s * 4 + arr) * AT_TILE + row * AT_RB + part * 16;
                CP_ASYNC16(dst, srcs[arr] + (size_t)(kt * 64 + row) * HEAD + part * 8);
            }
        CP_COMMIT();
        float* bw = (float*)(dsm + A2_BW + s * 512);
        float* mw = (float*)(dsm + A2_MW + s * 256);
        if (tid < 127) {
            int idx = kt * 64 + tid - 63 - qt0 + 2047;
            idx = max(0, min(4094, idx));
            bw[tid] = bias_h[idx];
        }
        if (tid < 64) {
            float mk = key_mask[(size_t)b * SEQ + kt * 64 + tid];
            mw[tid] = (1.0f - mk) * -10000.0f;
        }
    };

    issue_kv(0, 0);

    // ---- Q fragments: direct gmem->register loads in mma A-layout ----
    // a0={Q[r][c],Q[r][c+1]}, a1=Q[r+8][c..], a2=Q[r][c+8..], a3=Q[r+8][c+8..]
    // with r = wid*16 + (lane>>2), c = kk*16 + (lane&3)*2.
    uint32_t qhi[4][4], qlo[4][4];
    {
        const __nv_bfloat16* Qh = g_qhi + bh;
        const __nv_bfloat16* Ql = g_qlo + bh;
        int r0 = qt0 + wid * 16 + g;
        #pragma unroll
        for (int kk = 0; kk < 4; kk++) {
            int c0 = kk * 16 + q4 * 2;
            qhi[kk][0] = *(const uint32_t*)&Qh[(size_t)(r0)     * HEAD + c0];
            qhi[kk][1] = *(const uint32_t*)&Qh[(size_t)(r0 + 8) * HEAD + c0];
            qhi[kk][2] = *(const uint32_t*)&Qh[(size_t)(r0)     * HEAD + c0 + 8];
            qhi[kk][3] = *(const uint32_t*)&Qh[(size_t)(r0 + 8) * HEAD + c0 + 8];
            qlo[kk][0] = *(const uint32_t*)&Ql[(size_t)(r0)     * HEAD + c0];
            qlo[kk][1] = *(const uint32_t*)&Ql[(size_t)(r0 + 8) * HEAD + c0];
            qlo[kk][2] = *(const uint32_t*)&Ql[(size_t)(r0)     * HEAD + c0 + 8];
            qlo[kk][3] = *(const uint32_t*)&Ql[(size_t)(r0 + 8) * HEAD + c0 + 8];
        }
    }

    float oacc[8][4];
    #pragma unroll
    for (int nt = 0; nt < 8; nt++)
        #pragma unroll
        for (int r = 0; r < 4; r++) oacc[nt][r] = 0.0f;
    float mrow[2] = { -INFINITY, -INFINITY };
    float lrow[2] = { 0.0f, 0.0f };

    for (int t = 0; t < NKT; t++) {
        CP_WAIT(0);
        __syncthreads();                 // publish load t; order prior reads
        if (t + 1 < NKT) issue_kv(t + 1, (t + 1) & 1);

        const int s = t & 1;
        const uint32_t kb_hi = sb + (s * 4 + 0) * AT_TILE;
        const uint32_t kb_lo = sb + (s * 4 + 1) * AT_TILE;
        const uint32_t vb_hi = sb + (s * 4 + 2) * AT_TILE;
        const uint32_t vb_lo = sb + (s * 4 + 3) * AT_TILE;
        const float* bw = (const float*)(dsm + A2_BW + s * 512);
        const float* mw = (const float*)(dsm + A2_MW + s * 256);

        // ---- S = Q K^T (3-pass split) ----
        float sacc[8][4];
        #pragma unroll
        for (int nt = 0; nt < 8; nt++)
            #pragma unroll
            for (int r = 0; r < 4; r++) sacc[nt][r] = 0.0f;

        #pragma unroll
        for (int kk = 0; kk < 4; kk++) {
            uint32_t bhif[8][2], blof[8][2];
            #pragma unroll
            for (int bp = 0; bp < 4; bp++) {
                uint32_t off = (uint32_t)((bp * 16 + l16 * 8 + l7) * AT_RB +
                                          (kk * 16 + l8 * 8) * 2);
                uint32_t r0, r1, r2, r3;
                LDMATRIX_X4(r0, r1, r2, r3, kb_hi + off);
                bhif[bp * 2][0] = r0; bhif[bp * 2][1] = r1;
                bhif[bp * 2 + 1][0] = r2; bhif[bp * 2 + 1][1] = r3;
                LDMATRIX_X4(r0, r1, r2, r3, kb_lo + off);
                blof[bp * 2][0] = r0; blof[bp * 2][1] = r1;
                blof[bp * 2 + 1][0] = r2; blof[bp * 2 + 1][1] = r3;
            }
            #pragma unroll
            for (int nt = 0; nt < 8; nt++) {
                mma_bf16(sacc[nt], qhi[kk], bhif[nt]);
                mma_bf16(sacc[nt], qlo[kk], bhif[nt]);
                mma_bf16(sacc[nt], qhi[kk], blof[nt]);
            }
        }

        // ---- softmax in registers ----
        #pragma unroll
        for (int hl = 0; hl < 2; hl++) {
            int rr = wid * 16 + g + hl * 8;
            float mx = -INFINITY;
            #pragma unroll
            for (int nt = 0; nt < 8; nt++) {
                #pragma unroll
                for (int e = 0; e < 2; e++) {
                    int c = nt * 8 + q4 * 2 + e;
                    float v = sacc[nt][hl * 2 + e] + bw[c - rr + 63] + mw[c];
                    sacc[nt][hl * 2 + e] = v;
                    mx = fmaxf(mx, v);
                }
            }
            mx = fmaxf(mx, __shfl_xor_sync(0xffffffffu, mx, 1));
            mx = fmaxf(mx, __shfl_xor_sync(0xffffffffu, mx, 2));
            float mnew = fmaxf(mrow[hl], mx);
            float corr = __expf(mrow[hl] - mnew);
            mrow[hl] = mnew;
            float sum = 0.0f;
            #pragma unroll
            for (int nt = 0; nt < 8; nt++) {
                #pragma unroll
                for (int e = 0; e < 2; e++) {
                    float p = __expf(sacc[nt][hl * 2 + e] - mnew);
                    sacc[nt][hl * 2 + e] = p;
                    sum += p;
                }
            }
            sum += __shfl_xor_sync(0xffffffffu, sum, 1);
            sum += __shfl_xor_sync(0xffffffffu, sum, 2);
            lrow[hl] = lrow[hl] * corr + sum;
            #pragma unroll
            for (int nt = 0; nt < 8; nt++) {
                oacc[nt][hl * 2 + 0] *= corr;
                oacc[nt][hl * 2 + 1] *= corr;
            }
        }

        // ---- P -> bf16 hi/lo A-fragments ----
        uint32_t phi[4][4], plo[4][4];
        #pragma unroll
        for (int kk = 0; kk < 4; kk++) {
            #pragma unroll
            for (int part = 0; part < 4; part++) {
                int nt = 2 * kk + (part >> 1);
                int o = (part & 1) * 2;
                float p0 = sacc[nt][o], p1 = sacc[nt][o + 1];
                float h0 = __bfloat162float(__float2bfloat16(p0));
                float h1 = __bfloat162float(__float2bfloat16(p1));
                phi[kk][part] = pack_bf2(p0, p1);
                plo[kk][part] = pack_bf2(p0 - h0, p1 - h1);
            }
        }

        // ---- O += P V (3-pass split), V via trans ldmatrix ----
        #pragma unroll
        for (int kk = 0; kk < 4; kk++) {
            uint32_t vhif[8][2], vlof[8][2];
            #pragma unroll
            for (int db = 0; db < 4; db++) {
                uint32_t off = (uint32_t)((kk * 16 + l8 * 8 + l7) * AT_RB +
                                          (db * 16 + l16 * 8) * 2);
                uint32_t r0, r1, r2, r3;
                LDMATRIX_X4T(r0, r1, r2, r3, vb_hi + off);
                vhif[db * 2][0] = r0; vhif[db * 2][1] = r1;
                vhif[db * 2 + 1][0] = r2; vhif[db * 2 + 1][1] = r3;
                LDMATRIX_X4T(r0, r1, r2, r3, vb_lo + off);
                vlof[db * 2][0] = r0; vlof[db * 2][1] = r1;
                vlof[db * 2 + 1][0] = r2; vlof[db * 2 + 1][1] = r3;
            }
            #pragma unroll
            for (int nt = 0; nt < 8; nt++) {
                mma_bf16(oacc[nt], phi[kk], vhif[nt]);
                mma_bf16(oacc[nt], plo[kk], vhif[nt]);
                mma_bf16(oacc[nt], phi[kk], vlof[nt]);
            }
        }
    }

    // ---- epilogue: out[b][qrow][h*64 + d] = O / l ----
    #pragma unroll
    for (int hl = 0; hl < 2; hl++) {
        int rr = wid * 16 + g + hl * 8;
        float inv = 1.0f / lrow[hl];
        size_t base = ((size_t)(b * SEQ + qt0 + rr)) * (NHEADS * HEAD) + h * HEAD;
        #pragma unroll
        for (int nt = 0; nt < 8; nt++) {
            int c = nt * 8 + q4 * 2;
            float2 v;
            v.x = oacc[nt][hl * 2 + 0] * inv;
            v.y = oacc[nt][hl * 2 + 1] * inv;
            *(float2*)&out[base + c] = v;
        }
    }
}

// ---------------------------------------------------------------------------
// Launch
// ---------------------------------------------------------------------------
extern "C" void kernel_launch(void* const* d_in, const int* in_sizes, int n_in,
                              void* d_out, int out_size) {
    const float* query    = (const float*)d_in[0];
    const float* key      = (const float*)d_in[1];
    const float* value    = (const float*)d_in[2];
    const float* key_mask = (const float*)d_in[3];
    const float* Wq       = (const float*)d_in[4];
    const float* Wk       = (const float*)d_in[5];
    const float* Wv       = (const float*)d_in[6];
    const float* bias_tab = (const float*)d_in[7];
    float* out = (float*)d_out;

    cudaFuncSetAttribute(proj_mma_kernel,
                         cudaFuncAttributeMaxDynamicSharedMemorySize, PROJ_SMEM);
    cudaFuncSetAttribute(attn_mma_kernel,
                         cudaFuncAttributeMaxDynamicSharedMemorySize, A2_SMEM);

    bias_precompute_kernel<<<16, 256>>>(bias_tab);
    convert_x_kernel<<<dim3(4096, 3), 256>>>(query, key, value);
    convert_w_kernel<<<dim3(32, 32, 3), dim3(32, 32)>>>(Wq, Wk, Wv);
    proj_mma_kernel<<<dim3(8, 32, 3), 256, PROJ_SMEM>>>();
    attn_mma_kernel<<<dim3(SEQ / 64, NHEADS, NB), 128, A2_SMEM>>>(key_mask, out);
}

// round 14
// speedup vs baseline: 3.2042x; 1.1451x over previous
#include <cuda_runtime.h>
#include <cuda_bf16.h>
#include <cuda_fp16.h>
#include <math.h>
#include <stdint.h>

// ---------------------------------------------------------------------------
// Problem constants (B=2, S=2048, D_MODEL=1024, H=16, Dh=64)
// ---------------------------------------------------------------------------
#define NB      2
#define SEQ     2048
#define DM      1024
#define NHEADS  16
#define HEAD    64

__device__ float g_bias[NHEADS * 4096];

// bf16 split operands for projection GEMMs
__device__ __nv_bfloat16 g_Ahi[3][4096 * 1024];
__device__ __nv_bfloat16 g_Alo[3][4096 * 1024];
__device__ __nv_bfloat16 g_Bhi[3][1024 * 1024];
__device__ __nv_bfloat16 g_Blo[3][1024 * 1024];

// Q/K split outputs (bf16 hi/lo); V output as SINGLE fp16 (PV is linear ->
// relative accuracy only; fp16 single-product error ~4e-4 << 1e-3)
#define QKV_ELE (NB * NHEADS * SEQ * HEAD)
__device__ __nv_bfloat16 g_qhi[QKV_ELE], g_qlo[QKV_ELE];
__device__ __nv_bfloat16 g_khi[QKV_ELE], g_klo[QKV_ELE];
__device__ __half        g_vh [QKV_ELE];

// ---------------------------------------------------------------------------
// PTX helpers
// ---------------------------------------------------------------------------
__device__ __forceinline__ uint32_t smem_u32(const void* p) {
    uint32_t a;
    asm("{ .reg .u64 t; cvta.to.shared.u64 t, %1; cvt.u32.u64 %0, t; }"
        : "=r"(a) : "l"(p));
    return a;
}
#define CP_ASYNC16(dst, src) \
    asm volatile("cp.async.cg.shared.global [%0], [%1], 16;" :: "r"(dst), "l"(src))
#define CP_COMMIT() asm volatile("cp.async.commit_group;" ::: "memory")
#define CP_WAIT(n)  asm volatile("cp.async.wait_group %0;" :: "n"(n) : "memory")

#define LDMATRIX_X4(r0, r1, r2, r3, addr) \
    asm volatile("ldmatrix.sync.aligned.m8n8.x4.shared.b16 {%0,%1,%2,%3}, [%4];" \
                 : "=r"(r0), "=r"(r1), "=r"(r2), "=r"(r3) : "r"(addr))
#define LDMATRIX_X4T(r0, r1, r2, r3, addr) \
    asm volatile("ldmatrix.sync.aligned.m8n8.x4.trans.shared.b16 {%0,%1,%2,%3}, [%4];" \
                 : "=r"(r0), "=r"(r1), "=r"(r2), "=r"(r3) : "r"(addr))

__device__ __forceinline__ void mma_bf16(float* d, const uint32_t* a,
                                         const uint32_t* b) {
    asm volatile(
        "mma.sync.aligned.m16n8k16.row.col.f32.bf16.bf16.f32 "
        "{%0,%1,%2,%3}, {%4,%5,%6,%7}, {%8,%9}, {%0,%1,%2,%3};"
        : "+f"(d[0]), "+f"(d[1]), "+f"(d[2]), "+f"(d[3])
        : "r"(a[0]), "r"(a[1]), "r"(a[2]), "r"(a[3]), "r"(b[0]), "r"(b[1]));
}
__device__ __forceinline__ void mma_fp16(float* d, const uint32_t* a,
                                         const uint32_t* b) {
    asm volatile(
        "mma.sync.aligned.m16n8k16.row.col.f32.f16.f16.f32 "
        "{%0,%1,%2,%3}, {%4,%5,%6,%7}, {%8,%9}, {%0,%1,%2,%3};"
        : "+f"(d[0]), "+f"(d[1]), "+f"(d[2]), "+f"(d[3])
        : "r"(a[0]), "r"(a[1]), "r"(a[2]), "r"(a[3]), "r"(b[0]), "r"(b[1]));
}
__device__ __forceinline__ uint32_t pack_bf2(float a, float b) {
    __nv_bfloat162 t = __floats2bfloat162_rn(a, b);
    return *(uint32_t*)&t;
}
__device__ __forceinline__ uint32_t pack_h2(float a, float b) {
    __half2 t = __floats2half2_rn(a, b);
    return *(uint32_t*)&t;
}

// ---------------------------------------------------------------------------
// Kernel 1: relative-position bias table expansion (known-good)
// ---------------------------------------------------------------------------
__global__ void bias_precompute_kernel(const float* __restrict__ bias_table) {
    int i = blockIdx.x * blockDim.x + threadIdx.x;
    if (i >= 4095) return;
    int delta = i - 2047;
    int ret = (delta > 0) ? 16 : 0;
    int rp = abs(delta);
    int bucket;
    if (rp < 8) {
        bucket = ret + rp;
    } else {
        int vl;
        if ((rp & (rp - 1)) == 0) {
            int k = __ffs(rp) - 1;
            vl = 8 + 2 * (k - 3);
        } else {
            float t = logf((float)rp * 0.125f) / 2.7725887f;
            vl = 8 + (int)(t * 8.0f);
        }
        bucket = ret + min(vl, 15);
    }
    #pragma unroll
    for (int h = 0; h < NHEADS; h++)
        g_bias[h * 4096 + i] = bias_table[bucket * NHEADS + h];
}

// ---------------------------------------------------------------------------
// Kernel 2a: split activations X -> bf16 hi/lo
// ---------------------------------------------------------------------------
__global__ void __launch_bounds__(256) convert_x_kernel(
    const float* __restrict__ Xq, const float* __restrict__ Xk,
    const float* __restrict__ Xv)
{
    int z = blockIdx.y;
    const float* X = (z == 0) ? Xq : (z == 1) ? Xk : Xv;
    __nv_bfloat16* hi = g_Ahi[z];
    __nv_bfloat16* lo = g_Alo[z];
    size_t i = ((size_t)blockIdx.x * 256 + threadIdx.x) * 4;
    float4 v = *(const float4*)(X + i);
    float f[4] = {v.x, v.y, v.z, v.w};
    #pragma unroll
    for (int j = 0; j < 4; j++) {
        __nv_bfloat16 h = __float2bfloat16(f[j]);
        hi[i + j] = h;
        lo[i + j] = __float2bfloat16(f[j] - __bfloat162float(h));
    }
}

// ---------------------------------------------------------------------------
// Kernel 2b: transpose + split weights  W[k][n] -> Wt[n][k] bf16 hi/lo
// ---------------------------------------------------------------------------
__global__ void __launch_bounds__(1024) convert_w_kernel(
    const float* __restrict__ Wq, const float* __restrict__ Wk,
    const float* __restrict__ Wv)
{
    __shared__ float tile[32][33];
    int z = blockIdx.z;
    const float* W = (z == 0) ? Wq : (z == 1) ? Wk : Wv;
    int k0 = blockIdx.x * 32;
    int n0 = blockIdx.y * 32;
    int tx = threadIdx.x, ty = threadIdx.y;
    tile[ty][tx] = W[(size_t)(k0 + ty) * DM + n0 + tx];
    __syncthreads();
    float v = tile[tx][ty];
    __nv_bfloat16 h = __float2bfloat16(v);
    size_t idx = (size_t)(n0 + ty) * DM + k0 + tx;
    g_Bhi[z][idx] = h;
    g_Blo[z][idx] = __float2bfloat16(v - __bfloat162float(h));
}

// ---------------------------------------------------------------------------
// Kernel 3: projection GEMM, FUSED 3-pass split, single barrier per k-iter.
// Epilogue: z<2 -> bf16 hi/lo; z==2 (V) -> single packed fp16.
// ---------------------------------------------------------------------------
#define BK 32
#define TB 10240
#define STAGE_B (4 * TB)
#define PROJ_SMEM (2 * STAGE_B)          // 81920 B
#define NCHUNK 32

__global__ void __launch_bounds__(256, 2) proj_mma_kernel() {
    extern __shared__ char psm[];

    const int tid  = threadIdx.x;
    const int lane = tid & 31;
    const int wid  = tid >> 5;
    const int wm   = wid >> 2;
    const int wn   = wid & 3;
    const int grp  = lane >> 2;
    const int q4   = lane & 3;

    const int z   = blockIdx.z;
    const int bm0 = blockIdx.y * 128;
    const int bn0 = blockIdx.x * 128;

    const __nv_bfloat16* __restrict__ srcs[4] = {
        g_Ahi[z], g_Alo[z], g_Bhi[z], g_Blo[z] };

    const uint32_t s0 = smem_u32(psm);

    float acc[4][4][4];
    #pragma unroll
    for (int i = 0; i < 4; i++)
        #pragma unroll
        for (int j = 0; j < 4; j++)
            #pragma unroll
            for (int r = 0; r < 4; r++) acc[i][j][r] = 0.0f;

    auto load_chunk = [&](int t, int s) {
        int k0 = t * BK;
        uint32_t base = s0 + s * STAGE_B;
        #pragma unroll
        for (int arr = 0; arr < 4; arr++) {
            int r0 = (arr < 2) ? bm0 : bn0;
            #pragma unroll
            for (int j = 0; j < 2; j++) {
                int id = tid + 256 * j;
                int row = id >> 2, part = id & 3;
                uint32_t off = (uint32_t)(row * 80 + part * 16);
                CP_ASYNC16(base + arr * TB + off,
                           srcs[arr] + (size_t)(r0 + row) * DM + k0 + part * 8);
            }
        }
        CP_COMMIT();
    };

    const int l7  = lane & 7;
    const int l8  = (lane >> 3) & 1;
    const int l16 = (lane >> 4) & 1;

    load_chunk(0, 0);

    for (int t = 0; t < NCHUNK; t++) {
        CP_WAIT(0);
        __syncthreads();                 // publish load t; order prior reads
        if (t + 1 < NCHUNK) load_chunk(t + 1, (t + 1) & 1);

        const int s = t & 1;
        const uint32_t aHi = s0 + s * STAGE_B;
        const uint32_t aLo = aHi + TB;
        const uint32_t bHi = aHi + 2 * TB;
        const uint32_t bLo = aHi + 3 * TB;

        #pragma unroll
        for (int ks = 0; ks < 2; ks++) {
            const int kb = ks * 16;
            uint32_t bhif[4][2], blof[4][2];
            #pragma unroll
            for (int bp = 0; bp < 2; bp++) {
                uint32_t off = (uint32_t)((wn * 32 + bp * 16 + l16 * 8 + l7) * 80 +
                                          (kb + l8 * 8) * 2);
                uint32_t r0, r1, r2, r3;
                LDMATRIX_X4(r0, r1, r2, r3, bHi + off);
                bhif[bp * 2 + 0][0] = r0; bhif[bp * 2 + 0][1] = r1;
                bhif[bp * 2 + 1][0] = r2; bhif[bp * 2 + 1][1] = r3;
                LDMATRIX_X4(r0, r1, r2, r3, bLo + off);
                blof[bp * 2 + 0][0] = r0; blof[bp * 2 + 0][1] = r1;
                blof[bp * 2 + 1][0] = r2; blof[bp * 2 + 1][1] = r3;
            }
            #pragma unroll
            for (int mh = 0; mh < 2; mh++) {
                uint32_t afrag[2][4];
                #pragma unroll
                for (int mi = 0; mi < 2; mi++) {
                    int mt = mh * 2 + mi;
                    uint32_t addr = aHi +
                        (uint32_t)((wm * 64 + mt * 16 + l8 * 8 + l7) * 80 +
                                   (kb + l16 * 8) * 2);
                    LDMATRIX_X4(afrag[mi][0], afrag[mi][1], afrag[mi][2], afrag[mi][3], addr);
                }
                #pragma unroll
                for (int mi = 0; mi < 2; mi++)
                    #pragma unroll
                    for (int nt = 0; nt < 4; nt++) {
                        mma_bf16(acc[mh * 2 + mi][nt], afrag[mi], bhif[nt]);
                        mma_bf16(acc[mh * 2 + mi][nt], afrag[mi], blof[nt]);
                    }
                #pragma unroll
                for (int mi = 0; mi < 2; mi++) {
                    int mt = mh * 2 + mi;
                    uint32_t addr = aLo +
                        (uint32_t)((wm * 64 + mt * 16 + l8 * 8 + l7) * 80 +
                                   (kb + l16 * 8) * 2);
                    LDMATRIX_X4(afrag[mi][0], afrag[mi][1], afrag[mi][2], afrag[mi][3], addr);
                }
                #pragma unroll
                for (int mi = 0; mi < 2; mi++)
                    #pragma unroll
                    for (int nt = 0; nt < 4; nt++)
                        mma_bf16(acc[mh * 2 + mi][nt], afrag[mi], bhif[nt]);
            }
        }
    }

    // epilogue
    if (z == 2) {
        // V: single packed fp16
        #pragma unroll
        for (int mt = 0; mt < 4; mt++) {
            #pragma unroll
            for (int half = 0; half < 2; half++) {
                int m = bm0 + wm * 64 + mt * 16 + grp + half * 8;
                int bb = m >> 11;
                int ss = m & (SEQ - 1);
                #pragma unroll
                for (int nt = 0; nt < 4; nt++) {
                    int n = bn0 + wn * 32 + nt * 8 + q4 * 2;
                    int h = n >> 6, d = n & 63;
                    size_t idx = (((size_t)(bb * NHEADS + h) * SEQ + ss) << 6) + d;
                    *(uint32_t*)&g_vh[idx] =
                        pack_h2(acc[mt][nt][half * 2 + 0], acc[mt][nt][half * 2 + 1]);
                }
            }
        }
    } else {
        __nv_bfloat16* dhi = (z == 0) ? g_qhi : g_khi;
        __nv_bfloat16* dlo = (z == 0) ? g_qlo : g_klo;
        #pragma unroll
        for (int mt = 0; mt < 4; mt++) {
            #pragma unroll
            for (int half = 0; half < 2; half++) {
                int m = bm0 + wm * 64 + mt * 16 + grp + half * 8;
                int bb = m >> 11;
                int ss = m & (SEQ - 1);
                #pragma unroll
                for (int nt = 0; nt < 4; nt++) {
                    int n = bn0 + wn * 32 + nt * 8 + q4 * 2;
                    int h = n >> 6, d = n & 63;
                    float x = acc[mt][nt][half * 2 + 0];
                    float y = acc[mt][nt][half * 2 + 1];
                    float xh = __bfloat162float(__float2bfloat16(x));
                    float yh = __bfloat162float(__float2bfloat16(y));
                    size_t idx = (((size_t)(bb * NHEADS + h) * SEQ + ss) << 6) + d;
                    *(uint32_t*)&dhi[idx] = pack_bf2(x, y);
                    *(uint32_t*)&dlo[idx] = pack_bf2(x - xh, y - yh);
                }
            }
        }
    }
}

// ---------------------------------------------------------------------------
// Kernel 4: flash attention. QK = 3-product bf16 split (logits need absolute
// accuracy); PV = SINGLE fp16 product (linear -> relative accuracy, ~4e-4).
// 128 threads, BM=64, 2-stage KV ring {Khi, Klo, Vh}, one barrier per tile,
// Q direct gmem->regs, 3 CTAs/SM (smem 56.8 KB).
// ---------------------------------------------------------------------------
#define AT_RB   144
#define AT_TILE (64 * AT_RB)                      // 9216 B per 64x64 tile
#define A2NS    2
#define A2_BW   (A2NS * 3 * AT_TILE)              // 55296: bw[2][128] f32
#define A2_MW   (A2_BW + A2NS * 128 * 4)          // 56320: mw[2][64] f32
#define A2_SMEM (A2_MW + A2NS * 64 * 4)           // 56832
#define NKT     (SEQ / 64)

__global__ void __launch_bounds__(128, 3) attn_mma_kernel(
    const float* __restrict__ key_mask, float* __restrict__ out)
{
    extern __shared__ char dsm[];
    const uint32_t sb = smem_u32(dsm);

    const int tid  = threadIdx.x;
    const int lane = tid & 31;
    const int wid  = tid >> 5;
    const int g    = lane >> 2;
    const int q4   = lane & 3;
    const int l7   = lane & 7;
    const int l8   = (lane >> 3) & 1;
    const int l16  = (lane >> 4) & 1;

    const int qt0 = blockIdx.x * 64;
    const int h   = blockIdx.y;
    const int b   = blockIdx.z;
    const size_t bh = ((size_t)(b * NHEADS + h)) << 17;

    const __nv_bfloat16* Khi = g_khi + bh;
    const __nv_bfloat16* Klo = g_klo + bh;
    const __nv_bfloat16* Vh  = (const __nv_bfloat16*)(g_vh + bh);  // addr only
    const float* bias_h = g_bias + h * 4096;

    auto issue_kv = [&](int kt, int s) {
        const __nv_bfloat16* srcs[3] = { Khi, Klo, Vh };
        #pragma unroll
        for (int arr = 0; arr < 3; arr++)
            #pragma unroll
            for (int jj = 0; jj < 4; jj++) {
                int rem = jj * 128 + tid;
                int row = rem >> 3, part = rem & 7;
                uint32_t dst = sb + (s * 3 + arr) * AT_TILE + row * AT_RB + part * 16;
                CP_ASYNC16(dst, srcs[arr] + (size_t)(kt * 64 + row) * HEAD + part * 8);
            }
        CP_COMMIT();
        float* bw = (float*)(dsm + A2_BW + s * 512);
        float* mw = (float*)(dsm + A2_MW + s * 256);
        if (tid < 127) {
            int idx = kt * 64 + tid - 63 - qt0 + 2047;
            idx = max(0, min(4094, idx));
            bw[tid] = bias_h[idx];
        }
        if (tid < 64) {
            float mk = key_mask[(size_t)b * SEQ + kt * 64 + tid];
            mw[tid] = (1.0f - mk) * -10000.0f;
        }
    };

    issue_kv(0, 0);

    // ---- Q fragments: direct gmem->register loads in mma A-layout ----
    uint32_t qhi[4][4], qlo[4][4];
    {
        const __nv_bfloat16* Qh = g_qhi + bh;
        const __nv_bfloat16* Ql = g_qlo + bh;
        int r0 = qt0 + wid * 16 + g;
        #pragma unroll
        for (int kk = 0; kk < 4; kk++) {
            int c0 = kk * 16 + q4 * 2;
            qhi[kk][0] = *(const uint32_t*)&Qh[(size_t)(r0)     * HEAD + c0];
            qhi[kk][1] = *(const uint32_t*)&Qh[(size_t)(r0 + 8) * HEAD + c0];
            qhi[kk][2] = *(const uint32_t*)&Qh[(size_t)(r0)     * HEAD + c0 + 8];
            qhi[kk][3] = *(const uint32_t*)&Qh[(size_t)(r0 + 8) * HEAD + c0 + 8];
            qlo[kk][0] = *(const uint32_t*)&Ql[(size_t)(r0)     * HEAD + c0];
            qlo[kk][1] = *(const uint32_t*)&Ql[(size_t)(r0 + 8) * HEAD + c0];
            qlo[kk][2] = *(const uint32_t*)&Ql[(size_t)(r0)     * HEAD + c0 + 8];
            qlo[kk][3] = *(const uint32_t*)&Ql[(size_t)(r0 + 8) * HEAD + c0 + 8];
        }
    }

    float oacc[8][4];
    #pragma unroll
    for (int nt = 0; nt < 8; nt++)
        #pragma unroll
        for (int r = 0; r < 4; r++) oacc[nt][r] = 0.0f;
    float mrow[2] = { -INFINITY, -INFINITY };
    float lrow[2] = { 0.0f, 0.0f };

    for (int t = 0; t < NKT; t++) {
        CP_WAIT(0);
        __syncthreads();                 // publish load t; order prior reads
        if (t + 1 < NKT) issue_kv(t + 1, (t + 1) & 1);

        const int s = t & 1;
        const uint32_t kb_hi = sb + (s * 3 + 0) * AT_TILE;
        const uint32_t kb_lo = sb + (s * 3 + 1) * AT_TILE;
        const uint32_t vb    = sb + (s * 3 + 2) * AT_TILE;
        const float* bw = (const float*)(dsm + A2_BW + s * 512);
        const float* mw = (const float*)(dsm + A2_MW + s * 256);

        // ---- S = Q K^T (3-pass bf16 split) ----
        float sacc[8][4];
        #pragma unroll
        for (int nt = 0; nt < 8; nt++)
            #pragma unroll
            for (int r = 0; r < 4; r++) sacc[nt][r] = 0.0f;

        #pragma unroll
        for (int kk = 0; kk < 4; kk++) {
            uint32_t bhif[8][2], blof[8][2];
            #pragma unroll
            for (int bp = 0; bp < 4; bp++) {
                uint32_t off = (uint32_t)((bp * 16 + l16 * 8 + l7) * AT_RB +
                                          (kk * 16 + l8 * 8) * 2);
                uint32_t r0, r1, r2, r3;
                LDMATRIX_X4(r0, r1, r2, r3, kb_hi + off);
                bhif[bp * 2][0] = r0; bhif[bp * 2][1] = r1;
                bhif[bp * 2 + 1][0] = r2; bhif[bp * 2 + 1][1] = r3;
                LDMATRIX_X4(r0, r1, r2, r3, kb_lo + off);
                blof[bp * 2][0] = r0; blof[bp * 2][1] = r1;
                blof[bp * 2 + 1][0] = r2; blof[bp * 2 + 1][1] = r3;
            }
            #pragma unroll
            for (int nt = 0; nt < 8; nt++) {
                mma_bf16(sacc[nt], qhi[kk], bhif[nt]);
                mma_bf16(sacc[nt], qlo[kk], bhif[nt]);
                mma_bf16(sacc[nt], qhi[kk], blof[nt]);
            }
        }

        // ---- softmax in registers ----
        #pragma unroll
        for (int hl = 0; hl < 2; hl++) {
            int rr = wid * 16 + g + hl * 8;
            float mx = -INFINITY;
            #pragma unroll
            for (int nt = 0; nt < 8; nt++) {
                #pragma unroll
                for (int e = 0; e < 2; e++) {
                    int c = nt * 8 + q4 * 2 + e;
                    float v = sacc[nt][hl * 2 + e] + bw[c - rr + 63] + mw[c];
                    sacc[nt][hl * 2 + e] = v;
                    mx = fmaxf(mx, v);
                }
            }
            mx = fmaxf(mx, __shfl_xor_sync(0xffffffffu, mx, 1));
            mx = fmaxf(mx, __shfl_xor_sync(0xffffffffu, mx, 2));
            float mnew = fmaxf(mrow[hl], mx);
            float corr = __expf(mrow[hl] - mnew);
            mrow[hl] = mnew;
            float sum = 0.0f;
            #pragma unroll
            for (int nt = 0; nt < 8; nt++) {
                #pragma unroll
                for (int e = 0; e < 2; e++) {
                    float p = __expf(sacc[nt][hl * 2 + e] - mnew);
                    sacc[nt][hl * 2 + e] = p;
                    sum += p;
                }
            }
            sum += __shfl_xor_sync(0xffffffffu, sum, 1);
            sum += __shfl_xor_sync(0xffffffffu, sum, 2);
            lrow[hl] = lrow[hl] * corr + sum;
            #pragma unroll
            for (int nt = 0; nt < 8; nt++) {
                oacc[nt][hl * 2 + 0] *= corr;
                oacc[nt][hl * 2 + 1] *= corr;
            }
        }

        // ---- P -> fp16 A-fragments (single product, no split) ----
        uint32_t ph[4][4];
        #pragma unroll
        for (int kk = 0; kk < 4; kk++) {
            #pragma unroll
            for (int part = 0; part < 4; part++) {
                int nt = 2 * kk + (part >> 1);
                int o = (part & 1) * 2;
                ph[kk][part] = pack_h2(sacc[nt][o], sacc[nt][o + 1]);
            }
        }

        // ---- O += P V (fp16 single product), V via trans ldmatrix ----
        #pragma unroll
        for (int kk = 0; kk < 4; kk++) {
            uint32_t vhf[8][2];
            #pragma unroll
            for (int db = 0; db < 4; db++) {
                uint32_t off = (uint32_t)((kk * 16 + l8 * 8 + l7) * AT_RB +
                                          (db * 16 + l16 * 8) * 2);
                uint32_t r0, r1, r2, r3;
                LDMATRIX_X4T(r0, r1, r2, r3, vb + off);
                vhf[db * 2][0] = r0; vhf[db * 2][1] = r1;
                vhf[db * 2 + 1][0] = r2; vhf[db * 2 + 1][1] = r3;
            }
            #pragma unroll
            for (int nt = 0; nt < 8; nt++)
                mma_fp16(oacc[nt], ph[kk], vhf[nt]);
        }
    }

    // ---- epilogue: out[b][qrow][h*64 + d] = O / l ----
    #pragma unroll
    for (int hl = 0; hl < 2; hl++) {
        int rr = wid * 16 + g + hl * 8;
        float inv = 1.0f / lrow[hl];
        size_t base = ((size_t)(b * SEQ + qt0 + rr)) * (NHEADS * HEAD) + h * HEAD;
        #pragma unroll
        for (int nt = 0; nt < 8; nt++) {
            int c = nt * 8 + q4 * 2;
            float2 v;
            v.x = oacc[nt][hl * 2 + 0] * inv;
            v.y = oacc[nt][hl * 2 + 1] * inv;
            *(float2*)&out[base + c] = v;
        }
    }
}

// ---------------------------------------------------------------------------
// Launch
// ---------------------------------------------------------------------------
extern "C" void kernel_launch(void* const* d_in, const int* in_sizes, int n_in,
                              void* d_out, int out_size) {
    const float* query    = (const float*)d_in[0];
    const float* key      = (const float*)d_in[1];
    const float* value    = (const float*)d_in[2];
    const float* key_mask = (const float*)d_in[3];
    const float* Wq       = (const float*)d_in[4];
    const float* Wk       = (const float*)d_in[5];
    const float* Wv       = (const float*)d_in[6];
    const float* bias_tab = (const float*)d_in[7];
    float* out = (float*)d_out;

    cudaFuncSetAttribute(proj_mma_kernel,
                         cudaFuncAttributeMaxDynamicSharedMemorySize, PROJ_SMEM);
    cudaFuncSetAttribute(attn_mma_kernel,
                         cudaFuncAttributeMaxDynamicSharedMemorySize, A2_SMEM);

    bias_precompute_kernel<<<16, 256>>>(bias_tab);
    convert_x_kernel<<<dim3(4096, 3), 256>>>(query, key, value);
    convert_w_kernel<<<dim3(32, 32, 3), dim3(32, 32)>>>(Wq, Wk, Wv);
    proj_mma_kernel<<<dim3(8, 32, 3), 256, PROJ_SMEM>>>();
    attn_mma_kernel<<<dim3(SEQ / 64, NHEADS, NB), 128, A2_SMEM>>>(key_mask, out);
}